// round 4
// baseline (speedup 1.0000x reference)
#include <cuda_runtime.h>
#include <math.h>

// ---------------------------------------------------------------------------
// Problem constants
// ---------------------------------------------------------------------------
namespace {
constexpr int B_  = 16;
constexpr int TT_ = 128;
constexpr int TS_ = 512;
constexpr int L_  = TT_ + TS_ + 2;   // 642
constexpr int D_  = 1024;
constexpr int H_  = 16;
constexpr int HD_ = 64;
constexpr int F_  = 4096;
constexpr int NL_ = 4;
constexpr int M_  = B_ * L_;         // 10272
constexpr int SMEM_ATT = (4096 * 3 + 64 * 68 + 64) * 4;  // 66816 bytes
}

// ---------------------------------------------------------------------------
// Scratch (allocation-free: __device__ globals)
// ---------------------------------------------------------------------------
__device__ float g_x  [(size_t)M_ * D_];
__device__ float g_q  [(size_t)M_ * D_];
__device__ float g_k  [(size_t)M_ * D_];
__device__ float g_v  [(size_t)M_ * D_];
__device__ float g_att[(size_t)M_ * D_];
__device__ float g_y  [(size_t)M_ * D_];
__device__ float g_h  [(size_t)M_ * F_];
__device__ int   g_tlen[B_];
__device__ int   g_slen[B_];
__device__ int   g_pad[M_];

// ---------------------------------------------------------------------------
// Mask length computation with on-device dtype detection.
// bool masks may arrive as uint8, int32, or float32; detect from byte pattern:
//   any byte == 0x3F            -> float32 (1.0f = 00 00 80 3F)
//   any byte == 1 at i%4 != 0   -> uint8   (int32 1 only has byte at i%4==0)
//   else                        -> int32 (word path; also fine for float32)
// ---------------------------------------------------------------------------
__global__ void lengths_kernel(const void* tmask, const void* smask) {
    int which = blockIdx.x;                 // 0 = text, 1 = speech
    const void* mask = which ? smask : tmask;
    int T = which ? TS_ : TT_;
    int* lens = which ? g_slen : g_tlen;
    int N = B_ * T;

    __shared__ int f3F, fMis;
    __shared__ int cnt[B_];
    int tid = threadIdx.x;
    if (tid == 0) { f3F = 0; fMis = 0; }
    if (tid < B_) cnt[tid] = 0;
    __syncthreads();

    const unsigned char* bytes = (const unsigned char*)mask;
    int l3 = 0, lm = 0;
    for (int i = tid; i < N; i += blockDim.x) {
        unsigned char c = bytes[i];
        if (c == 0x3F) l3 = 1;
        if (c == 1 && (i & 3)) lm = 1;
    }
    if (l3) atomicOr(&f3F, 1);
    if (lm) atomicOr(&fMis, 1);
    __syncthreads();

    if (fMis && !f3F) {
        // uint8 storage
        for (int i = tid; i < N; i += blockDim.x)
            if (bytes[i] == 0) atomicAdd(&cnt[i / T], 1);
    } else {
        // 32-bit storage (int32 or float32): zero iff word == 0
        const unsigned int* w = (const unsigned int*)mask;
        for (int i = tid; i < N; i += blockDim.x)
            if (w[i] == 0u) atomicAdd(&cnt[i / T], 1);
    }
    __syncthreads();
    if (tid < B_) lens[tid] = cnt[tid];
}

// ---------------------------------------------------------------------------
// Build concatenated sequence x[b, pos, :] and key-padding mask
// ---------------------------------------------------------------------------
__global__ void build_x_kernel(const float* __restrict__ text,
                               const float* __restrict__ speech,
                               const float* __restrict__ cls,
                               const float* __restrict__ sep) {
    int pos = blockIdx.x, b = blockIdx.y;
    int tl = g_tlen[b], sl = g_slen[b];
    float* xr = &g_x[((size_t)(b * L_) + pos) * D_];
    if (threadIdx.x == 0)
        g_pad[b * L_ + pos] = (pos >= 2 + tl + sl) ? 1 : 0;

    const float* s;
    if (pos == 0)                 s = cls;
    else if (pos < 1 + tl)        s = &text  [((size_t)(pos - 1) * B_ + b) * D_];
    else if (pos == 1 + tl)       s = sep;
    else if (pos < 2 + tl + sl)   s = &speech[((size_t)(pos - 2 - tl) * B_ + b) * D_];
    else                          s = nullptr;

    for (int d = threadIdx.x; d < D_; d += blockDim.x)
        xr[d] = s ? s[d] : 0.f;
}

// ---------------------------------------------------------------------------
// SGEMM: C[M,N] = A[M,K] @ W[K,N] + bias[N], optional ReLU.
// 64x64 blocktile, BK=16, 256 threads, 4x4 register fragments.
// ---------------------------------------------------------------------------
template <int RELU>
__global__ __launch_bounds__(256) void gemm_kernel(
    const float* __restrict__ A, const float* __restrict__ W,
    const float* __restrict__ bias, float* __restrict__ C,
    int Mn, int Nn, int Kn) {
    __shared__ float As[16][64];   // As[k][m]
    __shared__ float Bs[16][64];   // Bs[k][n]

    int tid = threadIdx.x;
    int tx = tid & 15, ty = tid >> 4;
    int m0 = blockIdx.y * 64, n0 = blockIdx.x * 64;

    float acc[4][4] = {};
    int arow = tid >> 2, acol = (tid & 3) * 4;
    int brow = tid >> 4, bcol = (tid & 15) * 4;

    for (int k0 = 0; k0 < Kn; k0 += 16) {
        float4 av = make_float4(0.f, 0.f, 0.f, 0.f);
        if (m0 + arow < Mn)
            av = *(const float4*)&A[(size_t)(m0 + arow) * Kn + k0 + acol];
        As[acol + 0][arow] = av.x;
        As[acol + 1][arow] = av.y;
        As[acol + 2][arow] = av.z;
        As[acol + 3][arow] = av.w;
        *(float4*)&Bs[brow][bcol] =
            *(const float4*)&W[(size_t)(k0 + brow) * Nn + n0 + bcol];
        __syncthreads();

        #pragma unroll
        for (int kk = 0; kk < 16; kk++) {
            float4 a = *(float4*)&As[kk][ty * 4];
            float4 b = *(float4*)&Bs[kk][tx * 4];
            float ar[4] = {a.x, a.y, a.z, a.w};
            float br[4] = {b.x, b.y, b.z, b.w};
            #pragma unroll
            for (int i = 0; i < 4; i++)
                #pragma unroll
                for (int j = 0; j < 4; j++)
                    acc[i][j] += ar[i] * br[j];
        }
        __syncthreads();
    }

    #pragma unroll
    for (int i = 0; i < 4; i++) {
        int m = m0 + ty * 4 + i;
        if (m < Mn) {
            float4 vv;
            float* pv = (float*)&vv;
            #pragma unroll
            for (int j = 0; j < 4; j++) {
                float t = acc[i][j] + bias[n0 + tx * 4 + j];
                if (RELU) t = fmaxf(t, 0.f);
                pv[j] = t;
            }
            *(float4*)&C[(size_t)m * Nn + n0 + tx * 4] = vv;
        }
    }
}

// ---------------------------------------------------------------------------
// Fused flash attention. One block per (q-tile 64, head, batch).
// Q scaled by HD^-0.5 at load. Keys masked by pad mask / length.
// ---------------------------------------------------------------------------
__global__ __launch_bounds__(256) void attn_kernel() {
    extern __shared__ float sm[];
    float* Qs = sm;                    // [64][64] Qs[d*64+q]  (transposed)
    float* Ks = sm + 4096;             // [64][64] Ks[d*64+k]  (transposed)
    float* Vs = sm + 8192;             // [64][64] Vs[k*64+d]
    float* Pt = sm + 12288;            // [64][68] Pt[k*68+q]  (padded stride)
    float* km = sm + 12288 + 64 * 68;  // [64] key mask (1 = masked)

    int tid = threadIdx.x;
    int tx = tid & 15, ty = tid >> 4;
    int qt = blockIdx.x, h = blockIdx.y, b = blockIdx.z;
    int q0 = qt * 64;
    int ldr = tid >> 2;            // 0..63 (row loaded by this thread)
    int cb  = (tid & 3) * 16;      // column base (16 floats per thread)

    // Load Q tile transposed, pre-scaled
    {
        int qrow = q0 + ldr;
        bool valid = qrow < L_;
        const float* src = &g_q[((size_t)(b * L_) + (valid ? qrow : 0)) * D_ + h * HD_];
        #pragma unroll
        for (int u = 0; u < 16; u += 4) {
            float4 vv = valid ? *(const float4*)&src[cb + u]
                              : make_float4(0.f, 0.f, 0.f, 0.f);
            Qs[(cb + u + 0) * 64 + ldr] = vv.x * 0.125f;
            Qs[(cb + u + 1) * 64 + ldr] = vv.y * 0.125f;
            Qs[(cb + u + 2) * 64 + ldr] = vv.z * 0.125f;
            Qs[(cb + u + 3) * 64 + ldr] = vv.w * 0.125f;
        }
    }

    float o[4][4] = {};
    float mr[4]   = {-1e30f, -1e30f, -1e30f, -1e30f};
    float lsum[4] = {0.f, 0.f, 0.f, 0.f};

    const int NKT = (L_ + 63) / 64;  // 11
    for (int kt = 0; kt < NKT; kt++) {
        int k0 = kt * 64;
        __syncthreads();  // protect Vs/Pt/Qs from previous iter before overwrite

        {
            int krow = k0 + ldr;
            bool valid = krow < L_;
            const float* ksrc = &g_k[((size_t)(b * L_) + (valid ? krow : 0)) * D_ + h * HD_];
            const float* vsrc = &g_v[((size_t)(b * L_) + (valid ? krow : 0)) * D_ + h * HD_];
            #pragma unroll
            for (int u = 0; u < 16; u += 4) {
                float4 vv = valid ? *(const float4*)&ksrc[cb + u]
                                  : make_float4(0.f, 0.f, 0.f, 0.f);
                Ks[(cb + u + 0) * 64 + ldr] = vv.x;
                Ks[(cb + u + 1) * 64 + ldr] = vv.y;
                Ks[(cb + u + 2) * 64 + ldr] = vv.z;
                Ks[(cb + u + 3) * 64 + ldr] = vv.w;
            }
            #pragma unroll
            for (int u = 0; u < 16; u += 4) {
                float4 vv = valid ? *(const float4*)&vsrc[cb + u]
                                  : make_float4(0.f, 0.f, 0.f, 0.f);
                *(float4*)&Vs[ldr * 64 + cb + u] = vv;
            }
        }
        if (tid < 64) {
            int kp = k0 + tid;
            km[tid] = (kp < L_ && g_pad[b * L_ + kp] == 0) ? 0.f : 1.f;
        }
        __syncthreads();

        // S = Q^T K  (64x64, each thread 4x4)
        float s[4][4] = {};
        #pragma unroll 8
        for (int d = 0; d < 64; d++) {
            float4 a  = *(float4*)&Qs[d * 64 + ty * 4];
            float4 bb = *(float4*)&Ks[d * 64 + tx * 4];
            float ar[4] = {a.x, a.y, a.z, a.w};
            float br[4] = {bb.x, bb.y, bb.z, bb.w};
            #pragma unroll
            for (int i = 0; i < 4; i++)
                #pragma unroll
                for (int j = 0; j < 4; j++)
                    s[i][j] += ar[i] * br[j];
        }

        float kmr[4];
        #pragma unroll
        for (int j = 0; j < 4; j++) kmr[j] = km[tx * 4 + j];
        #pragma unroll
        for (int i = 0; i < 4; i++)
            #pragma unroll
            for (int j = 0; j < 4; j++)
                if (kmr[j] != 0.f) s[i][j] = -1e9f;

        // Online softmax (row stats shared across the 16 tx lanes)
        #pragma unroll
        for (int i = 0; i < 4; i++) {
            float tmax = fmaxf(fmaxf(s[i][0], s[i][1]), fmaxf(s[i][2], s[i][3]));
            #pragma unroll
            for (int off = 8; off >= 1; off >>= 1)
                tmax = fmaxf(tmax, __shfl_xor_sync(0xffffffffu, tmax, off));
            float mnew  = fmaxf(mr[i], tmax);
            float alpha = expf(mr[i] - mnew);
            float rsum = 0.f;
            #pragma unroll
            for (int j = 0; j < 4; j++) {
                float p = expf(s[i][j] - mnew);
                s[i][j] = p;
                rsum += p;
            }
            #pragma unroll
            for (int off = 8; off >= 1; off >>= 1)
                rsum += __shfl_xor_sync(0xffffffffu, rsum, off);
            lsum[i] = lsum[i] * alpha + rsum;
            mr[i] = mnew;
            #pragma unroll
            for (int j = 0; j < 4; j++) o[i][j] *= alpha;
        }

        // Write P transposed for the PV GEMM
        #pragma unroll
        for (int j = 0; j < 4; j++)
            #pragma unroll
            for (int i = 0; i < 4; i++)
                Pt[(tx * 4 + j) * 68 + ty * 4 + i] = s[i][j];
        __syncthreads();

        // O += P V
        #pragma unroll 8
        for (int kk = 0; kk < 64; kk++) {
            float4 a  = *(float4*)&Pt[kk * 68 + ty * 4];
            float4 bb = *(float4*)&Vs[kk * 64 + tx * 4];
            float ar[4] = {a.x, a.y, a.z, a.w};
            float br[4] = {bb.x, bb.y, bb.z, bb.w};
            #pragma unroll
            for (int i = 0; i < 4; i++)
                #pragma unroll
                for (int j = 0; j < 4; j++)
                    o[i][j] += ar[i] * br[j];
        }
    }

    #pragma unroll
    for (int i = 0; i < 4; i++) {
        int qrow = q0 + ty * 4 + i;
        if (qrow < L_) {
            float inv = 1.f / lsum[i];
            float4 vv = make_float4(o[i][0] * inv, o[i][1] * inv,
                                    o[i][2] * inv, o[i][3] * inv);
            *(float4*)&g_att[((size_t)(b * L_) + qrow) * D_ + h * HD_ + tx * 4] = vv;
        }
    }
}

// ---------------------------------------------------------------------------
// x = LayerNorm(x + y) * s + b  (in place on g_x; y = g_y)
// ---------------------------------------------------------------------------
__global__ __launch_bounds__(256) void add_ln_kernel(const float* __restrict__ sc,
                                                     const float* __restrict__ bi) {
    int row = blockIdx.x;
    float* xr = &g_x[(size_t)row * D_];
    const float* yr = &g_y[(size_t)row * D_];
    __shared__ float red[256];
    int tid = threadIdx.x;

    float v[4];
    float s = 0.f;
    #pragma unroll
    for (int u = 0; u < 4; u++) {
        int d = tid + u * 256;
        v[u] = xr[d] + yr[d];
        s += v[u];
    }
    red[tid] = s;
    __syncthreads();
    for (int off = 128; off > 0; off >>= 1) {
        if (tid < off) red[tid] += red[tid + off];
        __syncthreads();
    }
    float mean = red[0] * (1.f / D_);
    __syncthreads();

    float s2 = 0.f;
    #pragma unroll
    for (int u = 0; u < 4; u++) { float dd = v[u] - mean; s2 += dd * dd; }
    red[tid] = s2;
    __syncthreads();
    for (int off = 128; off > 0; off >>= 1) {
        if (tid < off) red[tid] += red[tid + off];
        __syncthreads();
    }
    float var = red[0] * (1.f / D_);
    float inv = rsqrtf(var + 1e-5f);

    #pragma unroll
    for (int u = 0; u < 4; u++) {
        int d = tid + u * 256;
        xr[d] = (v[u] - mean) * inv * sc[d] + bi[d];
    }
}

// ---------------------------------------------------------------------------
// out[b] = dot(x[b, 0, :], out_w)
// ---------------------------------------------------------------------------
__global__ __launch_bounds__(256) void final_kernel(const float* __restrict__ ow,
                                                    float* __restrict__ out) {
    int b = blockIdx.x;
    __shared__ float red[256];
    const float* xr = &g_x[(size_t)(b * L_) * D_];
    int tid = threadIdx.x;
    float s = 0.f;
    for (int d = tid; d < D_; d += 256) s += xr[d] * ow[d];
    red[tid] = s;
    __syncthreads();
    for (int off = 128; off > 0; off >>= 1) {
        if (tid < off) red[tid] += red[tid + off];
        __syncthreads();
    }
    if (tid == 0) out[b] = red[0];
}

// ---------------------------------------------------------------------------
// Launch
// ---------------------------------------------------------------------------
extern "C" void kernel_launch(void* const* d_in, const int* in_sizes, int n_in,
                              void* d_out, int out_size) {
    const float* text   = (const float*)d_in[0];
    const float* speech = (const float*)d_in[1];
    const void*  tmask  = d_in[2];
    const void*  smask  = d_in[3];
    const float* cls    = (const float*)d_in[4];
    const float* sep    = (const float*)d_in[5];
    const float* Wq     = (const float*)d_in[6];
    const float* bq     = (const float*)d_in[7];
    const float* Wk     = (const float*)d_in[8];
    const float* bk     = (const float*)d_in[9];
    const float* Wv     = (const float*)d_in[10];
    const float* bv     = (const float*)d_in[11];
    const float* Wo     = (const float*)d_in[12];
    const float* bo     = (const float*)d_in[13];
    const float* ln1s   = (const float*)d_in[14];
    const float* ln1b   = (const float*)d_in[15];
    const float* f1w    = (const float*)d_in[16];
    const float* f1b    = (const float*)d_in[17];
    const float* f2w    = (const float*)d_in[18];
    const float* f2b    = (const float*)d_in[19];
    const float* ln2s   = (const float*)d_in[20];
    const float* ln2b   = (const float*)d_in[21];
    const float* outw   = (const float*)d_in[22];
    float* out = (float*)d_out;

    float *x, *q, *k, *v, *att, *y, *hbuf;
    cudaGetSymbolAddress((void**)&x,    g_x);
    cudaGetSymbolAddress((void**)&q,    g_q);
    cudaGetSymbolAddress((void**)&k,    g_k);
    cudaGetSymbolAddress((void**)&v,    g_v);
    cudaGetSymbolAddress((void**)&att,  g_att);
    cudaGetSymbolAddress((void**)&y,    g_y);
    cudaGetSymbolAddress((void**)&hbuf, g_h);

    cudaFuncSetAttribute(attn_kernel,
                         cudaFuncAttributeMaxDynamicSharedMemorySize, SMEM_ATT);

    lengths_kernel<<<2, 256>>>(tmask, smask);
    build_x_kernel<<<dim3(L_, B_), 256>>>(text, speech, cls, sep);

    dim3 gD(D_ / 64, (M_ + 63) / 64);
    dim3 gF(F_ / 64, (M_ + 63) / 64);
    dim3 gAtt((L_ + 63) / 64, H_, B_);

    for (int l = 0; l < NL_; l++) {
        gemm_kernel<0><<<gD, 256>>>(x, Wq + (size_t)l * D_ * D_, bq + l * D_, q, M_, D_, D_);
        gemm_kernel<0><<<gD, 256>>>(x, Wk + (size_t)l * D_ * D_, bk + l * D_, k, M_, D_, D_);
        gemm_kernel<0><<<gD, 256>>>(x, Wv + (size_t)l * D_ * D_, bv + l * D_, v, M_, D_, D_);
        attn_kernel<<<gAtt, 256, SMEM_ATT>>>();
        gemm_kernel<0><<<gD, 256>>>(att, Wo + (size_t)l * D_ * D_, bo + l * D_, y, M_, D_, D_);
        add_ln_kernel<<<M_, 256>>>(ln1s + l * D_, ln1b + l * D_);
        gemm_kernel<1><<<gF, 256>>>(x, f1w + (size_t)l * D_ * F_, f1b + l * F_, hbuf, M_, F_, D_);
        gemm_kernel<0><<<gD, 256>>>(hbuf, f2w + (size_t)l * F_ * D_, f2b + l * D_, y, M_, D_, F_);
        add_ln_kernel<<<M_, 256>>>(ln2s + l * D_, ln2b + l * D_);
    }
    final_kernel<<<B_, 256>>>(outw, out);
}

// round 7
// speedup vs baseline: 2.1433x; 2.1433x over previous
#include <cuda_runtime.h>
#include <cuda_bf16.h>
#include <math.h>
#include <stdint.h>

// ---------------------------------------------------------------------------
// Problem constants
// ---------------------------------------------------------------------------
namespace {
constexpr int B_  = 16;
constexpr int TT_ = 128;
constexpr int TS_ = 512;
constexpr int L_  = TT_ + TS_ + 2;   // 642
constexpr int D_  = 1024;
constexpr int H_  = 16;
constexpr int HD_ = 64;
constexpr int F_  = 4096;
constexpr int NL_ = 4;
constexpr int M_  = B_ * L_;         // 10272
constexpr int SMEM_ATT = (4096 * 3 + 64 * 68 + 64) * 4;  // 66816 bytes

// GEMM tiling
constexpr int BK_     = 32;
constexpr int STAGES_ = 3;
constexpr int LDS_    = 40;                    // padded row stride (elements)
constexpr int ASZ_    = 128 * LDS_ * 2;        // 10240 bytes per tile array
constexpr int STAGE_B = 4 * ASZ_;              // 40960 bytes per stage
constexpr int GEMM_SMEM = STAGES_ * STAGE_B + 1024;  // 123904
}

// ---------------------------------------------------------------------------
// Scratch (allocation-free: __device__ globals)
// ---------------------------------------------------------------------------
__device__ float g_x[(size_t)M_ * D_];
__device__ float g_q[(size_t)M_ * D_];
__device__ float g_k[(size_t)M_ * D_];
__device__ float g_v[(size_t)M_ * D_];
__device__ float g_y[(size_t)M_ * D_];
__device__ __nv_bfloat16 g_xh [(size_t)M_ * D_];
__device__ __nv_bfloat16 g_xl [(size_t)M_ * D_];
__device__ __nv_bfloat16 g_ath[(size_t)M_ * D_];
__device__ __nv_bfloat16 g_atl[(size_t)M_ * D_];
__device__ __nv_bfloat16 g_hh [(size_t)M_ * F_];
__device__ __nv_bfloat16 g_hl [(size_t)M_ * F_];
// transposed + hi/lo-split weights: [N,K] layout
__device__ __nv_bfloat16 g_Wqh[(size_t)NL_ * D_ * D_];
__device__ __nv_bfloat16 g_Wql[(size_t)NL_ * D_ * D_];
__device__ __nv_bfloat16 g_Wkh[(size_t)NL_ * D_ * D_];
__device__ __nv_bfloat16 g_Wkl[(size_t)NL_ * D_ * D_];
__device__ __nv_bfloat16 g_Wvh[(size_t)NL_ * D_ * D_];
__device__ __nv_bfloat16 g_Wvl[(size_t)NL_ * D_ * D_];
__device__ __nv_bfloat16 g_Woh[(size_t)NL_ * D_ * D_];
__device__ __nv_bfloat16 g_Wol[(size_t)NL_ * D_ * D_];
__device__ __nv_bfloat16 g_F1h[(size_t)NL_ * D_ * F_];
__device__ __nv_bfloat16 g_F1l[(size_t)NL_ * D_ * F_];
__device__ __nv_bfloat16 g_F2h[(size_t)NL_ * F_ * D_];
__device__ __nv_bfloat16 g_F2l[(size_t)NL_ * F_ * D_];
__device__ int g_tlen[B_];
__device__ int g_slen[B_];
__device__ int g_pad[M_];

// ---------------------------------------------------------------------------
// PTX helpers (sm_80-era subset only: cp.async, ldmatrix, mma.sync)
// ---------------------------------------------------------------------------
__device__ __forceinline__ uint32_t s2u(const void* p) {
    uint32_t a;
    asm("{ .reg .u64 t; cvta.to.shared.u64 t, %1; cvt.u32.u64 %0, t; }"
        : "=r"(a) : "l"(p));
    return a;
}
__device__ __forceinline__ void cp16(uint32_t s, const void* g, int nbytes) {
    asm volatile("cp.async.cg.shared.global [%0], [%1], 16, %2;"
                 :: "r"(s), "l"(g), "r"(nbytes));
}
__device__ __forceinline__ void cp_commit() {
    asm volatile("cp.async.commit_group;");
}
template <int N> __device__ __forceinline__ void cp_wait() {
    asm volatile("cp.async.wait_group %0;" :: "n"(N));
}
__device__ __forceinline__ void ldsm4(uint32_t* r, uint32_t addr) {
    asm volatile("ldmatrix.sync.aligned.m8n8.x4.shared.b16 {%0,%1,%2,%3}, [%4];"
                 : "=r"(r[0]), "=r"(r[1]), "=r"(r[2]), "=r"(r[3]) : "r"(addr));
}
__device__ __forceinline__ void mma16816(float* c, const uint32_t* a,
                                         uint32_t b0, uint32_t b1) {
    asm volatile(
        "mma.sync.aligned.m16n8k16.row.col.f32.bf16.bf16.f32 "
        "{%0,%1,%2,%3}, {%4,%5,%6,%7}, {%8,%9}, {%0,%1,%2,%3};\n"
        : "+f"(c[0]), "+f"(c[1]), "+f"(c[2]), "+f"(c[3])
        : "r"(a[0]), "r"(a[1]), "r"(a[2]), "r"(a[3]), "r"(b0), "r"(b1));
}

// ---------------------------------------------------------------------------
// Mask length computation with on-device dtype detection
// ---------------------------------------------------------------------------
__global__ void lengths_kernel(const void* tmask, const void* smask) {
    int which = blockIdx.x;
    const void* mask = which ? smask : tmask;
    int T = which ? TS_ : TT_;
    int* lens = which ? g_slen : g_tlen;
    int N = B_ * T;

    __shared__ int f3F, fMis;
    __shared__ int cnt[B_];
    int tid = threadIdx.x;
    if (tid == 0) { f3F = 0; fMis = 0; }
    if (tid < B_) cnt[tid] = 0;
    __syncthreads();

    const unsigned char* bytes = (const unsigned char*)mask;
    int l3 = 0, lm = 0;
    for (int i = tid; i < N; i += blockDim.x) {
        unsigned char c = bytes[i];
        if (c == 0x3F) l3 = 1;
        if (c == 1 && (i & 3)) lm = 1;
    }
    if (l3) atomicOr(&f3F, 1);
    if (lm) atomicOr(&fMis, 1);
    __syncthreads();

    if (fMis && !f3F) {
        for (int i = tid; i < N; i += blockDim.x)
            if (bytes[i] == 0) atomicAdd(&cnt[i / T], 1);
    } else {
        const unsigned int* w = (const unsigned int*)mask;
        for (int i = tid; i < N; i += blockDim.x)
            if (w[i] == 0u) atomicAdd(&cnt[i / T], 1);
    }
    __syncthreads();
    if (tid < B_) lens[tid] = cnt[tid];
}

// ---------------------------------------------------------------------------
// Build concatenated sequence x (fp32 + bf16 hi/lo) and key-padding mask
// ---------------------------------------------------------------------------
__global__ void build_x_kernel(const float* __restrict__ text,
                               const float* __restrict__ speech,
                               const float* __restrict__ cls,
                               const float* __restrict__ sep) {
    int pos = blockIdx.x, b = blockIdx.y;
    int tl = g_tlen[b], sl = g_slen[b];
    size_t base = ((size_t)(b * L_) + pos) * D_;
    if (threadIdx.x == 0)
        g_pad[b * L_ + pos] = (pos >= 2 + tl + sl) ? 1 : 0;

    const float* s;
    if (pos == 0)                 s = cls;
    else if (pos < 1 + tl)        s = &text  [((size_t)(pos - 1) * B_ + b) * D_];
    else if (pos == 1 + tl)       s = sep;
    else if (pos < 2 + tl + sl)   s = &speech[((size_t)(pos - 2 - tl) * B_ + b) * D_];
    else                          s = nullptr;

    for (int d = threadIdx.x; d < D_; d += blockDim.x) {
        float v = s ? s[d] : 0.f;
        g_x[base + d] = v;
        __nv_bfloat16 h = __float2bfloat16(v);
        g_xh[base + d] = h;
        g_xl[base + d] = __float2bfloat16(v - __bfloat162float(h));
    }
}

// ---------------------------------------------------------------------------
// Weight transpose + hi/lo split: W[K,N] fp32 -> Th/Tl[N,K] bf16
// ---------------------------------------------------------------------------
__global__ void wsplit_kernel(const float* __restrict__ W,
                              __nv_bfloat16* __restrict__ Th,
                              __nv_bfloat16* __restrict__ Tl, int K, int N) {
    __shared__ float t[32][33];
    int n0 = blockIdx.x * 32, k0 = blockIdx.y * 32;
    int tx = threadIdx.x, ty = threadIdx.y;
    #pragma unroll
    for (int j = 0; j < 4; j++) {
        int k = k0 + ty + j * 8;
        t[ty + j * 8][tx] = W[(size_t)k * N + n0 + tx];
    }
    __syncthreads();
    #pragma unroll
    for (int j = 0; j < 4; j++) {
        int n = n0 + ty + j * 8;
        float v = t[tx][ty + j * 8];
        __nv_bfloat16 h = __float2bfloat16(v);
        Th[(size_t)n * K + k0 + tx] = h;
        Tl[(size_t)n * K + k0 + tx] = __float2bfloat16(v - __bfloat162float(h));
    }
}

// ---------------------------------------------------------------------------
// HMMA bf16 GEMM with 3-term hi/lo compensation.
// C[M,N] = A[M,K] @ B^T[N,K] + bias (A/B pre-split into hi/lo bf16).
// 128x128x32 tile, 256 threads (8 warps, 2x4), 3-stage cp.async pipeline.
// MODE 0: write fp32 C. MODE 1: write bf16 hi/lo C (after optional RELU).
// ---------------------------------------------------------------------------
template <int RELU, int MODE>
__global__ __launch_bounds__(256, 1) void gemm_mma(
    const __nv_bfloat16* __restrict__ Ah, const __nv_bfloat16* __restrict__ Al,
    const __nv_bfloat16* __restrict__ Bh, const __nv_bfloat16* __restrict__ Bl,
    const float* __restrict__ bias,
    float* __restrict__ Cf,
    __nv_bfloat16* __restrict__ Ch, __nv_bfloat16* __restrict__ Cl,
    int Mn, int Nn, int Kn) {
    extern __shared__ char dynsmem[];
    uint32_t sbase = (s2u(dynsmem) + 1023u) & ~1023u;
    int tid = threadIdx.x;
    int wid = tid >> 5, lane = tid & 31;
    int m0 = blockIdx.y * 128, n0 = blockIdx.x * 128;
    int wm = wid & 1, wn = wid >> 1;
    int m0w = wm * 64, n0w = wn * 32;
    const int T = Kn / BK_;

    int la = tid >> 6;        // 0..3 -> Ah, Al, Bh, Bl
    int t6 = tid & 63;

    auto issue = [&](int kt) {
        uint32_t stb = sbase + (kt % STAGES_) * STAGE_B + la * ASZ_;
        #pragma unroll
        for (int i = 0; i < 8; i++) {
            int chunk = t6 + 64 * i;          // 0..511
            int row = chunk >> 2;             // 0..127
            int col = chunk & 3;              // 16B chunk within 64B row
            uint32_t dst = stb + (uint32_t)(row * LDS_ + col * 8) * 2;
            if (la < 2) {
                int gr = m0 + row;
                bool v = gr < Mn;
                const __nv_bfloat16* src =
                    (la ? Al : Ah) + (size_t)(v ? gr : 0) * Kn + kt * BK_ + col * 8;
                cp16(dst, src, v ? 16 : 0);
            } else {
                const __nv_bfloat16* src =
                    (la == 2 ? Bh : Bl) + (size_t)(n0 + row) * Kn + kt * BK_ + col * 8;
                cp16(dst, src, 16);
            }
        }
        cp_commit();
    };

    issue(0);
    issue(1);

    float acc[4][4][4];
    #pragma unroll
    for (int i = 0; i < 4; i++)
        #pragma unroll
        for (int j = 0; j < 4; j++)
            #pragma unroll
            for (int p = 0; p < 4; p++) acc[i][j][p] = 0.f;

    int lr = lane & 15, lc8 = (lane >> 4) * 8;

    for (int kt = 0; kt < T; kt++) {
        cp_wait<STAGES_ - 2>();
        __syncthreads();
        uint32_t stb = sbase + (kt % STAGES_) * STAGE_B;
        #pragma unroll
        for (int kk = 0; kk < 2; kk++) {
            int koff = kk * 16 + lc8;
            uint32_t ah[4][4], al[4][4], bh[2][4], bl[2][4];
            #pragma unroll
            for (int im = 0; im < 4; im++) {
                uint32_t ad = stb + (uint32_t)((m0w + im * 16 + lr) * LDS_ + koff) * 2;
                ldsm4(ah[im], ad);
                ldsm4(al[im], ad + ASZ_);
            }
            #pragma unroll
            for (int ib = 0; ib < 2; ib++) {
                uint32_t bd = stb + 2 * ASZ_ +
                              (uint32_t)((n0w + ib * 16 + lr) * LDS_ + koff) * 2;
                ldsm4(bh[ib], bd);
                ldsm4(bl[ib], bd + ASZ_);
            }
            #pragma unroll
            for (int im = 0; im < 4; im++)
                #pragma unroll
                for (int in = 0; in < 4; in++) {
                    int ib = in >> 1, sb = in & 1;
                    mma16816(acc[im][in], ah[im], bh[ib][sb], bh[ib][sb + 2]);
                    mma16816(acc[im][in], ah[im], bl[ib][sb], bl[ib][sb + 2]);
                    mma16816(acc[im][in], al[im], bh[ib][sb], bh[ib][sb + 2]);
                }
        }
        int nt = kt + STAGES_ - 1;
        if (nt < T) issue(nt); else cp_commit();
    }

    // Epilogue
    int g = lane >> 2, tq = lane & 3;
    #pragma unroll
    for (int in = 0; in < 4; in++) {
        int cb = n0 + n0w + in * 8 + tq * 2;
        float b0 = __ldg(&bias[cb]), b1 = __ldg(&bias[cb + 1]);
        #pragma unroll
        for (int im = 0; im < 4; im++) {
            #pragma unroll
            for (int hrow = 0; hrow < 2; hrow++) {
                int m = m0 + m0w + im * 16 + g + hrow * 8;
                if (m < Mn) {
                    float v0 = acc[im][in][hrow * 2 + 0] + b0;
                    float v1 = acc[im][in][hrow * 2 + 1] + b1;
                    if (RELU) { v0 = fmaxf(v0, 0.f); v1 = fmaxf(v1, 0.f); }
                    if (MODE == 0) {
                        *(float2*)&Cf[(size_t)m * Nn + cb] = make_float2(v0, v1);
                    } else {
                        __nv_bfloat16 h0 = __float2bfloat16(v0);
                        __nv_bfloat16 h1 = __float2bfloat16(v1);
                        float l0 = v0 - __bfloat162float(h0);
                        float l1 = v1 - __bfloat162float(h1);
                        __nv_bfloat162 hh2 = __halves2bfloat162(h0, h1);
                        __nv_bfloat162 ll2 = __halves2bfloat162(
                            __float2bfloat16(l0), __float2bfloat16(l1));
                        *(uint32_t*)&Ch[(size_t)m * Nn + cb] = *(uint32_t*)&hh2;
                        *(uint32_t*)&Cl[(size_t)m * Nn + cb] = *(uint32_t*)&ll2;
                    }
                }
            }
        }
    }
}

// ---------------------------------------------------------------------------
// Fused flash attention (fp32), valid-length aware, writes bf16 hi/lo output.
// ---------------------------------------------------------------------------
__global__ __launch_bounds__(256) void attn_kernel() {
    extern __shared__ float sm[];
    float* Qs = sm;
    float* Ks = sm + 4096;
    float* Vs = sm + 8192;
    float* Pt = sm + 12288;
    float* km = sm + 12288 + 64 * 68;

    int tid = threadIdx.x;
    int tx = tid & 15, ty = tid >> 4;
    int qt = blockIdx.x, h = blockIdx.y, b = blockIdx.z;
    int q0 = qt * 64;
    int ldr = tid >> 2;
    int cb  = (tid & 3) * 16;

    int Lv = 2 + g_tlen[b] + g_slen[b];
    if (q0 >= Lv) {
        int r2 = tid >> 2;
        int c2 = (tid & 3) * 16;
        int qrow = q0 + r2;
        if (qrow < L_) {
            size_t base = ((size_t)(b * L_) + qrow) * D_ + h * HD_ + c2;
            uint4 z = make_uint4(0, 0, 0, 0);
            *(uint4*)&g_ath[base] = z;   *(uint4*)&g_ath[base + 8] = z;
            *(uint4*)&g_atl[base] = z;   *(uint4*)&g_atl[base + 8] = z;
        }
        return;
    }

    {
        int qrow = q0 + ldr;
        bool valid = qrow < L_;
        const float* src = &g_q[((size_t)(b * L_) + (valid ? qrow : 0)) * D_ + h * HD_];
        #pragma unroll
        for (int u = 0; u < 16; u += 4) {
            float4 vv = valid ? *(const float4*)&src[cb + u]
                              : make_float4(0.f, 0.f, 0.f, 0.f);
            Qs[(cb + u + 0) * 64 + ldr] = vv.x * 0.125f;
            Qs[(cb + u + 1) * 64 + ldr] = vv.y * 0.125f;
            Qs[(cb + u + 2) * 64 + ldr] = vv.z * 0.125f;
            Qs[(cb + u + 3) * 64 + ldr] = vv.w * 0.125f;
        }
    }

    float o[4][4] = {};
    float mr[4]   = {-1e30f, -1e30f, -1e30f, -1e30f};
    float lsum[4] = {0.f, 0.f, 0.f, 0.f};

    const int NKT = (Lv + 63) >> 6;
    for (int kt = 0; kt < NKT; kt++) {
        int k0 = kt * 64;
        __syncthreads();

        {
            int krow = k0 + ldr;
            bool valid = krow < L_;
            const float* ksrc = &g_k[((size_t)(b * L_) + (valid ? krow : 0)) * D_ + h * HD_];
            const float* vsrc = &g_v[((size_t)(b * L_) + (valid ? krow : 0)) * D_ + h * HD_];
            #pragma unroll
            for (int u = 0; u < 16; u += 4) {
                float4 vv = valid ? *(const float4*)&ksrc[cb + u]
                                  : make_float4(0.f, 0.f, 0.f, 0.f);
                Ks[(cb + u + 0) * 64 + ldr] = vv.x;
                Ks[(cb + u + 1) * 64 + ldr] = vv.y;
                Ks[(cb + u + 2) * 64 + ldr] = vv.z;
                Ks[(cb + u + 3) * 64 + ldr] = vv.w;
            }
            #pragma unroll
            for (int u = 0; u < 16; u += 4) {
                float4 vv = valid ? *(const float4*)&vsrc[cb + u]
                                  : make_float4(0.f, 0.f, 0.f, 0.f);
                *(float4*)&Vs[ldr * 64 + cb + u] = vv;
            }
        }
        if (tid < 64) {
            int kp = k0 + tid;
            km[tid] = (kp < L_ && g_pad[b * L_ + kp] == 0) ? 0.f : 1.f;
        }
        __syncthreads();

        float s[4][4] = {};
        #pragma unroll 8
        for (int d = 0; d < 64; d++) {
            float4 a  = *(float4*)&Qs[d * 64 + ty * 4];
            float4 bb = *(float4*)&Ks[d * 64 + tx * 4];
            float ar[4] = {a.x, a.y, a.z, a.w};
            float br[4] = {bb.x, bb.y, bb.z, bb.w};
            #pragma unroll
            for (int i = 0; i < 4; i++)
                #pragma unroll
                for (int j = 0; j < 4; j++)
                    s[i][j] += ar[i] * br[j];
        }

        float kmr[4];
        #pragma unroll
        for (int j = 0; j < 4; j++) kmr[j] = km[tx * 4 + j];
        #pragma unroll
        for (int i = 0; i < 4; i++)
            #pragma unroll
            for (int j = 0; j < 4; j++)
                if (kmr[j] != 0.f) s[i][j] = -1e9f;

        #pragma unroll
        for (int i = 0; i < 4; i++) {
            float tmax = fmaxf(fmaxf(s[i][0], s[i][1]), fmaxf(s[i][2], s[i][3]));
            #pragma unroll
            for (int off = 8; off >= 1; off >>= 1)
                tmax = fmaxf(tmax, __shfl_xor_sync(0xffffffffu, tmax, off));
            float mnew  = fmaxf(mr[i], tmax);
            float alpha = expf(mr[i] - mnew);
            float rsum = 0.f;
            #pragma unroll
            for (int j = 0; j < 4; j++) {
                float p = expf(s[i][j] - mnew);
                s[i][j] = p;
                rsum += p;
            }
            #pragma unroll
            for (int off = 8; off >= 1; off >>= 1)
                rsum += __shfl_xor_sync(0xffffffffu, rsum, off);
            lsum[i] = lsum[i] * alpha + rsum;
            mr[i] = mnew;
            #pragma unroll
            for (int j = 0; j < 4; j++) o[i][j] *= alpha;
        }

        #pragma unroll
        for (int j = 0; j < 4; j++)
            #pragma unroll
            for (int i = 0; i < 4; i++)
                Pt[(tx * 4 + j) * 68 + ty * 4 + i] = s[i][j];
        __syncthreads();

        #pragma unroll 8
        for (int kk = 0; kk < 64; kk++) {
            float4 a  = *(float4*)&Pt[kk * 68 + ty * 4];
            float4 bb = *(float4*)&Vs[kk * 64 + tx * 4];
            float ar[4] = {a.x, a.y, a.z, a.w};
            float br[4] = {bb.x, bb.y, bb.z, bb.w};
            #pragma unroll
            for (int i = 0; i < 4; i++)
                #pragma unroll
                for (int j = 0; j < 4; j++)
                    o[i][j] += ar[i] * br[j];
        }
    }

    #pragma unroll
    for (int i = 0; i < 4; i++) {
        int qrow = q0 + ty * 4 + i;
        if (qrow < L_) {
            float inv = 1.f / lsum[i];
            size_t base = ((size_t)(b * L_) + qrow) * D_ + h * HD_ + tx * 4;
            #pragma unroll
            for (int j = 0; j < 4; j++) {
                float t = o[i][j] * inv;
                __nv_bfloat16 hh = __float2bfloat16(t);
                g_ath[base + j] = hh;
                g_atl[base + j] = __float2bfloat16(t - __bfloat162float(hh));
            }
        }
    }
}

// ---------------------------------------------------------------------------
// x = LayerNorm(x + y) * s + b (in place) + bf16 hi/lo emission
// ---------------------------------------------------------------------------
__global__ __launch_bounds__(256) void add_ln_kernel(const float* __restrict__ sc,
                                                     const float* __restrict__ bi) {
    int row = blockIdx.x;
    size_t base = (size_t)row * D_;
    __shared__ float red[256];
    int tid = threadIdx.x;

    float v[4];
    float s = 0.f;
    #pragma unroll
    for (int u = 0; u < 4; u++) {
        int d = tid + u * 256;
        v[u] = g_x[base + d] + g_y[base + d];
        s += v[u];
    }
    red[tid] = s;
    __syncthreads();
    for (int off = 128; off > 0; off >>= 1) {
        if (tid < off) red[tid] += red[tid + off];
        __syncthreads();
    }
    float mean = red[0] * (1.f / D_);
    __syncthreads();

    float s2 = 0.f;
    #pragma unroll
    for (int u = 0; u < 4; u++) { float dd = v[u] - mean; s2 += dd * dd; }
    red[tid] = s2;
    __syncthreads();
    for (int off = 128; off > 0; off >>= 1) {
        if (tid < off) red[tid] += red[tid + off];
        __syncthreads();
    }
    float var = red[0] * (1.f / D_);
    float inv = rsqrtf(var + 1e-5f);

    #pragma unroll
    for (int u = 0; u < 4; u++) {
        int d = tid + u * 256;
        float t = (v[u] - mean) * inv * sc[d] + bi[d];
        g_x[base + d] = t;
        __nv_bfloat16 hh = __float2bfloat16(t);
        g_xh[base + d] = hh;
        g_xl[base + d] = __float2bfloat16(t - __bfloat162float(hh));
    }
}

// ---------------------------------------------------------------------------
// out[b] = dot(x[b, 0, :], out_w)
// ---------------------------------------------------------------------------
__global__ __launch_bounds__(256) void final_kernel(const float* __restrict__ ow,
                                                    float* __restrict__ out) {
    int b = blockIdx.x;
    __shared__ float red[256];
    const float* xr = &g_x[(size_t)(b * L_) * D_];
    int tid = threadIdx.x;
    float s = 0.f;
    for (int d = tid; d < D_; d += 256) s += xr[d] * ow[d];
    red[tid] = s;
    __syncthreads();
    for (int off = 128; off > 0; off >>= 1) {
        if (tid < off) red[tid] += red[tid + off];
        __syncthreads();
    }
    if (tid == 0) out[b] = red[0];
}

// ---------------------------------------------------------------------------
// Launch
// ---------------------------------------------------------------------------
extern "C" void kernel_launch(void* const* d_in, const int* in_sizes, int n_in,
                              void* d_out, int out_size) {
    const float* text   = (const float*)d_in[0];
    const float* speech = (const float*)d_in[1];
    const void*  tmask  = d_in[2];
    const void*  smask  = d_in[3];
    const float* cls    = (const float*)d_in[4];
    const float* sep    = (const float*)d_in[5];
    const float* Wq     = (const float*)d_in[6];
    const float* bq     = (const float*)d_in[7];
    const float* Wk     = (const float*)d_in[8];
    const float* bk     = (const float*)d_in[9];
    const float* Wv     = (const float*)d_in[10];
    const float* bv     = (const float*)d_in[11];
    const float* Wo     = (const float*)d_in[12];
    const float* bo     = (const float*)d_in[13];
    const float* ln1s   = (const float*)d_in[14];
    const float* ln1b   = (const float*)d_in[15];
    const float* f1w    = (const float*)d_in[16];
    const float* f1b    = (const float*)d_in[17];
    const float* f2w    = (const float*)d_in[18];
    const float* f2b    = (const float*)d_in[19];
    const float* ln2s   = (const float*)d_in[20];
    const float* ln2b   = (const float*)d_in[21];
    const float* outw   = (const float*)d_in[22];
    float* out = (float*)d_out;

    float *q, *k, *v, *y;
    __nv_bfloat16 *xh, *xl, *ath, *atl, *hh, *hl;
    __nv_bfloat16 *Wqh, *Wql, *Wkh, *Wkl, *Wvh, *Wvl, *Woh, *Wol, *F1h, *F1l, *F2h, *F2l;
    cudaGetSymbolAddress((void**)&q,   g_q);
    cudaGetSymbolAddress((void**)&k,   g_k);
    cudaGetSymbolAddress((void**)&v,   g_v);
    cudaGetSymbolAddress((void**)&y,   g_y);
    cudaGetSymbolAddress((void**)&xh,  g_xh);
    cudaGetSymbolAddress((void**)&xl,  g_xl);
    cudaGetSymbolAddress((void**)&ath, g_ath);
    cudaGetSymbolAddress((void**)&atl, g_atl);
    cudaGetSymbolAddress((void**)&hh,  g_hh);
    cudaGetSymbolAddress((void**)&hl,  g_hl);
    cudaGetSymbolAddress((void**)&Wqh, g_Wqh);
    cudaGetSymbolAddress((void**)&Wql, g_Wql);
    cudaGetSymbolAddress((void**)&Wkh, g_Wkh);
    cudaGetSymbolAddress((void**)&Wkl, g_Wkl);
    cudaGetSymbolAddress((void**)&Wvh, g_Wvh);
    cudaGetSymbolAddress((void**)&Wvl, g_Wvl);
    cudaGetSymbolAddress((void**)&Woh, g_Woh);
    cudaGetSymbolAddress((void**)&Wol, g_Wol);
    cudaGetSymbolAddress((void**)&F1h, g_F1h);
    cudaGetSymbolAddress((void**)&F1l, g_F1l);
    cudaGetSymbolAddress((void**)&F2h, g_F2h);
    cudaGetSymbolAddress((void**)&F2l, g_F2l);

    cudaFuncSetAttribute(attn_kernel,
                         cudaFuncAttributeMaxDynamicSharedMemorySize, SMEM_ATT);
    cudaFuncSetAttribute(gemm_mma<0, 0>,
                         cudaFuncAttributeMaxDynamicSharedMemorySize, GEMM_SMEM);
    cudaFuncSetAttribute(gemm_mma<1, 1>,
                         cudaFuncAttributeMaxDynamicSharedMemorySize, GEMM_SMEM);

    lengths_kernel<<<2, 256>>>(tmask, smask);
    build_x_kernel<<<dim3(L_, B_), 256>>>(text, speech, cls, sep);

    dim3 tb(32, 8);
    for (int l = 0; l < NL_; l++) {
        size_t od = (size_t)l * D_ * D_;
        size_t o1 = (size_t)l * D_ * F_;
        size_t o2 = (size_t)l * F_ * D_;
        wsplit_kernel<<<dim3(D_ / 32, D_ / 32), tb>>>(Wq + od, Wqh + od, Wql + od, D_, D_);
        wsplit_kernel<<<dim3(D_ / 32, D_ / 32), tb>>>(Wk + od, Wkh + od, Wkl + od, D_, D_);
        wsplit_kernel<<<dim3(D_ / 32, D_ / 32), tb>>>(Wv + od, Wvh + od, Wvl + od, D_, D_);
        wsplit_kernel<<<dim3(D_ / 32, D_ / 32), tb>>>(Wo + od, Woh + od, Wol + od, D_, D_);
        wsplit_kernel<<<dim3(F_ / 32, D_ / 32), tb>>>(f1w + o1, F1h + o1, F1l + o1, D_, F_);
        wsplit_kernel<<<dim3(D_ / 32, F_ / 32), tb>>>(f2w + o2, F2h + o2, F2l + o2, F_, D_);
    }

    int mt = (M_ + 127) / 128;  // 81
    dim3 gD(D_ / 128, mt);
    dim3 gF(F_ / 128, mt);
    dim3 gAtt((L_ + 63) / 64, H_, B_);

    for (int l = 0; l < NL_; l++) {
        size_t od = (size_t)l * D_ * D_;
        size_t o1 = (size_t)l * D_ * F_;
        size_t o2 = (size_t)l * F_ * D_;
        gemm_mma<0, 0><<<gD, 256, GEMM_SMEM>>>(xh, xl, Wqh + od, Wql + od, bq + l * D_,
                                               q, nullptr, nullptr, M_, D_, D_);
        gemm_mma<0, 0><<<gD, 256, GEMM_SMEM>>>(xh, xl, Wkh + od, Wkl + od, bk + l * D_,
                                               k, nullptr, nullptr, M_, D_, D_);
        gemm_mma<0, 0><<<gD, 256, GEMM_SMEM>>>(xh, xl, Wvh + od, Wvl + od, bv + l * D_,
                                               v, nullptr, nullptr, M_, D_, D_);
        attn_kernel<<<gAtt, 256, SMEM_ATT>>>();
        gemm_mma<0, 0><<<gD, 256, GEMM_SMEM>>>(ath, atl, Woh + od, Wol + od, bo + l * D_,
                                               y, nullptr, nullptr, M_, D_, D_);
        add_ln_kernel<<<M_, 256>>>(ln1s + l * D_, ln1b + l * D_);
        gemm_mma<1, 1><<<gF, 256, GEMM_SMEM>>>(xh, xl, F1h + o1, F1l + o1, f1b + l * F_,
                                               nullptr, hh, hl, M_, F_, D_);
        gemm_mma<0, 0><<<gD, 256, GEMM_SMEM>>>(hh, hl, F2h + o2, F2l + o2, f2b + l * D_,
                                               y, nullptr, nullptr, M_, D_, F_);
        add_ln_kernel<<<M_, 256>>>(ln2s + l * D_, ln2b + l * D_);
    }
    final_kernel<<<B_, 256>>>(outw, out);
}

// round 8
// speedup vs baseline: 2.6023x; 1.2142x over previous
#include <cuda_runtime.h>
#include <cuda_bf16.h>
#include <math.h>
#include <stdint.h>

// ---------------------------------------------------------------------------
// Problem constants
// ---------------------------------------------------------------------------
namespace {
constexpr int B_  = 16;
constexpr int TT_ = 128;
constexpr int TS_ = 512;
constexpr int L_  = TT_ + TS_ + 2;   // 642
constexpr int D_  = 1024;
constexpr int H_  = 16;
constexpr int HD_ = 64;
constexpr int F_  = 4096;
constexpr int NL_ = 4;
constexpr int M_  = B_ * L_;         // 10272
constexpr int SMEM_ATT = (4096 * 3 + 64 * 68 + 64) * 4;  // 66816 bytes

// GEMM tiling
constexpr int BK_     = 32;
constexpr int STAGES_ = 3;
constexpr int LDS_    = 40;                    // padded row stride (elements)
constexpr int ASZ_    = 128 * LDS_ * 2;        // 10240 bytes per tile array
constexpr int STAGE_B = 4 * ASZ_;              // 40960 bytes per stage
constexpr int GEMM_SMEM = STAGES_ * STAGE_B + 1024;  // 123904
}

// ---------------------------------------------------------------------------
// Scratch (allocation-free: __device__ globals)
// ---------------------------------------------------------------------------
__device__ float g_x[(size_t)M_ * D_];
__device__ float g_q[(size_t)M_ * D_];
__device__ float g_k[(size_t)M_ * D_];
__device__ float g_v[(size_t)M_ * D_];
__device__ float g_y[(size_t)M_ * D_];
__device__ __nv_bfloat16 g_xh [(size_t)M_ * D_];
__device__ __nv_bfloat16 g_xl [(size_t)M_ * D_];
__device__ __nv_bfloat16 g_ath[(size_t)M_ * D_];
__device__ __nv_bfloat16 g_atl[(size_t)M_ * D_];
__device__ __nv_bfloat16 g_hh [(size_t)M_ * F_];
__device__ __nv_bfloat16 g_hl [(size_t)M_ * F_];
// transposed + hi/lo-split weights: [N,K] layout
__device__ __nv_bfloat16 g_Wqh[(size_t)NL_ * D_ * D_];
__device__ __nv_bfloat16 g_Wql[(size_t)NL_ * D_ * D_];
__device__ __nv_bfloat16 g_Wkh[(size_t)NL_ * D_ * D_];
__device__ __nv_bfloat16 g_Wkl[(size_t)NL_ * D_ * D_];
__device__ __nv_bfloat16 g_Wvh[(size_t)NL_ * D_ * D_];
__device__ __nv_bfloat16 g_Wvl[(size_t)NL_ * D_ * D_];
__device__ __nv_bfloat16 g_Woh[(size_t)NL_ * D_ * D_];
__device__ __nv_bfloat16 g_Wol[(size_t)NL_ * D_ * D_];
__device__ __nv_bfloat16 g_F1h[(size_t)NL_ * D_ * F_];
__device__ __nv_bfloat16 g_F1l[(size_t)NL_ * D_ * F_];
__device__ __nv_bfloat16 g_F2h[(size_t)NL_ * F_ * D_];
__device__ __nv_bfloat16 g_F2l[(size_t)NL_ * F_ * D_];
__device__ int g_tlen[B_];
__device__ int g_slen[B_];
__device__ int g_pad[M_];

// ---------------------------------------------------------------------------
// PTX helpers (sm_80-era subset only: cp.async, ldmatrix, mma.sync)
// ---------------------------------------------------------------------------
__device__ __forceinline__ uint32_t s2u(const void* p) {
    uint32_t a;
    asm("{ .reg .u64 t; cvta.to.shared.u64 t, %1; cvt.u32.u64 %0, t; }"
        : "=r"(a) : "l"(p));
    return a;
}
__device__ __forceinline__ void cp16(uint32_t s, const void* g, int nbytes) {
    asm volatile("cp.async.cg.shared.global [%0], [%1], 16, %2;"
                 :: "r"(s), "l"(g), "r"(nbytes));
}
__device__ __forceinline__ void cp_commit() {
    asm volatile("cp.async.commit_group;");
}
template <int N> __device__ __forceinline__ void cp_wait() {
    asm volatile("cp.async.wait_group %0;" :: "n"(N));
}
__device__ __forceinline__ void ldsm4(uint32_t* r, uint32_t addr) {
    asm volatile("ldmatrix.sync.aligned.m8n8.x4.shared.b16 {%0,%1,%2,%3}, [%4];"
                 : "=r"(r[0]), "=r"(r[1]), "=r"(r[2]), "=r"(r[3]) : "r"(addr));
}
__device__ __forceinline__ void mma16816(float* c, const uint32_t* a,
                                         uint32_t b0, uint32_t b1) {
    asm volatile(
        "mma.sync.aligned.m16n8k16.row.col.f32.bf16.bf16.f32 "
        "{%0,%1,%2,%3}, {%4,%5,%6,%7}, {%8,%9}, {%0,%1,%2,%3};\n"
        : "+f"(c[0]), "+f"(c[1]), "+f"(c[2]), "+f"(c[3])
        : "r"(a[0]), "r"(a[1]), "r"(a[2]), "r"(a[3]), "r"(b0), "r"(b1));
}

// ---------------------------------------------------------------------------
// Mask length computation with on-device dtype detection
// ---------------------------------------------------------------------------
__global__ void lengths_kernel(const void* tmask, const void* smask) {
    int which = blockIdx.x;
    const void* mask = which ? smask : tmask;
    int T = which ? TS_ : TT_;
    int* lens = which ? g_slen : g_tlen;
    int N = B_ * T;

    __shared__ int f3F, fMis;
    __shared__ int cnt[B_];
    int tid = threadIdx.x;
    if (tid == 0) { f3F = 0; fMis = 0; }
    if (tid < B_) cnt[tid] = 0;
    __syncthreads();

    const unsigned char* bytes = (const unsigned char*)mask;
    int l3 = 0, lm = 0;
    for (int i = tid; i < N; i += blockDim.x) {
        unsigned char c = bytes[i];
        if (c == 0x3F) l3 = 1;
        if (c == 1 && (i & 3)) lm = 1;
    }
    if (l3) atomicOr(&f3F, 1);
    if (lm) atomicOr(&fMis, 1);
    __syncthreads();

    if (fMis && !f3F) {
        for (int i = tid; i < N; i += blockDim.x)
            if (bytes[i] == 0) atomicAdd(&cnt[i / T], 1);
    } else {
        const unsigned int* w = (const unsigned int*)mask;
        for (int i = tid; i < N; i += blockDim.x)
            if (w[i] == 0u) atomicAdd(&cnt[i / T], 1);
    }
    __syncthreads();
    if (tid < B_) lens[tid] = cnt[tid];
}

// ---------------------------------------------------------------------------
// Build concatenated sequence x (fp32 + bf16 hi/lo) and key-padding mask
// ---------------------------------------------------------------------------
__global__ void build_x_kernel(const float* __restrict__ text,
                               const float* __restrict__ speech,
                               const float* __restrict__ cls,
                               const float* __restrict__ sep) {
    int pos = blockIdx.x, b = blockIdx.y;
    int tl = g_tlen[b], sl = g_slen[b];
    size_t base = ((size_t)(b * L_) + pos) * D_;
    if (threadIdx.x == 0)
        g_pad[b * L_ + pos] = (pos >= 2 + tl + sl) ? 1 : 0;

    const float* s;
    if (pos == 0)                 s = cls;
    else if (pos < 1 + tl)        s = &text  [((size_t)(pos - 1) * B_ + b) * D_];
    else if (pos == 1 + tl)       s = sep;
    else if (pos < 2 + tl + sl)   s = &speech[((size_t)(pos - 2 - tl) * B_ + b) * D_];
    else                          s = nullptr;

    for (int d = threadIdx.x; d < D_; d += blockDim.x) {
        float v = s ? s[d] : 0.f;
        g_x[base + d] = v;
        __nv_bfloat16 h = __float2bfloat16(v);
        g_xh[base + d] = h;
        g_xl[base + d] = __float2bfloat16(v - __bfloat162float(h));
    }
}

// ---------------------------------------------------------------------------
// Weight transpose + hi/lo split: W[K,N] fp32 -> Th/Tl[N,K] bf16
// ---------------------------------------------------------------------------
__global__ void wsplit_kernel(const float* __restrict__ W,
                              __nv_bfloat16* __restrict__ Th,
                              __nv_bfloat16* __restrict__ Tl, int K, int N) {
    __shared__ float t[32][33];
    int n0 = blockIdx.x * 32, k0 = blockIdx.y * 32;
    int tx = threadIdx.x, ty = threadIdx.y;
    #pragma unroll
    for (int j = 0; j < 4; j++) {
        int k = k0 + ty + j * 8;
        t[ty + j * 8][tx] = W[(size_t)k * N + n0 + tx];
    }
    __syncthreads();
    #pragma unroll
    for (int j = 0; j < 4; j++) {
        int n = n0 + ty + j * 8;
        float v = t[tx][ty + j * 8];
        __nv_bfloat16 h = __float2bfloat16(v);
        Th[(size_t)n * K + k0 + tx] = h;
        Tl[(size_t)n * K + k0 + tx] = __float2bfloat16(v - __bfloat162float(h));
    }
}

// ---------------------------------------------------------------------------
// HMMA bf16 GEMM with 3-term hi/lo compensation + pad-tile skipping.
// C[M,N] = A[M,K] @ B^T[N,K] + bias (A/B pre-split into hi/lo bf16).
// 128x128x32 tile, 256 threads (8 warps, 2x4), 3-stage cp.async pipeline.
// Rows are b*L+pos; a CTA whose every row has pos >= Lv(b) is dead work
// (pad rows never influence valid rows anywhere downstream) -> early exit.
// MODE 0: write fp32 C. MODE 1: write bf16 hi/lo C (after optional RELU).
// ---------------------------------------------------------------------------
template <int RELU, int MODE>
__global__ __launch_bounds__(256, 1) void gemm_mma(
    const __nv_bfloat16* __restrict__ Ah, const __nv_bfloat16* __restrict__ Al,
    const __nv_bfloat16* __restrict__ Bh, const __nv_bfloat16* __restrict__ Bl,
    const float* __restrict__ bias,
    float* __restrict__ Cf,
    __nv_bfloat16* __restrict__ Ch, __nv_bfloat16* __restrict__ Cl,
    int Mn, int Nn, int Kn) {
    extern __shared__ char dynsmem[];
    uint32_t sbase = (s2u(dynsmem) + 1023u) & ~1023u;
    int tid = threadIdx.x;
    int wid = tid >> 5, lane = tid & 31;
    int m0 = blockIdx.y * 128, n0 = blockIdx.x * 128;

    // ---- pad-tile skip (uniform across CTA; no barriers before this) ----
    {
        int rend = m0 + 128;
        if (rend > Mn) rend = Mn;
        int bb0 = m0 / L_, bb1 = (rend - 1) / L_;
        bool anyv = false;
        for (int b = bb0; b <= bb1; b++) {
            int seg = m0 > b * L_ ? m0 - b * L_ : 0;
            if (seg < 2 + g_tlen[b] + g_slen[b]) anyv = true;
        }
        if (!anyv) return;
    }

    int wm = wid & 1, wn = wid >> 1;
    int m0w = wm * 64, n0w = wn * 32;
    const int T = Kn / BK_;

    int la = tid >> 6;        // 0..3 -> Ah, Al, Bh, Bl
    int t6 = tid & 63;

    auto issue = [&](int kt) {
        uint32_t stb = sbase + (kt % STAGES_) * STAGE_B + la * ASZ_;
        #pragma unroll
        for (int i = 0; i < 8; i++) {
            int chunk = t6 + 64 * i;          // 0..511
            int row = chunk >> 2;             // 0..127
            int col = chunk & 3;              // 16B chunk within 64B row
            uint32_t dst = stb + (uint32_t)(row * LDS_ + col * 8) * 2;
            if (la < 2) {
                int gr = m0 + row;
                bool v = gr < Mn;
                const __nv_bfloat16* src =
                    (la ? Al : Ah) + (size_t)(v ? gr : 0) * Kn + kt * BK_ + col * 8;
                cp16(dst, src, v ? 16 : 0);
            } else {
                const __nv_bfloat16* src =
                    (la == 2 ? Bh : Bl) + (size_t)(n0 + row) * Kn + kt * BK_ + col * 8;
                cp16(dst, src, 16);
            }
        }
        cp_commit();
    };

    issue(0);
    issue(1);

    float acc[4][4][4];
    #pragma unroll
    for (int i = 0; i < 4; i++)
        #pragma unroll
        for (int j = 0; j < 4; j++)
            #pragma unroll
            for (int p = 0; p < 4; p++) acc[i][j][p] = 0.f;

    int lr = lane & 15, lc8 = (lane >> 4) * 8;

    for (int kt = 0; kt < T; kt++) {
        cp_wait<STAGES_ - 2>();
        __syncthreads();
        uint32_t stb = sbase + (kt % STAGES_) * STAGE_B;
        #pragma unroll
        for (int kk = 0; kk < 2; kk++) {
            int koff = kk * 16 + lc8;
            uint32_t ah[4][4], al[4][4], bh[2][4], bl[2][4];
            #pragma unroll
            for (int im = 0; im < 4; im++) {
                uint32_t ad = stb + (uint32_t)((m0w + im * 16 + lr) * LDS_ + koff) * 2;
                ldsm4(ah[im], ad);
                ldsm4(al[im], ad + ASZ_);
            }
            #pragma unroll
            for (int ib = 0; ib < 2; ib++) {
                uint32_t bd = stb + 2 * ASZ_ +
                              (uint32_t)((n0w + ib * 16 + lr) * LDS_ + koff) * 2;
                ldsm4(bh[ib], bd);
                ldsm4(bl[ib], bd + ASZ_);
            }
            #pragma unroll
            for (int im = 0; im < 4; im++)
                #pragma unroll
                for (int in = 0; in < 4; in++) {
                    int ib = in >> 1, sb = in & 1;
                    mma16816(acc[im][in], ah[im], bh[ib][sb], bh[ib][sb + 2]);
                    mma16816(acc[im][in], ah[im], bl[ib][sb], bl[ib][sb + 2]);
                    mma16816(acc[im][in], al[im], bh[ib][sb], bh[ib][sb + 2]);
                }
        }
        int nt = kt + STAGES_ - 1;
        if (nt < T) issue(nt); else cp_commit();
    }

    // Epilogue
    int g = lane >> 2, tq = lane & 3;
    #pragma unroll
    for (int in = 0; in < 4; in++) {
        int cb = n0 + n0w + in * 8 + tq * 2;
        float b0 = __ldg(&bias[cb]), b1 = __ldg(&bias[cb + 1]);
        #pragma unroll
        for (int im = 0; im < 4; im++) {
            #pragma unroll
            for (int hrow = 0; hrow < 2; hrow++) {
                int m = m0 + m0w + im * 16 + g + hrow * 8;
                if (m < Mn) {
                    float v0 = acc[im][in][hrow * 2 + 0] + b0;
                    float v1 = acc[im][in][hrow * 2 + 1] + b1;
                    if (RELU) { v0 = fmaxf(v0, 0.f); v1 = fmaxf(v1, 0.f); }
                    if (MODE == 0) {
                        *(float2*)&Cf[(size_t)m * Nn + cb] = make_float2(v0, v1);
                    } else {
                        __nv_bfloat16 h0 = __float2bfloat16(v0);
                        __nv_bfloat16 h1 = __float2bfloat16(v1);
                        float l0 = v0 - __bfloat162float(h0);
                        float l1 = v1 - __bfloat162float(h1);
                        __nv_bfloat162 hh2 = __halves2bfloat162(h0, h1);
                        __nv_bfloat162 ll2 = __halves2bfloat162(
                            __float2bfloat16(l0), __float2bfloat16(l1));
                        *(uint32_t*)&Ch[(size_t)m * Nn + cb] = *(uint32_t*)&hh2;
                        *(uint32_t*)&Cl[(size_t)m * Nn + cb] = *(uint32_t*)&ll2;
                    }
                }
            }
        }
    }
}

// ---------------------------------------------------------------------------
// Fused flash attention (fp32), valid-length aware, writes bf16 hi/lo output.
// ---------------------------------------------------------------------------
__global__ __launch_bounds__(256) void attn_kernel() {
    extern __shared__ float sm[];
    float* Qs = sm;
    float* Ks = sm + 4096;
    float* Vs = sm + 8192;
    float* Pt = sm + 12288;
    float* km = sm + 12288 + 64 * 68;

    int tid = threadIdx.x;
    int tx = tid & 15, ty = tid >> 4;
    int qt = blockIdx.x, h = blockIdx.y, b = blockIdx.z;
    int q0 = qt * 64;
    int ldr = tid >> 2;
    int cb  = (tid & 3) * 16;

    int Lv = 2 + g_tlen[b] + g_slen[b];
    if (q0 >= Lv) return;   // pad q-tile: outputs are dead downstream

    {
        int qrow = q0 + ldr;
        bool valid = qrow < L_;
        const float* src = &g_q[((size_t)(b * L_) + (valid ? qrow : 0)) * D_ + h * HD_];
        #pragma unroll
        for (int u = 0; u < 16; u += 4) {
            float4 vv = valid ? *(const float4*)&src[cb + u]
                              : make_float4(0.f, 0.f, 0.f, 0.f);
            Qs[(cb + u + 0) * 64 + ldr] = vv.x * 0.125f;
            Qs[(cb + u + 1) * 64 + ldr] = vv.y * 0.125f;
            Qs[(cb + u + 2) * 64 + ldr] = vv.z * 0.125f;
            Qs[(cb + u + 3) * 64 + ldr] = vv.w * 0.125f;
        }
    }

    float o[4][4] = {};
    float mr[4]   = {-1e30f, -1e30f, -1e30f, -1e30f};
    float lsum[4] = {0.f, 0.f, 0.f, 0.f};

    const int NKT = (Lv + 63) >> 6;
    for (int kt = 0; kt < NKT; kt++) {
        int k0 = kt * 64;
        __syncthreads();

        {
            int krow = k0 + ldr;
            bool valid = krow < L_;
            const float* ksrc = &g_k[((size_t)(b * L_) + (valid ? krow : 0)) * D_ + h * HD_];
            const float* vsrc = &g_v[((size_t)(b * L_) + (valid ? krow : 0)) * D_ + h * HD_];
            #pragma unroll
            for (int u = 0; u < 16; u += 4) {
                float4 vv = valid ? *(const float4*)&ksrc[cb + u]
                                  : make_float4(0.f, 0.f, 0.f, 0.f);
                Ks[(cb + u + 0) * 64 + ldr] = vv.x;
                Ks[(cb + u + 1) * 64 + ldr] = vv.y;
                Ks[(cb + u + 2) * 64 + ldr] = vv.z;
                Ks[(cb + u + 3) * 64 + ldr] = vv.w;
            }
            #pragma unroll
            for (int u = 0; u < 16; u += 4) {
                float4 vv = valid ? *(const float4*)&vsrc[cb + u]
                                  : make_float4(0.f, 0.f, 0.f, 0.f);
                *(float4*)&Vs[ldr * 64 + cb + u] = vv;
            }
        }
        if (tid < 64) {
            int kp = k0 + tid;
            km[tid] = (kp < L_ && g_pad[b * L_ + kp] == 0) ? 0.f : 1.f;
        }
        __syncthreads();

        float s[4][4] = {};
        #pragma unroll 8
        for (int d = 0; d < 64; d++) {
            float4 a  = *(float4*)&Qs[d * 64 + ty * 4];
            float4 bb = *(float4*)&Ks[d * 64 + tx * 4];
            float ar[4] = {a.x, a.y, a.z, a.w};
            float br[4] = {bb.x, bb.y, bb.z, bb.w};
            #pragma unroll
            for (int i = 0; i < 4; i++)
                #pragma unroll
                for (int j = 0; j < 4; j++)
                    s[i][j] += ar[i] * br[j];
        }

        float kmr[4];
        #pragma unroll
        for (int j = 0; j < 4; j++) kmr[j] = km[tx * 4 + j];
        #pragma unroll
        for (int i = 0; i < 4; i++)
            #pragma unroll
            for (int j = 0; j < 4; j++)
                if (kmr[j] != 0.f) s[i][j] = -1e9f;

        #pragma unroll
        for (int i = 0; i < 4; i++) {
            float tmax = fmaxf(fmaxf(s[i][0], s[i][1]), fmaxf(s[i][2], s[i][3]));
            #pragma unroll
            for (int off = 8; off >= 1; off >>= 1)
                tmax = fmaxf(tmax, __shfl_xor_sync(0xffffffffu, tmax, off));
            float mnew  = fmaxf(mr[i], tmax);
            float alpha = expf(mr[i] - mnew);
            float rsum = 0.f;
            #pragma unroll
            for (int j = 0; j < 4; j++) {
                float p = expf(s[i][j] - mnew);
                s[i][j] = p;
                rsum += p;
            }
            #pragma unroll
            for (int off = 8; off >= 1; off >>= 1)
                rsum += __shfl_xor_sync(0xffffffffu, rsum, off);
            lsum[i] = lsum[i] * alpha + rsum;
            mr[i] = mnew;
            #pragma unroll
            for (int j = 0; j < 4; j++) o[i][j] *= alpha;
        }

        #pragma unroll
        for (int j = 0; j < 4; j++)
            #pragma unroll
            for (int i = 0; i < 4; i++)
                Pt[(tx * 4 + j) * 68 + ty * 4 + i] = s[i][j];
        __syncthreads();

        #pragma unroll 8
        for (int kk = 0; kk < 64; kk++) {
            float4 a  = *(float4*)&Pt[kk * 68 + ty * 4];
            float4 bb = *(float4*)&Vs[kk * 64 + tx * 4];
            float ar[4] = {a.x, a.y, a.z, a.w};
            float br[4] = {bb.x, bb.y, bb.z, bb.w};
            #pragma unroll
            for (int i = 0; i < 4; i++)
                #pragma unroll
                for (int j = 0; j < 4; j++)
                    o[i][j] += ar[i] * br[j];
        }
    }

    #pragma unroll
    for (int i = 0; i < 4; i++) {
        int qrow = q0 + ty * 4 + i;
        if (qrow < L_) {
            float inv = 1.f / lsum[i];
            size_t base = ((size_t)(b * L_) + qrow) * D_ + h * HD_ + tx * 4;
            #pragma unroll
            for (int j = 0; j < 4; j++) {
                float t = o[i][j] * inv;
                __nv_bfloat16 hh = __float2bfloat16(t);
                g_ath[base + j] = hh;
                g_atl[base + j] = __float2bfloat16(t - __bfloat162float(hh));
            }
        }
    }
}

// ---------------------------------------------------------------------------
// x = LayerNorm(x + y) * s + b (in place) + bf16 hi/lo emission.
// Pad rows are dead downstream -> early exit.
// ---------------------------------------------------------------------------
__global__ __launch_bounds__(256) void add_ln_kernel(const float* __restrict__ sc,
                                                     const float* __restrict__ bi) {
    int row = blockIdx.x;
    {
        int b = row / L_, pos = row - b * L_;
        if (pos >= 2 + g_tlen[b] + g_slen[b]) return;
    }
    size_t base = (size_t)row * D_;
    __shared__ float red[256];
    int tid = threadIdx.x;

    float v[4];
    float s = 0.f;
    #pragma unroll
    for (int u = 0; u < 4; u++) {
        int d = tid + u * 256;
        v[u] = g_x[base + d] + g_y[base + d];
        s += v[u];
    }
    red[tid] = s;
    __syncthreads();
    for (int off = 128; off > 0; off >>= 1) {
        if (tid < off) red[tid] += red[tid + off];
        __syncthreads();
    }
    float mean = red[0] * (1.f / D_);
    __syncthreads();

    float s2 = 0.f;
    #pragma unroll
    for (int u = 0; u < 4; u++) { float dd = v[u] - mean; s2 += dd * dd; }
    red[tid] = s2;
    __syncthreads();
    for (int off = 128; off > 0; off >>= 1) {
        if (tid < off) red[tid] += red[tid + off];
        __syncthreads();
    }
    float var = red[0] * (1.f / D_);
    float inv = rsqrtf(var + 1e-5f);

    #pragma unroll
    for (int u = 0; u < 4; u++) {
        int d = tid + u * 256;
        float t = (v[u] - mean) * inv * sc[d] + bi[d];
        g_x[base + d] = t;
        __nv_bfloat16 hh = __float2bfloat16(t);
        g_xh[base + d] = hh;
        g_xl[base + d] = __float2bfloat16(t - __bfloat162float(hh));
    }
}

// ---------------------------------------------------------------------------
// out[b] = dot(x[b, 0, :], out_w)
// ---------------------------------------------------------------------------
__global__ __launch_bounds__(256) void final_kernel(const float* __restrict__ ow,
                                                    float* __restrict__ out) {
    int b = blockIdx.x;
    __shared__ float red[256];
    const float* xr = &g_x[(size_t)(b * L_) * D_];
    int tid = threadIdx.x;
    float s = 0.f;
    for (int d = tid; d < D_; d += 256) s += xr[d] * ow[d];
    red[tid] = s;
    __syncthreads();
    for (int off = 128; off > 0; off >>= 1) {
        if (tid < off) red[tid] += red[tid + off];
        __syncthreads();
    }
    if (tid == 0) out[b] = red[0];
}

// ---------------------------------------------------------------------------
// Launch
// ---------------------------------------------------------------------------
extern "C" void kernel_launch(void* const* d_in, const int* in_sizes, int n_in,
                              void* d_out, int out_size) {
    const float* text   = (const float*)d_in[0];
    const float* speech = (const float*)d_in[1];
    const void*  tmask  = d_in[2];
    const void*  smask  = d_in[3];
    const float* cls    = (const float*)d_in[4];
    const float* sep    = (const float*)d_in[5];
    const float* Wq     = (const float*)d_in[6];
    const float* bq     = (const float*)d_in[7];
    const float* Wk     = (const float*)d_in[8];
    const float* bk     = (const float*)d_in[9];
    const float* Wv     = (const float*)d_in[10];
    const float* bv     = (const float*)d_in[11];
    const float* Wo     = (const float*)d_in[12];
    const float* bo     = (const float*)d_in[13];
    const float* ln1s   = (const float*)d_in[14];
    const float* ln1b   = (const float*)d_in[15];
    const float* f1w    = (const float*)d_in[16];
    const float* f1b    = (const float*)d_in[17];
    const float* f2w    = (const float*)d_in[18];
    const float* f2b    = (const float*)d_in[19];
    const float* ln2s   = (const float*)d_in[20];
    const float* ln2b   = (const float*)d_in[21];
    const float* outw   = (const float*)d_in[22];
    float* out = (float*)d_out;

    float *q, *k, *v, *y;
    __nv_bfloat16 *xh, *xl, *ath, *atl, *hh, *hl;
    __nv_bfloat16 *Wqh, *Wql, *Wkh, *Wkl, *Wvh, *Wvl, *Woh, *Wol, *F1h, *F1l, *F2h, *F2l;
    cudaGetSymbolAddress((void**)&q,   g_q);
    cudaGetSymbolAddress((void**)&k,   g_k);
    cudaGetSymbolAddress((void**)&v,   g_v);
    cudaGetSymbolAddress((void**)&y,   g_y);
    cudaGetSymbolAddress((void**)&xh,  g_xh);
    cudaGetSymbolAddress((void**)&xl,  g_xl);
    cudaGetSymbolAddress((void**)&ath, g_ath);
    cudaGetSymbolAddress((void**)&atl, g_atl);
    cudaGetSymbolAddress((void**)&hh,  g_hh);
    cudaGetSymbolAddress((void**)&hl,  g_hl);
    cudaGetSymbolAddress((void**)&Wqh, g_Wqh);
    cudaGetSymbolAddress((void**)&Wql, g_Wql);
    cudaGetSymbolAddress((void**)&Wkh, g_Wkh);
    cudaGetSymbolAddress((void**)&Wkl, g_Wkl);
    cudaGetSymbolAddress((void**)&Wvh, g_Wvh);
    cudaGetSymbolAddress((void**)&Wvl, g_Wvl);
    cudaGetSymbolAddress((void**)&Woh, g_Woh);
    cudaGetSymbolAddress((void**)&Wol, g_Wol);
    cudaGetSymbolAddress((void**)&F1h, g_F1h);
    cudaGetSymbolAddress((void**)&F1l, g_F1l);
    cudaGetSymbolAddress((void**)&F2h, g_F2h);
    cudaGetSymbolAddress((void**)&F2l, g_F2l);

    cudaFuncSetAttribute(attn_kernel,
                         cudaFuncAttributeMaxDynamicSharedMemorySize, SMEM_ATT);
    cudaFuncSetAttribute(gemm_mma<0, 0>,
                         cudaFuncAttributeMaxDynamicSharedMemorySize, GEMM_SMEM);
    cudaFuncSetAttribute(gemm_mma<1, 1>,
                         cudaFuncAttributeMaxDynamicSharedMemorySize, GEMM_SMEM);

    lengths_kernel<<<2, 256>>>(tmask, smask);
    build_x_kernel<<<dim3(L_, B_), 256>>>(text, speech, cls, sep);

    dim3 tb(32, 8);
    for (int l = 0; l < NL_; l++) {
        size_t od = (size_t)l * D_ * D_;
        size_t o1 = (size_t)l * D_ * F_;
        size_t o2 = (size_t)l * F_ * D_;
        wsplit_kernel<<<dim3(D_ / 32, D_ / 32), tb>>>(Wq + od, Wqh + od, Wql + od, D_, D_);
        wsplit_kernel<<<dim3(D_ / 32, D_ / 32), tb>>>(Wk + od, Wkh + od, Wkl + od, D_, D_);
        wsplit_kernel<<<dim3(D_ / 32, D_ / 32), tb>>>(Wv + od, Wvh + od, Wvl + od, D_, D_);
        wsplit_kernel<<<dim3(D_ / 32, D_ / 32), tb>>>(Wo + od, Woh + od, Wol + od, D_, D_);
        wsplit_kernel<<<dim3(F_ / 32, D_ / 32), tb>>>(f1w + o1, F1h + o1, F1l + o1, D_, F_);
        wsplit_kernel<<<dim3(D_ / 32, F_ / 32), tb>>>(f2w + o2, F2h + o2, F2l + o2, F_, D_);
    }

    int mt = (M_ + 127) / 128;  // 81
    dim3 gD(D_ / 128, mt);
    dim3 gF(F_ / 128, mt);
    dim3 gAtt((L_ + 63) / 64, H_, B_);

    for (int l = 0; l < NL_; l++) {
        size_t od = (size_t)l * D_ * D_;
        size_t o1 = (size_t)l * D_ * F_;
        size_t o2 = (size_t)l * F_ * D_;
        gemm_mma<0, 0><<<gD, 256, GEMM_SMEM>>>(xh, xl, Wqh + od, Wql + od, bq + l * D_,
                                               q, nullptr, nullptr, M_, D_, D_);
        gemm_mma<0, 0><<<gD, 256, GEMM_SMEM>>>(xh, xl, Wkh + od, Wkl + od, bk + l * D_,
                                               k, nullptr, nullptr, M_, D_, D_);
        gemm_mma<0, 0><<<gD, 256, GEMM_SMEM>>>(xh, xl, Wvh + od, Wvl + od, bv + l * D_,
                                               v, nullptr, nullptr, M_, D_, D_);
        attn_kernel<<<gAtt, 256, SMEM_ATT>>>();
        gemm_mma<0, 0><<<gD, 256, GEMM_SMEM>>>(ath, atl, Woh + od, Wol + od, bo + l * D_,
                                               y, nullptr, nullptr, M_, D_, D_);
        add_ln_kernel<<<M_, 256>>>(ln1s + l * D_, ln1b + l * D_);
        gemm_mma<1, 1><<<gF, 256, GEMM_SMEM>>>(xh, xl, F1h + o1, F1l + o1, f1b + l * F_,
                                               nullptr, hh, hl, M_, F_, D_);
        gemm_mma<0, 0><<<gD, 256, GEMM_SMEM>>>(hh, hl, F2h + o2, F2l + o2, f2b + l * D_,
                                               y, nullptr, nullptr, M_, D_, F_);
        add_ln_kernel<<<M_, 256>>>(ln2s + l * D_, ln2b + l * D_);
    }
    final_kernel<<<B_, 256>>>(outw, out);
}

// round 10
// speedup vs baseline: 2.8552x; 1.0972x over previous
#include <cuda_runtime.h>
#include <cuda_bf16.h>
#include <math.h>
#include <stdint.h>

// ---------------------------------------------------------------------------
// Problem constants
// ---------------------------------------------------------------------------
namespace {
constexpr int B_  = 16;
constexpr int TT_ = 128;
constexpr int TS_ = 512;
constexpr int L_  = TT_ + TS_ + 2;   // 642
constexpr int LT_ = 648;             // vt row stride: multiple of 8 elems (16B)
constexpr int D_  = 1024;
constexpr int H_  = 16;
constexpr int HD_ = 64;
constexpr int F_  = 4096;
constexpr int NL_ = 4;
constexpr int M_  = B_ * L_;         // 10272

// GEMM tiling
constexpr int BK_     = 32;
constexpr int STAGES_ = 3;
constexpr int LDS_    = 40;                    // padded row stride (elements)
constexpr int ASZ_    = 128 * LDS_ * 2;        // 10240 bytes per tile array
constexpr int STAGE_B = 4 * ASZ_;              // 40960 bytes per stage
constexpr int GEMM_SMEM = STAGES_ * STAGE_B + 1024;  // 123904

// Attention tiling
constexpr int ATS      = 72;                   // smem row stride (elements)
constexpr int AT_TILE  = 64 * ATS * 2;         // 9216 bytes per 64x64 bf16 array
constexpr int ATT_ST0  = 2 * AT_TILE;          // Qh, Ql
constexpr int ATT_STG  = 4 * AT_TILE;          // Kh, Kl, Vth, Vtl per stage
constexpr int ATT_SMEM = ATT_ST0 + 2 * ATT_STG; // 92160
}

// ---------------------------------------------------------------------------
// Scratch (allocation-free: __device__ globals; zero-initialized)
// ---------------------------------------------------------------------------
__device__ float g_x[(size_t)M_ * D_];
__device__ float g_y[(size_t)M_ * D_];
__device__ __nv_bfloat16 g_xh [(size_t)M_ * D_];
__device__ __nv_bfloat16 g_xl [(size_t)M_ * D_];
__device__ __nv_bfloat16 g_qh [(size_t)M_ * D_];
__device__ __nv_bfloat16 g_ql [(size_t)M_ * D_];
__device__ __nv_bfloat16 g_kh [(size_t)M_ * D_];
__device__ __nv_bfloat16 g_kl [(size_t)M_ * D_];
__device__ __nv_bfloat16 g_vth[(size_t)B_ * D_ * LT_ + 64];
__device__ __nv_bfloat16 g_vtl[(size_t)B_ * D_ * LT_ + 64];
__device__ __nv_bfloat16 g_ath[(size_t)M_ * D_];
__device__ __nv_bfloat16 g_atl[(size_t)M_ * D_];
__device__ __nv_bfloat16 g_hh [(size_t)M_ * F_];
__device__ __nv_bfloat16 g_hl [(size_t)M_ * F_];
// transposed + hi/lo-split weights: [N,K] layout
__device__ __nv_bfloat16 g_Wqh[(size_t)NL_ * D_ * D_];
__device__ __nv_bfloat16 g_Wql[(size_t)NL_ * D_ * D_];
__device__ __nv_bfloat16 g_Wkh[(size_t)NL_ * D_ * D_];
__device__ __nv_bfloat16 g_Wkl[(size_t)NL_ * D_ * D_];
__device__ __nv_bfloat16 g_Wvh[(size_t)NL_ * D_ * D_];
__device__ __nv_bfloat16 g_Wvl[(size_t)NL_ * D_ * D_];
__device__ __nv_bfloat16 g_Woh[(size_t)NL_ * D_ * D_];
__device__ __nv_bfloat16 g_Wol[(size_t)NL_ * D_ * D_];
__device__ __nv_bfloat16 g_F1h[(size_t)NL_ * D_ * F_];
__device__ __nv_bfloat16 g_F1l[(size_t)NL_ * D_ * F_];
__device__ __nv_bfloat16 g_F2h[(size_t)NL_ * F_ * D_];
__device__ __nv_bfloat16 g_F2l[(size_t)NL_ * F_ * D_];
__device__ int g_tlen[B_];
__device__ int g_slen[B_];

// ---------------------------------------------------------------------------
// PTX helpers (sm_80-era subset only: cp.async, ldmatrix, mma.sync)
// ---------------------------------------------------------------------------
__device__ __forceinline__ uint32_t s2u(const void* p) {
    uint32_t a;
    asm("{ .reg .u64 t; cvta.to.shared.u64 t, %1; cvt.u32.u64 %0, t; }"
        : "=r"(a) : "l"(p));
    return a;
}
__device__ __forceinline__ void cp16(uint32_t s, const void* g, int nbytes) {
    asm volatile("cp.async.cg.shared.global [%0], [%1], 16, %2;"
                 :: "r"(s), "l"(g), "r"(nbytes));
}
__device__ __forceinline__ void cp_commit() {
    asm volatile("cp.async.commit_group;");
}
template <int N> __device__ __forceinline__ void cp_wait() {
    asm volatile("cp.async.wait_group %0;" :: "n"(N));
}
__device__ __forceinline__ void ldsm4(uint32_t* r, uint32_t addr) {
    asm volatile("ldmatrix.sync.aligned.m8n8.x4.shared.b16 {%0,%1,%2,%3}, [%4];"
                 : "=r"(r[0]), "=r"(r[1]), "=r"(r[2]), "=r"(r[3]) : "r"(addr));
}
__device__ __forceinline__ void mma16816(float* c, const uint32_t* a,
                                         uint32_t b0, uint32_t b1) {
    asm volatile(
        "mma.sync.aligned.m16n8k16.row.col.f32.bf16.bf16.f32 "
        "{%0,%1,%2,%3}, {%4,%5,%6,%7}, {%8,%9}, {%0,%1,%2,%3};\n"
        : "+f"(c[0]), "+f"(c[1]), "+f"(c[2]), "+f"(c[3])
        : "r"(a[0]), "r"(a[1]), "r"(a[2]), "r"(a[3]), "r"(b0), "r"(b1));
}
// split two fp32 into packed bf16x2 hi and lo words
__device__ __forceinline__ void packsplit(float x, float y,
                                          uint32_t& hi, uint32_t& lo) {
    __nv_bfloat16 hx = __float2bfloat16(x), hy = __float2bfloat16(y);
    __nv_bfloat162 hh = __halves2bfloat162(hx, hy);
    __nv_bfloat162 ll = __halves2bfloat162(
        __float2bfloat16(x - __bfloat162float(hx)),
        __float2bfloat16(y - __bfloat162float(hy)));
    hi = *(uint32_t*)&hh;
    lo = *(uint32_t*)&ll;
}

// ---------------------------------------------------------------------------
// Mask length computation with on-device dtype detection
// ---------------------------------------------------------------------------
__global__ void lengths_kernel(const void* tmask, const void* smask) {
    int which = blockIdx.x;
    const void* mask = which ? smask : tmask;
    int T = which ? TS_ : TT_;
    int* lens = which ? g_slen : g_tlen;
    int N = B_ * T;

    __shared__ int f3F, fMis;
    __shared__ int cnt[B_];
    int tid = threadIdx.x;
    if (tid == 0) { f3F = 0; fMis = 0; }
    if (tid < B_) cnt[tid] = 0;
    __syncthreads();

    const unsigned char* bytes = (const unsigned char*)mask;
    int l3 = 0, lm = 0;
    for (int i = tid; i < N; i += blockDim.x) {
        unsigned char c = bytes[i];
        if (c == 0x3F) l3 = 1;
        if (c == 1 && (i & 3)) lm = 1;
    }
    if (l3) atomicOr(&f3F, 1);
    if (lm) atomicOr(&fMis, 1);
    __syncthreads();

    if (fMis && !f3F) {
        for (int i = tid; i < N; i += blockDim.x)
            if (bytes[i] == 0) atomicAdd(&cnt[i / T], 1);
    } else {
        const unsigned int* w = (const unsigned int*)mask;
        for (int i = tid; i < N; i += blockDim.x)
            if (w[i] == 0u) atomicAdd(&cnt[i / T], 1);
    }
    __syncthreads();
    if (tid < B_) lens[tid] = cnt[tid];
}

// ---------------------------------------------------------------------------
// Build concatenated sequence x (fp32 + bf16 hi/lo)
// ---------------------------------------------------------------------------
__global__ void build_x_kernel(const float* __restrict__ text,
                               const float* __restrict__ speech,
                               const float* __restrict__ cls,
                               const float* __restrict__ sep) {
    int pos = blockIdx.x, b = blockIdx.y;
    int tl = g_tlen[b], sl = g_slen[b];
    size_t base = ((size_t)(b * L_) + pos) * D_;

    const float* s;
    if (pos == 0)                 s = cls;
    else if (pos < 1 + tl)        s = &text  [((size_t)(pos - 1) * B_ + b) * D_];
    else if (pos == 1 + tl)       s = sep;
    else if (pos < 2 + tl + sl)   s = &speech[((size_t)(pos - 2 - tl) * B_ + b) * D_];
    else                          s = nullptr;

    for (int d = threadIdx.x; d < D_; d += blockDim.x) {
        float v = s ? s[d] : 0.f;
        g_x[base + d] = v;
        __nv_bfloat16 h = __float2bfloat16(v);
        g_xh[base + d] = h;
        g_xl[base + d] = __float2bfloat16(v - __bfloat162float(h));
    }
}

// ---------------------------------------------------------------------------
// Weight transpose + hi/lo split: W[K,N] fp32 -> Th/Tl[N,K] bf16
// ---------------------------------------------------------------------------
__global__ void wsplit_kernel(const float* __restrict__ W,
                              __nv_bfloat16* __restrict__ Th,
                              __nv_bfloat16* __restrict__ Tl, int K, int N) {
    __shared__ float t[32][33];
    int n0 = blockIdx.x * 32, k0 = blockIdx.y * 32;
    int tx = threadIdx.x, ty = threadIdx.y;
    #pragma unroll
    for (int j = 0; j < 4; j++) {
        int k = k0 + ty + j * 8;
        t[ty + j * 8][tx] = W[(size_t)k * N + n0 + tx];
    }
    __syncthreads();
    #pragma unroll
    for (int j = 0; j < 4; j++) {
        int n = n0 + ty + j * 8;
        float v = t[tx][ty + j * 8];
        __nv_bfloat16 h = __float2bfloat16(v);
        Th[(size_t)n * K + k0 + tx] = h;
        Tl[(size_t)n * K + k0 + tx] = __float2bfloat16(v - __bfloat162float(h));
    }
}

// ---------------------------------------------------------------------------
// HMMA bf16 GEMM with 3-term hi/lo compensation + pad-tile skipping.
// MODE 0: fp32 C.  MODE 1: bf16 hi/lo C (after optional RELU).
// MODE 2: bf16 hi/lo C written TRANSPOSED per batch: vt[(b*D + n)*LT + pos].
// ---------------------------------------------------------------------------
template <int RELU, int MODE>
__global__ __launch_bounds__(256, 1) void gemm_mma(
    const __nv_bfloat16* __restrict__ Ah, const __nv_bfloat16* __restrict__ Al,
    const __nv_bfloat16* __restrict__ Bh, const __nv_bfloat16* __restrict__ Bl,
    const float* __restrict__ bias,
    float* __restrict__ Cf,
    __nv_bfloat16* __restrict__ Ch, __nv_bfloat16* __restrict__ Cl,
    int Mn, int Nn, int Kn) {
    extern __shared__ char dynsmem[];
    uint32_t sbase = (s2u(dynsmem) + 1023u) & ~1023u;
    int tid = threadIdx.x;
    int wid = tid >> 5, lane = tid & 31;
    int m0 = blockIdx.y * 128, n0 = blockIdx.x * 128;

    // ---- pad-tile skip ----
    {
        int rend = m0 + 128;
        if (rend > Mn) rend = Mn;
        int bb0 = m0 / L_, bb1 = (rend - 1) / L_;
        bool anyv = false;
        for (int b = bb0; b <= bb1; b++) {
            int seg = m0 > b * L_ ? m0 - b * L_ : 0;
            if (seg < 2 + g_tlen[b] + g_slen[b]) anyv = true;
        }
        if (!anyv) return;
    }

    int wm = wid & 1, wn = wid >> 1;
    int m0w = wm * 64, n0w = wn * 32;
    const int T = Kn / BK_;

    int la = tid >> 6;
    int t6 = tid & 63;

    auto issue = [&](int kt) {
        uint32_t stb = sbase + (kt % STAGES_) * STAGE_B + la * ASZ_;
        #pragma unroll
        for (int i = 0; i < 8; i++) {
            int chunk = t6 + 64 * i;
            int row = chunk >> 2;
            int col = chunk & 3;
            uint32_t dst = stb + (uint32_t)(row * LDS_ + col * 8) * 2;
            if (la < 2) {
                int gr = m0 + row;
                bool v = gr < Mn;
                const __nv_bfloat16* src =
                    (la ? Al : Ah) + (size_t)(v ? gr : 0) * Kn + kt * BK_ + col * 8;
                cp16(dst, src, v ? 16 : 0);
            } else {
                const __nv_bfloat16* src =
                    (la == 2 ? Bh : Bl) + (size_t)(n0 + row) * Kn + kt * BK_ + col * 8;
                cp16(dst, src, 16);
            }
        }
        cp_commit();
    };

    issue(0);
    issue(1);

    float acc[4][4][4];
    #pragma unroll
    for (int i = 0; i < 4; i++)
        #pragma unroll
        for (int j = 0; j < 4; j++)
            #pragma unroll
            for (int p = 0; p < 4; p++) acc[i][j][p] = 0.f;

    int lr = lane & 15, lc8 = (lane >> 4) * 8;

    for (int kt = 0; kt < T; kt++) {
        cp_wait<STAGES_ - 2>();
        __syncthreads();
        uint32_t stb = sbase + (kt % STAGES_) * STAGE_B;
        #pragma unroll
        for (int kk = 0; kk < 2; kk++) {
            int koff = kk * 16 + lc8;
            uint32_t ah[4][4], al[4][4], bh[2][4], bl[2][4];
            #pragma unroll
            for (int im = 0; im < 4; im++) {
                uint32_t ad = stb + (uint32_t)((m0w + im * 16 + lr) * LDS_ + koff) * 2;
                ldsm4(ah[im], ad);
                ldsm4(al[im], ad + ASZ_);
            }
            #pragma unroll
            for (int ib = 0; ib < 2; ib++) {
                uint32_t bd = stb + 2 * ASZ_ +
                              (uint32_t)((n0w + ib * 16 + lr) * LDS_ + koff) * 2;
                ldsm4(bh[ib], bd);
                ldsm4(bl[ib], bd + ASZ_);
            }
            #pragma unroll
            for (int im = 0; im < 4; im++)
                #pragma unroll
                for (int in = 0; in < 4; in++) {
                    int ib = in >> 1, sb = in & 1;
                    mma16816(acc[im][in], ah[im], bh[ib][sb], bh[ib][sb + 2]);
                    mma16816(acc[im][in], ah[im], bl[ib][sb], bl[ib][sb + 2]);
                    mma16816(acc[im][in], al[im], bh[ib][sb], bh[ib][sb + 2]);
                }
        }
        int nt = kt + STAGES_ - 1;
        if (nt < T) issue(nt); else cp_commit();
    }

    // Epilogue
    int g = lane >> 2, tq = lane & 3;
    #pragma unroll
    for (int in = 0; in < 4; in++) {
        int cb = n0 + n0w + in * 8 + tq * 2;
        float b0 = __ldg(&bias[cb]), b1 = __ldg(&bias[cb + 1]);
        #pragma unroll
        for (int im = 0; im < 4; im++) {
            #pragma unroll
            for (int hrow = 0; hrow < 2; hrow++) {
                int m = m0 + m0w + im * 16 + g + hrow * 8;
                if (m < Mn) {
                    float v0 = acc[im][in][hrow * 2 + 0] + b0;
                    float v1 = acc[im][in][hrow * 2 + 1] + b1;
                    if (RELU) { v0 = fmaxf(v0, 0.f); v1 = fmaxf(v1, 0.f); }
                    if (MODE == 0) {
                        *(float2*)&Cf[(size_t)m * Nn + cb] = make_float2(v0, v1);
                    } else if (MODE == 1) {
                        uint32_t hw, lw;
                        packsplit(v0, v1, hw, lw);
                        *(uint32_t*)&Ch[(size_t)m * Nn + cb] = hw;
                        *(uint32_t*)&Cl[(size_t)m * Nn + cb] = lw;
                    } else {
                        // transposed per-batch: vt[(b*D + n)*LT + pos]
                        int bb = m / L_, pos = m - bb * L_;
                        size_t vt0 = ((size_t)bb * D_ + cb) * LT_ + pos;
                        __nv_bfloat16 h0 = __float2bfloat16(v0);
                        __nv_bfloat16 h1 = __float2bfloat16(v1);
                        Ch[vt0]       = h0;
                        Ch[vt0 + LT_] = h1;
                        Cl[vt0]       = __float2bfloat16(v0 - __bfloat162float(h0));
                        Cl[vt0 + LT_] = __float2bfloat16(v1 - __bfloat162float(h1));
                    }
                }
            }
        }
    }
}

// ---------------------------------------------------------------------------
// HMMA flash attention with 3-term hi/lo compensation.
// Block: (q-tile 64, head, batch), 128 threads (4 warps x m16 rows).
// Q/K from g_qh/l, g_kh/l ([pos][d] bf16); V from g_vth/l ([d][pos], LT stride).
// Writes softmax(QK^T/8 masked) V to g_ath/l as bf16 hi/lo.
// ---------------------------------------------------------------------------
__global__ __launch_bounds__(128, 1) void attn_mma_kernel() {
    extern __shared__ char asmem[];
    uint32_t sb = s2u(asmem);
    int tid = threadIdx.x, lane = tid & 31, w = tid >> 5;
    int qt = blockIdx.x, h = blockIdx.y, b = blockIdx.z;
    int q0 = qt * 64;
    int Lv = 2 + g_tlen[b] + g_slen[b];
    if (q0 >= Lv) return;
    const int NKT = (Lv + 63) >> 6;

    int lr = lane & 15, lc8 = (lane >> 4) * 8;
    int r = lane >> 2, tq = lane & 3;
    int lrow = tid >> 1, lhf = tid & 1;   // smem-fill: row, col-half

    // ---- stage Q (hi/lo) ----
    {
        int qrow = q0 + lrow; if (qrow > L_ - 1) qrow = L_ - 1;
        size_t off = ((size_t)(b * L_) + qrow) * D_ + h * HD_ + lhf * 32;
        uint32_t dst = sb + (uint32_t)(lrow * ATS + lhf * 32) * 2;
        #pragma unroll
        for (int u = 0; u < 4; u++) {
            cp16(dst + u * 16,           g_qh + off + u * 8, 16);
            cp16(dst + AT_TILE + u * 16, g_ql + off + u * 8, 16);
        }
        cp_commit();
    }

    auto loadKV = [&](int kt) {
        uint32_t base = sb + ATT_ST0 + (kt & 1) * ATT_STG;
        int k0 = kt * 64;
        int krow = k0 + lrow; if (krow > L_ - 1) krow = L_ - 1;
        size_t koff = ((size_t)(b * L_) + krow) * D_ + h * HD_ + lhf * 32;
        uint32_t kdst = base + (uint32_t)(lrow * ATS + lhf * 32) * 2;
        #pragma unroll
        for (int u = 0; u < 4; u++) {
            cp16(kdst + u * 16,           g_kh + koff + u * 8, 16);
            cp16(kdst + AT_TILE + u * 16, g_kl + koff + u * 8, 16);
        }
        // V: row stride LT_ (16B-aligned); pad cols [L_, LT_) are zeros.
        size_t voff = ((size_t)b * D_ + h * HD_ + lrow) * LT_ + k0 + lhf * 32;
        uint32_t vdst = base + 2 * AT_TILE + (uint32_t)(lrow * ATS + lhf * 32) * 2;
        #pragma unroll
        for (int u = 0; u < 4; u++) {
            int col = k0 + lhf * 32 + u * 8;
            int nb = (col < LT_) ? 16 : 0;   // zfill past padded length
            cp16(vdst + u * 16,           g_vth + voff + u * 8, nb);
            cp16(vdst + AT_TILE + u * 16, g_vtl + voff + u * 8, nb);
        }
        cp_commit();
    };

    loadKV(0);
    cp_wait<1>();           // Q staged (KV0 may still be in flight)
    __syncthreads();

    // Q fragments (held in registers for the whole kernel)
    uint32_t qfh[4][4], qfl[4][4];
    #pragma unroll
    for (int c = 0; c < 4; c++) {
        uint32_t ad = sb + (uint32_t)((w * 16 + lr) * ATS + c * 16 + lc8) * 2;
        ldsm4(qfh[c], ad);
        ldsm4(qfl[c], ad + AT_TILE);
    }

    float o[8][4];
    #pragma unroll
    for (int j = 0; j < 8; j++)
        #pragma unroll
        for (int p = 0; p < 4; p++) o[j][p] = 0.f;
    float mrA = -1e30f, mrB = -1e30f, lsA = 0.f, lsB = 0.f;

    for (int kt = 0; kt < NKT; kt++) {
        if (kt + 1 < NKT) { loadKV(kt + 1); cp_wait<1>(); }
        else              { cp_wait<0>(); }
        __syncthreads();
        uint32_t base = sb + ATT_ST0 + (kt & 1) * ATT_STG;
        int k0 = kt * 64;

        // ---- S = Q K^T (3-term) ----
        float s[8][4];
        #pragma unroll
        for (int j = 0; j < 8; j++)
            #pragma unroll
            for (int p = 0; p < 4; p++) s[j][p] = 0.f;

        #pragma unroll
        for (int c = 0; c < 4; c++) {
            #pragma unroll
            for (int ib = 0; ib < 4; ib++) {
                uint32_t bd = base + (uint32_t)((ib * 16 + lr) * ATS + c * 16 + lc8) * 2;
                uint32_t kbh[4], kbl[4];
                ldsm4(kbh, bd);
                ldsm4(kbl, bd + AT_TILE);
                #pragma unroll
                for (int sbn = 0; sbn < 2; sbn++) {
                    int j = ib * 2 + sbn;
                    mma16816(s[j], qfh[c], kbh[sbn], kbh[sbn + 2]);
                    mma16816(s[j], qfh[c], kbl[sbn], kbl[sbn + 2]);
                    mma16816(s[j], qfl[c], kbh[sbn], kbh[sbn + 2]);
                }
            }
        }

        // ---- scale + mask ----
        #pragma unroll
        for (int j = 0; j < 8; j++) {
            int c0 = k0 + j * 8 + 2 * tq, c1 = c0 + 1;
            s[j][0] = (c0 < Lv) ? s[j][0] * 0.125f : -1e9f;
            s[j][1] = (c1 < Lv) ? s[j][1] * 0.125f : -1e9f;
            s[j][2] = (c0 < Lv) ? s[j][2] * 0.125f : -1e9f;
            s[j][3] = (c1 < Lv) ? s[j][3] * 0.125f : -1e9f;
        }

        // ---- online softmax (rows r and r+8) ----
        float mA = -1e30f, mB = -1e30f;
        #pragma unroll
        for (int j = 0; j < 8; j++) {
            mA = fmaxf(mA, fmaxf(s[j][0], s[j][1]));
            mB = fmaxf(mB, fmaxf(s[j][2], s[j][3]));
        }
        mA = fmaxf(mA, __shfl_xor_sync(0xffffffffu, mA, 1));
        mA = fmaxf(mA, __shfl_xor_sync(0xffffffffu, mA, 2));
        mB = fmaxf(mB, __shfl_xor_sync(0xffffffffu, mB, 1));
        mB = fmaxf(mB, __shfl_xor_sync(0xffffffffu, mB, 2));
        float mnA = fmaxf(mrA, mA), mnB = fmaxf(mrB, mB);
        float aA = expf(mrA - mnA), aB = expf(mrB - mnB);
        float rsA = 0.f, rsB = 0.f;
        #pragma unroll
        for (int j = 0; j < 8; j++) {
            s[j][0] = expf(s[j][0] - mnA);
            s[j][1] = expf(s[j][1] - mnA);
            s[j][2] = expf(s[j][2] - mnB);
            s[j][3] = expf(s[j][3] - mnB);
            rsA += s[j][0] + s[j][1];
            rsB += s[j][2] + s[j][3];
        }
        rsA += __shfl_xor_sync(0xffffffffu, rsA, 1);
        rsA += __shfl_xor_sync(0xffffffffu, rsA, 2);
        rsB += __shfl_xor_sync(0xffffffffu, rsB, 1);
        rsB += __shfl_xor_sync(0xffffffffu, rsB, 2);
        lsA = lsA * aA + rsA;
        lsB = lsB * aB + rsB;
        mrA = mnA; mrB = mnB;
        #pragma unroll
        for (int j = 0; j < 8; j++) {
            o[j][0] *= aA; o[j][1] *= aA;
            o[j][2] *= aB; o[j][3] *= aB;
        }

        // ---- O += P V (3-term) ----
        #pragma unroll
        for (int c = 0; c < 4; c++) {
            uint32_t pah[4], pal[4];
            packsplit(s[2 * c][0],     s[2 * c][1],     pah[0], pal[0]);
            packsplit(s[2 * c][2],     s[2 * c][3],     pah[1], pal[1]);
            packsplit(s[2 * c + 1][0], s[2 * c + 1][1], pah[2], pal[2]);
            packsplit(s[2 * c + 1][2], s[2 * c + 1][3], pah[3], pal[3]);
            #pragma unroll
            for (int ib = 0; ib < 4; ib++) {
                uint32_t bd = base + 2 * AT_TILE +
                              (uint32_t)((ib * 16 + lr) * ATS + c * 16 + lc8) * 2;
                uint32_t vbh[4], vbl[4];
                ldsm4(vbh, bd);
                ldsm4(vbl, bd + AT_TILE);
                #pragma unroll
                for (int sbn = 0; sbn < 2; sbn++) {
                    int j = ib * 2 + sbn;
                    mma16816(o[j], pah, vbh[sbn], vbh[sbn + 2]);
                    mma16816(o[j], pal, vbh[sbn], vbh[sbn + 2]);
                    mma16816(o[j], pah, vbl[sbn], vbl[sbn + 2]);
                }
            }
        }
        __syncthreads();
    }

    // ---- write O ----
    float iA = 1.f / lsA, iB = 1.f / lsB;
    int qA = q0 + w * 16 + r, qB = qA + 8;
    #pragma unroll
    for (int j = 0; j < 8; j++) {
        int d = h * HD_ + j * 8 + 2 * tq;
        if (qA < L_) {
            size_t off = ((size_t)(b * L_) + qA) * D_ + d;
            uint32_t hw, lw;
            packsplit(o[j][0] * iA, o[j][1] * iA, hw, lw);
            *(uint32_t*)&g_ath[off] = hw;
            *(uint32_t*)&g_atl[off] = lw;
        }
        if (qB < L_) {
            size_t off = ((size_t)(b * L_) + qB) * D_ + d;
            uint32_t hw, lw;
            packsplit(o[j][2] * iB, o[j][3] * iB, hw, lw);
            *(uint32_t*)&g_ath[off] = hw;
            *(uint32_t*)&g_atl[off] = lw;
        }
    }
}

// ---------------------------------------------------------------------------
// x = LayerNorm(x + y) * s + b (in place) + bf16 hi/lo emission.
// ---------------------------------------------------------------------------
__global__ __launch_bounds__(256) void add_ln_kernel(const float* __restrict__ sc,
                                                     const float* __restrict__ bi) {
    int row = blockIdx.x;
    {
        int b = row / L_, pos = row - b * L_;
        if (pos >= 2 + g_tlen[b] + g_slen[b]) return;
    }
    size_t base = (size_t)row * D_;
    __shared__ float red[256];
    int tid = threadIdx.x;

    float v[4];
    float s = 0.f;
    #pragma unroll
    for (int u = 0; u < 4; u++) {
        int d = tid + u * 256;
        v[u] = g_x[base + d] + g_y[base + d];
        s += v[u];
    }
    red[tid] = s;
    __syncthreads();
    for (int off = 128; off > 0; off >>= 1) {
        if (tid < off) red[tid] += red[tid + off];
        __syncthreads();
    }
    float mean = red[0] * (1.f / D_);
    __syncthreads();

    float s2 = 0.f;
    #pragma unroll
    for (int u = 0; u < 4; u++) { float dd = v[u] - mean; s2 += dd * dd; }
    red[tid] = s2;
    __syncthreads();
    for (int off = 128; off > 0; off >>= 1) {
        if (tid < off) red[tid] += red[tid + off];
        __syncthreads();
    }
    float var = red[0] * (1.f / D_);
    float inv = rsqrtf(var + 1e-5f);

    #pragma unroll
    for (int u = 0; u < 4; u++) {
        int d = tid + u * 256;
        float t = (v[u] - mean) * inv * sc[d] + bi[d];
        g_x[base + d] = t;
        __nv_bfloat16 hh = __float2bfloat16(t);
        g_xh[base + d] = hh;
        g_xl[base + d] = __float2bfloat16(t - __bfloat162float(hh));
    }
}

// ---------------------------------------------------------------------------
// out[b] = dot(x[b, 0, :], out_w)
// ---------------------------------------------------------------------------
__global__ __launch_bounds__(256) void final_kernel(const float* __restrict__ ow,
                                                    float* __restrict__ out) {
    int b = blockIdx.x;
    __shared__ float red[256];
    const float* xr = &g_x[(size_t)(b * L_) * D_];
    int tid = threadIdx.x;
    float s = 0.f;
    for (int d = tid; d < D_; d += 256) s += xr[d] * ow[d];
    red[tid] = s;
    __syncthreads();
    for (int off = 128; off > 0; off >>= 1) {
        if (tid < off) red[tid] += red[tid + off];
        __syncthreads();
    }
    if (tid == 0) out[b] = red[0];
}

// ---------------------------------------------------------------------------
// Launch
// ---------------------------------------------------------------------------
extern "C" void kernel_launch(void* const* d_in, const int* in_sizes, int n_in,
                              void* d_out, int out_size) {
    const float* text   = (const float*)d_in[0];
    const float* speech = (const float*)d_in[1];
    const void*  tmask  = d_in[2];
    const void*  smask  = d_in[3];
    const float* cls    = (const float*)d_in[4];
    const float* sep    = (const float*)d_in[5];
    const float* Wq     = (const float*)d_in[6];
    const float* bq     = (const float*)d_in[7];
    const float* Wk     = (const float*)d_in[8];
    const float* bk     = (const float*)d_in[9];
    const float* Wv     = (const float*)d_in[10];
    const float* bv     = (const float*)d_in[11];
    const float* Wo     = (const float*)d_in[12];
    const float* bo     = (const float*)d_in[13];
    const float* ln1s   = (const float*)d_in[14];
    const float* ln1b   = (const float*)d_in[15];
    const float* f1w    = (const float*)d_in[16];
    const float* f1b    = (const float*)d_in[17];
    const float* f2w    = (const float*)d_in[18];
    const float* f2b    = (const float*)d_in[19];
    const float* ln2s   = (const float*)d_in[20];
    const float* ln2b   = (const float*)d_in[21];
    const float* outw   = (const float*)d_in[22];
    float* out = (float*)d_out;

    float* y;
    __nv_bfloat16 *xh, *xl, *qh, *ql, *kh, *kl, *vth, *vtl, *ath, *atl, *hh, *hl;
    __nv_bfloat16 *Wqh, *Wql, *Wkh, *Wkl, *Wvh, *Wvl, *Woh, *Wol, *F1h, *F1l, *F2h, *F2l;
    cudaGetSymbolAddress((void**)&y,   g_y);
    cudaGetSymbolAddress((void**)&xh,  g_xh);
    cudaGetSymbolAddress((void**)&xl,  g_xl);
    cudaGetSymbolAddress((void**)&qh,  g_qh);
    cudaGetSymbolAddress((void**)&ql,  g_ql);
    cudaGetSymbolAddress((void**)&kh,  g_kh);
    cudaGetSymbolAddress((void**)&kl,  g_kl);
    cudaGetSymbolAddress((void**)&vth, g_vth);
    cudaGetSymbolAddress((void**)&vtl, g_vtl);
    cudaGetSymbolAddress((void**)&ath, g_ath);
    cudaGetSymbolAddress((void**)&atl, g_atl);
    cudaGetSymbolAddress((void**)&hh,  g_hh);
    cudaGetSymbolAddress((void**)&hl,  g_hl);
    cudaGetSymbolAddress((void**)&Wqh, g_Wqh);
    cudaGetSymbolAddress((void**)&Wql, g_Wql);
    cudaGetSymbolAddress((void**)&Wkh, g_Wkh);
    cudaGetSymbolAddress((void**)&Wkl, g_Wkl);
    cudaGetSymbolAddress((void**)&Wvh, g_Wvh);
    cudaGetSymbolAddress((void**)&Wvl, g_Wvl);
    cudaGetSymbolAddress((void**)&Woh, g_Woh);
    cudaGetSymbolAddress((void**)&Wol, g_Wol);
    cudaGetSymbolAddress((void**)&F1h, g_F1h);
    cudaGetSymbolAddress((void**)&F1l, g_F1l);
    cudaGetSymbolAddress((void**)&F2h, g_F2h);
    cudaGetSymbolAddress((void**)&F2l, g_F2l);

    cudaFuncSetAttribute(attn_mma_kernel,
                         cudaFuncAttributeMaxDynamicSharedMemorySize, ATT_SMEM);
    cudaFuncSetAttribute(gemm_mma<0, 0>,
                         cudaFuncAttributeMaxDynamicSharedMemorySize, GEMM_SMEM);
    cudaFuncSetAttribute(gemm_mma<0, 1>,
                         cudaFuncAttributeMaxDynamicSharedMemorySize, GEMM_SMEM);
    cudaFuncSetAttribute(gemm_mma<0, 2>,
                         cudaFuncAttributeMaxDynamicSharedMemorySize, GEMM_SMEM);
    cudaFuncSetAttribute(gemm_mma<1, 1>,
                         cudaFuncAttributeMaxDynamicSharedMemorySize, GEMM_SMEM);

    lengths_kernel<<<2, 256>>>(tmask, smask);
    build_x_kernel<<<dim3(L_, B_), 256>>>(text, speech, cls, sep);

    dim3 tb(32, 8);
    for (int l = 0; l < NL_; l++) {
        size_t od = (size_t)l * D_ * D_;
        size_t o1 = (size_t)l * D_ * F_;
        size_t o2 = (size_t)l * F_ * D_;
        wsplit_kernel<<<dim3(D_ / 32, D_ / 32), tb>>>(Wq + od, Wqh + od, Wql + od, D_, D_);
        wsplit_kernel<<<dim3(D_ / 32, D_ / 32), tb>>>(Wk + od, Wkh + od, Wkl + od, D_, D_);
        wsplit_kernel<<<dim3(D_ / 32, D_ / 32), tb>>>(Wv + od, Wvh + od, Wvl + od, D_, D_);
        wsplit_kernel<<<dim3(D_ / 32, D_ / 32), tb>>>(Wo + od, Woh + od, Wol + od, D_, D_);
        wsplit_kernel<<<dim3(F_ / 32, D_ / 32), tb>>>(f1w + o1, F1h + o1, F1l + o1, D_, F_);
        wsplit_kernel<<<dim3(D_ / 32, F_ / 32), tb>>>(f2w + o2, F2h + o2, F2l + o2, F_, D_);
    }

    int mt = (M_ + 127) / 128;  // 81
    dim3 gD(D_ / 128, mt);
    dim3 gF(F_ / 128, mt);
    dim3 gAtt((L_ + 63) / 64, H_, B_);

    for (int l = 0; l < NL_; l++) {
        size_t od = (size_t)l * D_ * D_;
        size_t o1 = (size_t)l * D_ * F_;
        size_t o2 = (size_t)l * F_ * D_;
        gemm_mma<0, 1><<<gD, 256, GEMM_SMEM>>>(xh, xl, Wqh + od, Wql + od, bq + l * D_,
                                               nullptr, qh, ql, M_, D_, D_);
        gemm_mma<0, 1><<<gD, 256, GEMM_SMEM>>>(xh, xl, Wkh + od, Wkl + od, bk + l * D_,
                                               nullptr, kh, kl, M_, D_, D_);
        gemm_mma<0, 2><<<gD, 256, GEMM_SMEM>>>(xh, xl, Wvh + od, Wvl + od, bv + l * D_,
                                               nullptr, vth, vtl, M_, D_, D_);
        attn_mma_kernel<<<gAtt, 128, ATT_SMEM>>>();
        gemm_mma<0, 0><<<gD, 256, GEMM_SMEM>>>(ath, atl, Woh + od, Wol + od, bo + l * D_,
                                               y, nullptr, nullptr, M_, D_, D_);
        add_ln_kernel<<<M_, 256>>>(ln1s + l * D_, ln1b + l * D_);
        gemm_mma<1, 1><<<gF, 256, GEMM_SMEM>>>(xh, xl, F1h + o1, F1l + o1, f1b + l * F_,
                                               nullptr, hh, hl, M_, F_, D_);
        gemm_mma<0, 0><<<gD, 256, GEMM_SMEM>>>(hh, hl, F2h + o2, F2l + o2, f2b + l * D_,
                                               y, nullptr, nullptr, M_, D_, F_);
        add_ln_kernel<<<M_, 256>>>(ln2s + l * D_, ln2b + l * D_);
    }
    final_kernel<<<B_, 256>>>(outw, out);
}

// round 11
// speedup vs baseline: 3.1367x; 1.0986x over previous
#include <cuda_runtime.h>
#include <cuda_bf16.h>
#include <math.h>
#include <stdint.h>

// ---------------------------------------------------------------------------
// Problem constants
// ---------------------------------------------------------------------------
namespace {
constexpr int B_  = 16;
constexpr int TT_ = 128;
constexpr int TS_ = 512;
constexpr int L_  = TT_ + TS_ + 2;   // 642
constexpr int LT_ = 648;             // vt row stride: multiple of 8 elems (16B)
constexpr int D_  = 1024;
constexpr int H_  = 16;
constexpr int HD_ = 64;
constexpr int F_  = 4096;
constexpr int NL_ = 4;
constexpr int M_  = B_ * L_;         // 10272

// GEMM tiling
constexpr int BK_     = 32;
constexpr int STAGES_ = 3;
constexpr int LDS_    = 40;                    // padded row stride (elements)
constexpr int ASZ_    = 128 * LDS_ * 2;        // 10240 bytes per tile array
constexpr int STAGE_B = 4 * ASZ_;              // 40960 bytes per stage
constexpr int GEMM_SMEM = STAGES_ * STAGE_B + 1024;  // 123904

// Attention tiling
constexpr int ATS      = 72;                   // smem row stride (elements)
constexpr int AT_TILE  = 64 * ATS * 2;         // 9216 bytes per 64x64 bf16 array
constexpr int ATT_ST0  = 2 * AT_TILE;          // Qh, Ql
constexpr int ATT_STG  = 4 * AT_TILE;          // Kh, Kl, Vth, Vtl per stage
constexpr int ATT_SMEM = ATT_ST0 + 2 * ATT_STG; // 92160
}

// ---------------------------------------------------------------------------
// Scratch (allocation-free: __device__ globals; zero-initialized)
// ---------------------------------------------------------------------------
__device__ float g_x[(size_t)M_ * D_];
__device__ float g_y[(size_t)M_ * D_];
__device__ __nv_bfloat16 g_xh [(size_t)M_ * D_];
__device__ __nv_bfloat16 g_xl [(size_t)M_ * D_];
__device__ __nv_bfloat16 g_qh [(size_t)M_ * D_];
__device__ __nv_bfloat16 g_ql [(size_t)M_ * D_];
__device__ __nv_bfloat16 g_kh [(size_t)M_ * D_];
__device__ __nv_bfloat16 g_kl [(size_t)M_ * D_];
__device__ __nv_bfloat16 g_vth[(size_t)B_ * D_ * LT_ + 64];
__device__ __nv_bfloat16 g_vtl[(size_t)B_ * D_ * LT_ + 64];
__device__ __nv_bfloat16 g_ath[(size_t)M_ * D_];
__device__ __nv_bfloat16 g_atl[(size_t)M_ * D_];
__device__ __nv_bfloat16 g_hh [(size_t)M_ * F_];
__device__ __nv_bfloat16 g_hl [(size_t)M_ * F_];
// transposed + hi/lo-split weights: [N,K] layout
__device__ __nv_bfloat16 g_Wqh[(size_t)NL_ * D_ * D_];
__device__ __nv_bfloat16 g_Wql[(size_t)NL_ * D_ * D_];
__device__ __nv_bfloat16 g_Wkh[(size_t)NL_ * D_ * D_];
__device__ __nv_bfloat16 g_Wkl[(size_t)NL_ * D_ * D_];
__device__ __nv_bfloat16 g_Wvh[(size_t)NL_ * D_ * D_];
__device__ __nv_bfloat16 g_Wvl[(size_t)NL_ * D_ * D_];
__device__ __nv_bfloat16 g_Woh[(size_t)NL_ * D_ * D_];
__device__ __nv_bfloat16 g_Wol[(size_t)NL_ * D_ * D_];
__device__ __nv_bfloat16 g_F1h[(size_t)NL_ * D_ * F_];
__device__ __nv_bfloat16 g_F1l[(size_t)NL_ * D_ * F_];
__device__ __nv_bfloat16 g_F2h[(size_t)NL_ * F_ * D_];
__device__ __nv_bfloat16 g_F2l[(size_t)NL_ * F_ * D_];
__device__ int g_tlen[B_];
__device__ int g_slen[B_];

// ---------------------------------------------------------------------------
// PTX helpers (sm_80-era subset only: cp.async, ldmatrix, mma.sync)
// ---------------------------------------------------------------------------
__device__ __forceinline__ uint32_t s2u(const void* p) {
    uint32_t a;
    asm("{ .reg .u64 t; cvta.to.shared.u64 t, %1; cvt.u32.u64 %0, t; }"
        : "=r"(a) : "l"(p));
    return a;
}
__device__ __forceinline__ void cp16(uint32_t s, const void* g, int nbytes) {
    asm volatile("cp.async.cg.shared.global [%0], [%1], 16, %2;"
                 :: "r"(s), "l"(g), "r"(nbytes));
}
__device__ __forceinline__ void cp_commit() {
    asm volatile("cp.async.commit_group;");
}
template <int N> __device__ __forceinline__ void cp_wait() {
    asm volatile("cp.async.wait_group %0;" :: "n"(N));
}
__device__ __forceinline__ void ldsm4(uint32_t* r, uint32_t addr) {
    asm volatile("ldmatrix.sync.aligned.m8n8.x4.shared.b16 {%0,%1,%2,%3}, [%4];"
                 : "=r"(r[0]), "=r"(r[1]), "=r"(r[2]), "=r"(r[3]) : "r"(addr));
}
__device__ __forceinline__ void mma16816(float* c, const uint32_t* a,
                                         uint32_t b0, uint32_t b1) {
    asm volatile(
        "mma.sync.aligned.m16n8k16.row.col.f32.bf16.bf16.f32 "
        "{%0,%1,%2,%3}, {%4,%5,%6,%7}, {%8,%9}, {%0,%1,%2,%3};\n"
        : "+f"(c[0]), "+f"(c[1]), "+f"(c[2]), "+f"(c[3])
        : "r"(a[0]), "r"(a[1]), "r"(a[2]), "r"(a[3]), "r"(b0), "r"(b1));
}
// split two fp32 into packed bf16x2 hi and lo words
__device__ __forceinline__ void packsplit(float x, float y,
                                          uint32_t& hi, uint32_t& lo) {
    __nv_bfloat16 hx = __float2bfloat16(x), hy = __float2bfloat16(y);
    __nv_bfloat162 hh = __halves2bfloat162(hx, hy);
    __nv_bfloat162 ll = __halves2bfloat162(
        __float2bfloat16(x - __bfloat162float(hx)),
        __float2bfloat16(y - __bfloat162float(hy)));
    hi = *(uint32_t*)&hh;
    lo = *(uint32_t*)&ll;
}

// ---------------------------------------------------------------------------
// Mask length computation with on-device dtype detection
// ---------------------------------------------------------------------------
__global__ void lengths_kernel(const void* tmask, const void* smask) {
    int which = blockIdx.x;
    const void* mask = which ? smask : tmask;
    int T = which ? TS_ : TT_;
    int* lens = which ? g_slen : g_tlen;
    int N = B_ * T;

    __shared__ int f3F, fMis;
    __shared__ int cnt[B_];
    int tid = threadIdx.x;
    if (tid == 0) { f3F = 0; fMis = 0; }
    if (tid < B_) cnt[tid] = 0;
    __syncthreads();

    const unsigned char* bytes = (const unsigned char*)mask;
    int l3 = 0, lm = 0;
    for (int i = tid; i < N; i += blockDim.x) {
        unsigned char c = bytes[i];
        if (c == 0x3F) l3 = 1;
        if (c == 1 && (i & 3)) lm = 1;
    }
    if (l3) atomicOr(&f3F, 1);
    if (lm) atomicOr(&fMis, 1);
    __syncthreads();

    if (fMis && !f3F) {
        for (int i = tid; i < N; i += blockDim.x)
            if (bytes[i] == 0) atomicAdd(&cnt[i / T], 1);
    } else {
        const unsigned int* w = (const unsigned int*)mask;
        for (int i = tid; i < N; i += blockDim.x)
            if (w[i] == 0u) atomicAdd(&cnt[i / T], 1);
    }
    __syncthreads();
    if (tid < B_) lens[tid] = cnt[tid];
}

// ---------------------------------------------------------------------------
// Build concatenated sequence x (fp32 + bf16 hi/lo)
// ---------------------------------------------------------------------------
__global__ void build_x_kernel(const float* __restrict__ text,
                               const float* __restrict__ speech,
                               const float* __restrict__ cls,
                               const float* __restrict__ sep) {
    int pos = blockIdx.x, b = blockIdx.y;
    int tl = g_tlen[b], sl = g_slen[b];
    size_t base = ((size_t)(b * L_) + pos) * D_;

    const float* s;
    if (pos == 0)                 s = cls;
    else if (pos < 1 + tl)        s = &text  [((size_t)(pos - 1) * B_ + b) * D_];
    else if (pos == 1 + tl)       s = sep;
    else if (pos < 2 + tl + sl)   s = &speech[((size_t)(pos - 2 - tl) * B_ + b) * D_];
    else                          s = nullptr;

    for (int d = threadIdx.x; d < D_; d += blockDim.x) {
        float v = s ? s[d] : 0.f;
        g_x[base + d] = v;
        __nv_bfloat16 h = __float2bfloat16(v);
        g_xh[base + d] = h;
        g_xl[base + d] = __float2bfloat16(v - __bfloat162float(h));
    }
}

// ---------------------------------------------------------------------------
// Weight transpose + hi/lo split: W[K,N] fp32 -> Th/Tl[N,K] bf16
// ---------------------------------------------------------------------------
__global__ void wsplit_kernel(const float* __restrict__ W,
                              __nv_bfloat16* __restrict__ Th,
                              __nv_bfloat16* __restrict__ Tl, int K, int N) {
    __shared__ float t[32][33];
    int n0 = blockIdx.x * 32, k0 = blockIdx.y * 32;
    int tx = threadIdx.x, ty = threadIdx.y;
    #pragma unroll
    for (int j = 0; j < 4; j++) {
        int k = k0 + ty + j * 8;
        t[ty + j * 8][tx] = W[(size_t)k * N + n0 + tx];
    }
    __syncthreads();
    #pragma unroll
    for (int j = 0; j < 4; j++) {
        int n = n0 + ty + j * 8;
        float v = t[tx][ty + j * 8];
        __nv_bfloat16 h = __float2bfloat16(v);
        Th[(size_t)n * K + k0 + tx] = h;
        Tl[(size_t)n * K + k0 + tx] = __float2bfloat16(v - __bfloat162float(h));
    }
}

// ---------------------------------------------------------------------------
// HMMA bf16 GEMM with 3-term hi/lo compensation + pad-tile skipping.
// 128x128x32 CTA tile, 512 threads (16 warps, 4x4 grid, 32x32 warp-tile),
// 3-stage cp.async pipeline. 16 warps/SM for latency hiding.
// MODE 0: fp32 C.  MODE 1: bf16 hi/lo C (after optional RELU).
// MODE 2: bf16 hi/lo C written TRANSPOSED per batch: vt[(b*D + n)*LT + pos].
// ---------------------------------------------------------------------------
template <int RELU, int MODE>
__global__ __launch_bounds__(512, 1) void gemm_mma(
    const __nv_bfloat16* __restrict__ Ah, const __nv_bfloat16* __restrict__ Al,
    const __nv_bfloat16* __restrict__ Bh, const __nv_bfloat16* __restrict__ Bl,
    const float* __restrict__ bias,
    float* __restrict__ Cf,
    __nv_bfloat16* __restrict__ Ch, __nv_bfloat16* __restrict__ Cl,
    int Mn, int Nn, int Kn) {
    extern __shared__ char dynsmem[];
    uint32_t sbase = (s2u(dynsmem) + 1023u) & ~1023u;
    int tid = threadIdx.x;
    int wid = tid >> 5, lane = tid & 31;
    int m0 = blockIdx.y * 128, n0 = blockIdx.x * 128;

    // ---- pad-tile skip ----
    {
        int rend = m0 + 128;
        if (rend > Mn) rend = Mn;
        int bb0 = m0 / L_, bb1 = (rend - 1) / L_;
        bool anyv = false;
        for (int b = bb0; b <= bb1; b++) {
            int seg = m0 > b * L_ ? m0 - b * L_ : 0;
            if (seg < 2 + g_tlen[b] + g_slen[b]) anyv = true;
        }
        if (!anyv) return;
    }

    int wm = wid & 3, wn = wid >> 2;     // 4x4 warp grid
    int m0w = wm * 32, n0w = wn * 32;
    const int T = Kn / BK_;

    int la = tid >> 7;        // 0..3 -> Ah, Al, Bh, Bl
    int t7 = tid & 127;

    auto issue = [&](int kt) {
        uint32_t stb = sbase + (kt % STAGES_) * STAGE_B + la * ASZ_;
        #pragma unroll
        for (int i = 0; i < 4; i++) {
            int chunk = t7 + 128 * i;         // 0..511
            int row = chunk >> 2;             // 0..127
            int col = chunk & 3;              // 16B chunk within 64B row
            uint32_t dst = stb + (uint32_t)(row * LDS_ + col * 8) * 2;
            if (la < 2) {
                int gr = m0 + row;
                bool v = gr < Mn;
                const __nv_bfloat16* src =
                    (la ? Al : Ah) + (size_t)(v ? gr : 0) * Kn + kt * BK_ + col * 8;
                cp16(dst, src, v ? 16 : 0);
            } else {
                const __nv_bfloat16* src =
                    (la == 2 ? Bh : Bl) + (size_t)(n0 + row) * Kn + kt * BK_ + col * 8;
                cp16(dst, src, 16);
            }
        }
        cp_commit();
    };

    issue(0);
    issue(1);

    float acc[2][4][4];
    #pragma unroll
    for (int i = 0; i < 2; i++)
        #pragma unroll
        for (int j = 0; j < 4; j++)
            #pragma unroll
            for (int p = 0; p < 4; p++) acc[i][j][p] = 0.f;

    int lr = lane & 15, lc8 = (lane >> 4) * 8;

    for (int kt = 0; kt < T; kt++) {
        cp_wait<STAGES_ - 2>();
        __syncthreads();
        uint32_t stb = sbase + (kt % STAGES_) * STAGE_B;
        #pragma unroll
        for (int kk = 0; kk < 2; kk++) {
            int koff = kk * 16 + lc8;
            uint32_t ah[2][4], al[2][4], bh[2][4], bl[2][4];
            #pragma unroll
            for (int im = 0; im < 2; im++) {
                uint32_t ad = stb + (uint32_t)((m0w + im * 16 + lr) * LDS_ + koff) * 2;
                ldsm4(ah[im], ad);
                ldsm4(al[im], ad + ASZ_);
            }
            #pragma unroll
            for (int ib = 0; ib < 2; ib++) {
                uint32_t bd = stb + 2 * ASZ_ +
                              (uint32_t)((n0w + ib * 16 + lr) * LDS_ + koff) * 2;
                ldsm4(bh[ib], bd);
                ldsm4(bl[ib], bd + ASZ_);
            }
            #pragma unroll
            for (int im = 0; im < 2; im++)
                #pragma unroll
                for (int in = 0; in < 4; in++) {
                    int ib = in >> 1, sb = in & 1;
                    mma16816(acc[im][in], ah[im], bh[ib][sb], bh[ib][sb + 2]);
                    mma16816(acc[im][in], ah[im], bl[ib][sb], bl[ib][sb + 2]);
                    mma16816(acc[im][in], al[im], bh[ib][sb], bh[ib][sb + 2]);
                }
        }
        int nt = kt + STAGES_ - 1;
        if (nt < T) issue(nt); else cp_commit();
    }

    // Epilogue
    int g = lane >> 2, tq = lane & 3;
    #pragma unroll
    for (int in = 0; in < 4; in++) {
        int cb = n0 + n0w + in * 8 + tq * 2;
        float b0 = __ldg(&bias[cb]), b1 = __ldg(&bias[cb + 1]);
        #pragma unroll
        for (int im = 0; im < 2; im++) {
            #pragma unroll
            for (int hrow = 0; hrow < 2; hrow++) {
                int m = m0 + m0w + im * 16 + g + hrow * 8;
                if (m < Mn) {
                    float v0 = acc[im][in][hrow * 2 + 0] + b0;
                    float v1 = acc[im][in][hrow * 2 + 1] + b1;
                    if (RELU) { v0 = fmaxf(v0, 0.f); v1 = fmaxf(v1, 0.f); }
                    if (MODE == 0) {
                        *(float2*)&Cf[(size_t)m * Nn + cb] = make_float2(v0, v1);
                    } else if (MODE == 1) {
                        uint32_t hw, lw;
                        packsplit(v0, v1, hw, lw);
                        *(uint32_t*)&Ch[(size_t)m * Nn + cb] = hw;
                        *(uint32_t*)&Cl[(size_t)m * Nn + cb] = lw;
                    } else {
                        // transposed per-batch: vt[(b*D + n)*LT + pos]
                        int bb = m / L_, pos = m - bb * L_;
                        size_t vt0 = ((size_t)bb * D_ + cb) * LT_ + pos;
                        __nv_bfloat16 h0 = __float2bfloat16(v0);
                        __nv_bfloat16 h1 = __float2bfloat16(v1);
                        Ch[vt0]       = h0;
                        Ch[vt0 + LT_] = h1;
                        Cl[vt0]       = __float2bfloat16(v0 - __bfloat162float(h0));
                        Cl[vt0 + LT_] = __float2bfloat16(v1 - __bfloat162float(h1));
                    }
                }
            }
        }
    }
}

// ---------------------------------------------------------------------------
// HMMA flash attention with 3-term hi/lo compensation.
// Block: (q-tile 64, head, batch), 128 threads (4 warps x m16 rows).
// Q/K from g_qh/l, g_kh/l ([pos][d] bf16); V from g_vth/l ([d][pos], LT stride).
// Writes softmax(QK^T/8 masked) V to g_ath/l as bf16 hi/lo.
// ---------------------------------------------------------------------------
__global__ __launch_bounds__(128, 1) void attn_mma_kernel() {
    extern __shared__ char asmem[];
    uint32_t sb = s2u(asmem);
    int tid = threadIdx.x, lane = tid & 31, w = tid >> 5;
    int qt = blockIdx.x, h = blockIdx.y, b = blockIdx.z;
    int q0 = qt * 64;
    int Lv = 2 + g_tlen[b] + g_slen[b];
    if (q0 >= Lv) return;
    const int NKT = (Lv + 63) >> 6;

    int lr = lane & 15, lc8 = (lane >> 4) * 8;
    int r = lane >> 2, tq = lane & 3;
    int lrow = tid >> 1, lhf = tid & 1;   // smem-fill: row, col-half

    // ---- stage Q (hi/lo) ----
    {
        int qrow = q0 + lrow; if (qrow > L_ - 1) qrow = L_ - 1;
        size_t off = ((size_t)(b * L_) + qrow) * D_ + h * HD_ + lhf * 32;
        uint32_t dst = sb + (uint32_t)(lrow * ATS + lhf * 32) * 2;
        #pragma unroll
        for (int u = 0; u < 4; u++) {
            cp16(dst + u * 16,           g_qh + off + u * 8, 16);
            cp16(dst + AT_TILE + u * 16, g_ql + off + u * 8, 16);
        }
        cp_commit();
    }

    auto loadKV = [&](int kt) {
        uint32_t base = sb + ATT_ST0 + (kt & 1) * ATT_STG;
        int k0 = kt * 64;
        int krow = k0 + lrow; if (krow > L_ - 1) krow = L_ - 1;
        size_t koff = ((size_t)(b * L_) + krow) * D_ + h * HD_ + lhf * 32;
        uint32_t kdst = base + (uint32_t)(lrow * ATS + lhf * 32) * 2;
        #pragma unroll
        for (int u = 0; u < 4; u++) {
            cp16(kdst + u * 16,           g_kh + koff + u * 8, 16);
            cp16(kdst + AT_TILE + u * 16, g_kl + koff + u * 8, 16);
        }
        // V: row stride LT_ (16B-aligned); pad cols [L_, LT_) are zeros.
        size_t voff = ((size_t)b * D_ + h * HD_ + lrow) * LT_ + k0 + lhf * 32;
        uint32_t vdst = base + 2 * AT_TILE + (uint32_t)(lrow * ATS + lhf * 32) * 2;
        #pragma unroll
        for (int u = 0; u < 4; u++) {
            int col = k0 + lhf * 32 + u * 8;
            int nb = (col < LT_) ? 16 : 0;   // zfill past padded length
            cp16(vdst + u * 16,           g_vth + voff + u * 8, nb);
            cp16(vdst + AT_TILE + u * 16, g_vtl + voff + u * 8, nb);
        }
        cp_commit();
    };

    loadKV(0);
    cp_wait<1>();           // Q staged (KV0 may still be in flight)
    __syncthreads();

    // Q fragments (held in registers for the whole kernel)
    uint32_t qfh[4][4], qfl[4][4];
    #pragma unroll
    for (int c = 0; c < 4; c++) {
        uint32_t ad = sb + (uint32_t)((w * 16 + lr) * ATS + c * 16 + lc8) * 2;
        ldsm4(qfh[c], ad);
        ldsm4(qfl[c], ad + AT_TILE);
    }

    float o[8][4];
    #pragma unroll
    for (int j = 0; j < 8; j++)
        #pragma unroll
        for (int p = 0; p < 4; p++) o[j][p] = 0.f;
    float mrA = -1e30f, mrB = -1e30f, lsA = 0.f, lsB = 0.f;

    for (int kt = 0; kt < NKT; kt++) {
        if (kt + 1 < NKT) { loadKV(kt + 1); cp_wait<1>(); }
        else              { cp_wait<0>(); }
        __syncthreads();
        uint32_t base = sb + ATT_ST0 + (kt & 1) * ATT_STG;
        int k0 = kt * 64;

        // ---- S = Q K^T (3-term) ----
        float s[8][4];
        #pragma unroll
        for (int j = 0; j < 8; j++)
            #pragma unroll
            for (int p = 0; p < 4; p++) s[j][p] = 0.f;

        #pragma unroll
        for (int c = 0; c < 4; c++) {
            #pragma unroll
            for (int ib = 0; ib < 4; ib++) {
                uint32_t bd = base + (uint32_t)((ib * 16 + lr) * ATS + c * 16 + lc8) * 2;
                uint32_t kbh[4], kbl[4];
                ldsm4(kbh, bd);
                ldsm4(kbl, bd + AT_TILE);
                #pragma unroll
                for (int sbn = 0; sbn < 2; sbn++) {
                    int j = ib * 2 + sbn;
                    mma16816(s[j], qfh[c], kbh[sbn], kbh[sbn + 2]);
                    mma16816(s[j], qfh[c], kbl[sbn], kbl[sbn + 2]);
                    mma16816(s[j], qfl[c], kbh[sbn], kbh[sbn + 2]);
                }
            }
        }

        // ---- scale + mask ----
        #pragma unroll
        for (int j = 0; j < 8; j++) {
            int c0 = k0 + j * 8 + 2 * tq, c1 = c0 + 1;
            s[j][0] = (c0 < Lv) ? s[j][0] * 0.125f : -1e9f;
            s[j][1] = (c1 < Lv) ? s[j][1] * 0.125f : -1e9f;
            s[j][2] = (c0 < Lv) ? s[j][2] * 0.125f : -1e9f;
            s[j][3] = (c1 < Lv) ? s[j][3] * 0.125f : -1e9f;
        }

        // ---- online softmax (rows r and r+8) ----
        float mA = -1e30f, mB = -1e30f;
        #pragma unroll
        for (int j = 0; j < 8; j++) {
            mA = fmaxf(mA, fmaxf(s[j][0], s[j][1]));
            mB = fmaxf(mB, fmaxf(s[j][2], s[j][3]));
        }
        mA = fmaxf(mA, __shfl_xor_sync(0xffffffffu, mA, 1));
        mA = fmaxf(mA, __shfl_xor_sync(0xffffffffu, mA, 2));
        mB = fmaxf(mB, __shfl_xor_sync(0xffffffffu, mB, 1));
        mB = fmaxf(mB, __shfl_xor_sync(0xffffffffu, mB, 2));
        float mnA = fmaxf(mrA, mA), mnB = fmaxf(mrB, mB);
        float aA = expf(mrA - mnA), aB = expf(mrB - mnB);
        float rsA = 0.f, rsB = 0.f;
        #pragma unroll
        for (int j = 0; j < 8; j++) {
            s[j][0] = expf(s[j][0] - mnA);
            s[j][1] = expf(s[j][1] - mnA);
            s[j][2] = expf(s[j][2] - mnB);
            s[j][3] = expf(s[j][3] - mnB);
            rsA += s[j][0] + s[j][1];
            rsB += s[j][2] + s[j][3];
        }
        rsA += __shfl_xor_sync(0xffffffffu, rsA, 1);
        rsA += __shfl_xor_sync(0xffffffffu, rsA, 2);
        rsB += __shfl_xor_sync(0xffffffffu, rsB, 1);
        rsB += __shfl_xor_sync(0xffffffffu, rsB, 2);
        lsA = lsA * aA + rsA;
        lsB = lsB * aB + rsB;
        mrA = mnA; mrB = mnB;
        #pragma unroll
        for (int j = 0; j < 8; j++) {
            o[j][0] *= aA; o[j][1] *= aA;
            o[j][2] *= aB; o[j][3] *= aB;
        }

        // ---- O += P V (3-term) ----
        #pragma unroll
        for (int c = 0; c < 4; c++) {
            uint32_t pah[4], pal[4];
            packsplit(s[2 * c][0],     s[2 * c][1],     pah[0], pal[0]);
            packsplit(s[2 * c][2],     s[2 * c][3],     pah[1], pal[1]);
            packsplit(s[2 * c + 1][0], s[2 * c + 1][1], pah[2], pal[2]);
            packsplit(s[2 * c + 1][2], s[2 * c + 1][3], pah[3], pal[3]);
            #pragma unroll
            for (int ib = 0; ib < 4; ib++) {
                uint32_t bd = base + 2 * AT_TILE +
                              (uint32_t)((ib * 16 + lr) * ATS + c * 16 + lc8) * 2;
                uint32_t vbh[4], vbl[4];
                ldsm4(vbh, bd);
                ldsm4(vbl, bd + AT_TILE);
                #pragma unroll
                for (int sbn = 0; sbn < 2; sbn++) {
                    int j = ib * 2 + sbn;
                    mma16816(o[j], pah, vbh[sbn], vbh[sbn + 2]);
                    mma16816(o[j], pal, vbh[sbn], vbh[sbn + 2]);
                    mma16816(o[j], pah, vbl[sbn], vbl[sbn + 2]);
                }
            }
        }
        __syncthreads();
    }

    // ---- write O ----
    float iA = 1.f / lsA, iB = 1.f / lsB;
    int qA = q0 + w * 16 + r, qB = qA + 8;
    #pragma unroll
    for (int j = 0; j < 8; j++) {
        int d = h * HD_ + j * 8 + 2 * tq;
        if (qA < L_) {
            size_t off = ((size_t)(b * L_) + qA) * D_ + d;
            uint32_t hw, lw;
            packsplit(o[j][0] * iA, o[j][1] * iA, hw, lw);
            *(uint32_t*)&g_ath[off] = hw;
            *(uint32_t*)&g_atl[off] = lw;
        }
        if (qB < L_) {
            size_t off = ((size_t)(b * L_) + qB) * D_ + d;
            uint32_t hw, lw;
            packsplit(o[j][2] * iB, o[j][3] * iB, hw, lw);
            *(uint32_t*)&g_ath[off] = hw;
            *(uint32_t*)&g_atl[off] = lw;
        }
    }
}

// ---------------------------------------------------------------------------
// x = LayerNorm(x + y) * s + b (in place) + bf16 hi/lo emission.
// ---------------------------------------------------------------------------
__global__ __launch_bounds__(256) void add_ln_kernel(const float* __restrict__ sc,
                                                     const float* __restrict__ bi) {
    int row = blockIdx.x;
    {
        int b = row / L_, pos = row - b * L_;
        if (pos >= 2 + g_tlen[b] + g_slen[b]) return;
    }
    size_t base = (size_t)row * D_;
    __shared__ float red[256];
    int tid = threadIdx.x;

    float v[4];
    float s = 0.f;
    #pragma unroll
    for (int u = 0; u < 4; u++) {
        int d = tid + u * 256;
        v[u] = g_x[base + d] + g_y[base + d];
        s += v[u];
    }
    red[tid] = s;
    __syncthreads();
    for (int off = 128; off > 0; off >>= 1) {
        if (tid < off) red[tid] += red[tid + off];
        __syncthreads();
    }
    float mean = red[0] * (1.f / D_);
    __syncthreads();

    float s2 = 0.f;
    #pragma unroll
    for (int u = 0; u < 4; u++) { float dd = v[u] - mean; s2 += dd * dd; }
    red[tid] = s2;
    __syncthreads();
    for (int off = 128; off > 0; off >>= 1) {
        if (tid < off) red[tid] += red[tid + off];
        __syncthreads();
    }
    float var = red[0] * (1.f / D_);
    float inv = rsqrtf(var + 1e-5f);

    #pragma unroll
    for (int u = 0; u < 4; u++) {
        int d = tid + u * 256;
        float t = (v[u] - mean) * inv * sc[d] + bi[d];
        g_x[base + d] = t;
        __nv_bfloat16 hh = __float2bfloat16(t);
        g_xh[base + d] = hh;
        g_xl[base + d] = __float2bfloat16(t - __bfloat162float(hh));
    }
}

// ---------------------------------------------------------------------------
// out[b] = dot(x[b, 0, :], out_w)
// ---------------------------------------------------------------------------
__global__ __launch_bounds__(256) void final_kernel(const float* __restrict__ ow,
                                                    float* __restrict__ out) {
    int b = blockIdx.x;
    __shared__ float red[256];
    const float* xr = &g_x[(size_t)(b * L_) * D_];
    int tid = threadIdx.x;
    float s = 0.f;
    for (int d = tid; d < D_; d += 256) s += xr[d] * ow[d];
    red[tid] = s;
    __syncthreads();
    for (int off = 128; off > 0; off >>= 1) {
        if (tid < off) red[tid] += red[tid + off];
        __syncthreads();
    }
    if (tid == 0) out[b] = red[0];
}

// ---------------------------------------------------------------------------
// Launch
// ---------------------------------------------------------------------------
extern "C" void kernel_launch(void* const* d_in, const int* in_sizes, int n_in,
                              void* d_out, int out_size) {
    const float* text   = (const float*)d_in[0];
    const float* speech = (const float*)d_in[1];
    const void*  tmask  = d_in[2];
    const void*  smask  = d_in[3];
    const float* cls    = (const float*)d_in[4];
    const float* sep    = (const float*)d_in[5];
    const float* Wq     = (const float*)d_in[6];
    const float* bq     = (const float*)d_in[7];
    const float* Wk     = (const float*)d_in[8];
    const float* bk     = (const float*)d_in[9];
    const float* Wv     = (const float*)d_in[10];
    const float* bv     = (const float*)d_in[11];
    const float* Wo     = (const float*)d_in[12];
    const float* bo     = (const float*)d_in[13];
    const float* ln1s   = (const float*)d_in[14];
    const float* ln1b   = (const float*)d_in[15];
    const float* f1w    = (const float*)d_in[16];
    const float* f1b    = (const float*)d_in[17];
    const float* f2w    = (const float*)d_in[18];
    const float* f2b    = (const float*)d_in[19];
    const float* ln2s   = (const float*)d_in[20];
    const float* ln2b   = (const float*)d_in[21];
    const float* outw   = (const float*)d_in[22];
    float* out = (float*)d_out;

    float* y;
    __nv_bfloat16 *xh, *xl, *qh, *ql, *kh, *kl, *vth, *vtl, *ath, *atl, *hh, *hl;
    __nv_bfloat16 *Wqh, *Wql, *Wkh, *Wkl, *Wvh, *Wvl, *Woh, *Wol, *F1h, *F1l, *F2h, *F2l;
    cudaGetSymbolAddress((void**)&y,   g_y);
    cudaGetSymbolAddress((void**)&xh,  g_xh);
    cudaGetSymbolAddress((void**)&xl,  g_xl);
    cudaGetSymbolAddress((void**)&qh,  g_qh);
    cudaGetSymbolAddress((void**)&ql,  g_ql);
    cudaGetSymbolAddress((void**)&kh,  g_kh);
    cudaGetSymbolAddress((void**)&kl,  g_kl);
    cudaGetSymbolAddress((void**)&vth, g_vth);
    cudaGetSymbolAddress((void**)&vtl, g_vtl);
    cudaGetSymbolAddress((void**)&ath, g_ath);
    cudaGetSymbolAddress((void**)&atl, g_atl);
    cudaGetSymbolAddress((void**)&hh,  g_hh);
    cudaGetSymbolAddress((void**)&hl,  g_hl);
    cudaGetSymbolAddress((void**)&Wqh, g_Wqh);
    cudaGetSymbolAddress((void**)&Wql, g_Wql);
    cudaGetSymbolAddress((void**)&Wkh, g_Wkh);
    cudaGetSymbolAddress((void**)&Wkl, g_Wkl);
    cudaGetSymbolAddress((void**)&Wvh, g_Wvh);
    cudaGetSymbolAddress((void**)&Wvl, g_Wvl);
    cudaGetSymbolAddress((void**)&Woh, g_Woh);
    cudaGetSymbolAddress((void**)&Wol, g_Wol);
    cudaGetSymbolAddress((void**)&F1h, g_F1h);
    cudaGetSymbolAddress((void**)&F1l, g_F1l);
    cudaGetSymbolAddress((void**)&F2h, g_F2h);
    cudaGetSymbolAddress((void**)&F2l, g_F2l);

    cudaFuncSetAttribute(attn_mma_kernel,
                         cudaFuncAttributeMaxDynamicSharedMemorySize, ATT_SMEM);
    cudaFuncSetAttribute(gemm_mma<0, 0>,
                         cudaFuncAttributeMaxDynamicSharedMemorySize, GEMM_SMEM);
    cudaFuncSetAttribute(gemm_mma<0, 1>,
                         cudaFuncAttributeMaxDynamicSharedMemorySize, GEMM_SMEM);
    cudaFuncSetAttribute(gemm_mma<0, 2>,
                         cudaFuncAttributeMaxDynamicSharedMemorySize, GEMM_SMEM);
    cudaFuncSetAttribute(gemm_mma<1, 1>,
                         cudaFuncAttributeMaxDynamicSharedMemorySize, GEMM_SMEM);

    lengths_kernel<<<2, 256>>>(tmask, smask);
    build_x_kernel<<<dim3(L_, B_), 256>>>(text, speech, cls, sep);

    dim3 tb(32, 8);
    for (int l = 0; l < NL_; l++) {
        size_t od = (size_t)l * D_ * D_;
        size_t o1 = (size_t)l * D_ * F_;
        size_t o2 = (size_t)l * F_ * D_;
        wsplit_kernel<<<dim3(D_ / 32, D_ / 32), tb>>>(Wq + od, Wqh + od, Wql + od, D_, D_);
        wsplit_kernel<<<dim3(D_ / 32, D_ / 32), tb>>>(Wk + od, Wkh + od, Wkl + od, D_, D_);
        wsplit_kernel<<<dim3(D_ / 32, D_ / 32), tb>>>(Wv + od, Wvh + od, Wvl + od, D_, D_);
        wsplit_kernel<<<dim3(D_ / 32, D_ / 32), tb>>>(Wo + od, Woh + od, Wol + od, D_, D_);
        wsplit_kernel<<<dim3(F_ / 32, D_ / 32), tb>>>(f1w + o1, F1h + o1, F1l + o1, D_, F_);
        wsplit_kernel<<<dim3(D_ / 32, F_ / 32), tb>>>(f2w + o2, F2h + o2, F2l + o2, F_, D_);
    }

    int mt = (M_ + 127) / 128;  // 81
    dim3 gD(D_ / 128, mt);
    dim3 gF(F_ / 128, mt);
    dim3 gAtt((L_ + 63) / 64, H_, B_);

    for (int l = 0; l < NL_; l++) {
        size_t od = (size_t)l * D_ * D_;
        size_t o1 = (size_t)l * D_ * F_;
        size_t o2 = (size_t)l * F_ * D_;
        gemm_mma<0, 1><<<gD, 512, GEMM_SMEM>>>(xh, xl, Wqh + od, Wql + od, bq + l * D_,
                                               nullptr, qh, ql, M_, D_, D_);
        gemm_mma<0, 1><<<gD, 512, GEMM_SMEM>>>(xh, xl, Wkh + od, Wkl + od, bk + l * D_,
                                               nullptr, kh, kl, M_, D_, D_);
        gemm_mma<0, 2><<<gD, 512, GEMM_SMEM>>>(xh, xl, Wvh + od, Wvl + od, bv + l * D_,
                                               nullptr, vth, vtl, M_, D_, D_);
        attn_mma_kernel<<<gAtt, 128, ATT_SMEM>>>();
        gemm_mma<0, 0><<<gD, 512, GEMM_SMEM>>>(ath, atl, Woh + od, Wol + od, bo + l * D_,
                                               y, nullptr, nullptr, M_, D_, D_);
        add_ln_kernel<<<M_, 256>>>(ln1s + l * D_, ln1b + l * D_);
        gemm_mma<1, 1><<<gF, 512, GEMM_SMEM>>>(xh, xl, F1h + o1, F1l + o1, f1b + l * F_,
                                               nullptr, hh, hl, M_, F_, D_);
        gemm_mma<0, 0><<<gD, 512, GEMM_SMEM>>>(hh, hl, F2h + o2, F2l + o2, f2b + l * D_,
                                               y, nullptr, nullptr, M_, D_, F_);
        add_ln_kernel<<<M_, 256>>>(ln2s + l * D_, ln2b + l * D_);
    }
    final_kernel<<<B_, 256>>>(outw, out);
}

// round 12
// speedup vs baseline: 3.8777x; 1.2362x over previous
#include <cuda_runtime.h>
#include <cuda_bf16.h>
#include <math.h>
#include <stdint.h>

// ---------------------------------------------------------------------------
// Problem constants
// ---------------------------------------------------------------------------
namespace {
constexpr int B_  = 16;
constexpr int TT_ = 128;
constexpr int TS_ = 512;
constexpr int L_  = TT_ + TS_ + 2;   // 642
constexpr int LT_ = 648;             // vt row stride: multiple of 8 elems (16B)
constexpr int D_  = 1024;
constexpr int H_  = 16;
constexpr int HD_ = 64;
constexpr int F_  = 4096;
constexpr int NL_ = 4;
constexpr int M_  = B_ * L_;         // 10272
constexpr int QKS_ = 2048;           // fused q|k buffer row stride

// GEMM tiling
constexpr int BK_     = 32;
constexpr int STAGES_ = 3;
constexpr int LDS_    = 40;                    // padded row stride (elements)
constexpr int ASZ_    = 128 * LDS_ * 2;        // 10240 bytes per tile array
constexpr int STAGE_B = 4 * ASZ_;              // 40960 bytes per stage
constexpr int GEMM_SMEM = STAGES_ * STAGE_B + 1024;  // 123904

// Attention tiling
constexpr int ATS      = 72;                   // smem row stride (elements)
constexpr int AT_TILE  = 64 * ATS * 2;         // 9216 bytes per 64x64 bf16 array
constexpr int ATT_ST0  = 2 * AT_TILE;          // Qh, Ql
constexpr int ATT_STG  = 4 * AT_TILE;          // Kh, Kl, Vth, Vtl per stage
constexpr int ATT_SMEM = ATT_ST0 + 2 * ATT_STG; // 92160

// fused wsplit decode
constexpr int WT_PER_LAYER = 4 * 1024 + 4096 + 4096;  // 12288 tiles/layer
}

// ---------------------------------------------------------------------------
// Scratch (allocation-free: __device__ globals; zero-initialized)
// ---------------------------------------------------------------------------
__device__ float g_x[(size_t)M_ * D_];
__device__ float g_y[(size_t)M_ * D_];
__device__ __nv_bfloat16 g_xh [(size_t)M_ * D_];
__device__ __nv_bfloat16 g_xl [(size_t)M_ * D_];
__device__ __nv_bfloat16 g_qkh[(size_t)M_ * QKS_];
__device__ __nv_bfloat16 g_qkl[(size_t)M_ * QKS_];
__device__ __nv_bfloat16 g_vth[(size_t)B_ * D_ * LT_ + 64];
__device__ __nv_bfloat16 g_vtl[(size_t)B_ * D_ * LT_ + 64];
__device__ __nv_bfloat16 g_ath[(size_t)M_ * D_];
__device__ __nv_bfloat16 g_atl[(size_t)M_ * D_];
__device__ __nv_bfloat16 g_hh [(size_t)M_ * F_];
__device__ __nv_bfloat16 g_hl [(size_t)M_ * F_];
// transposed + hi/lo-split weights ([N,K] layout); QKV concatenated (N=3072)
__device__ __nv_bfloat16 g_Wqkvh[(size_t)NL_ * 3072 * 1024];
__device__ __nv_bfloat16 g_Wqkvl[(size_t)NL_ * 3072 * 1024];
__device__ __nv_bfloat16 g_Woh[(size_t)NL_ * D_ * D_];
__device__ __nv_bfloat16 g_Wol[(size_t)NL_ * D_ * D_];
__device__ __nv_bfloat16 g_F1h[(size_t)NL_ * D_ * F_];
__device__ __nv_bfloat16 g_F1l[(size_t)NL_ * D_ * F_];
__device__ __nv_bfloat16 g_F2h[(size_t)NL_ * F_ * D_];
__device__ __nv_bfloat16 g_F2l[(size_t)NL_ * F_ * D_];
__device__ int g_tlen[B_];
__device__ int g_slen[B_];
__device__ int g_cum[B_ + 1];
__device__ int g_rowb[M_];        // batch index of each compact row

// ---------------------------------------------------------------------------
// PTX helpers (sm_80-era subset only: cp.async, ldmatrix, mma.sync)
// ---------------------------------------------------------------------------
__device__ __forceinline__ uint32_t s2u(const void* p) {
    uint32_t a;
    asm("{ .reg .u64 t; cvta.to.shared.u64 t, %1; cvt.u32.u64 %0, t; }"
        : "=r"(a) : "l"(p));
    return a;
}
__device__ __forceinline__ void cp16(uint32_t s, const void* g, int nbytes) {
    asm volatile("cp.async.cg.shared.global [%0], [%1], 16, %2;"
                 :: "r"(s), "l"(g), "r"(nbytes));
}
__device__ __forceinline__ void cp_commit() {
    asm volatile("cp.async.commit_group;");
}
template <int N> __device__ __forceinline__ void cp_wait() {
    asm volatile("cp.async.wait_group %0;" :: "n"(N));
}
__device__ __forceinline__ void ldsm4(uint32_t* r, uint32_t addr) {
    asm volatile("ldmatrix.sync.aligned.m8n8.x4.shared.b16 {%0,%1,%2,%3}, [%4];"
                 : "=r"(r[0]), "=r"(r[1]), "=r"(r[2]), "=r"(r[3]) : "r"(addr));
}
__device__ __forceinline__ void mma16816(float* c, const uint32_t* a,
                                         uint32_t b0, uint32_t b1) {
    asm volatile(
        "mma.sync.aligned.m16n8k16.row.col.f32.bf16.bf16.f32 "
        "{%0,%1,%2,%3}, {%4,%5,%6,%7}, {%8,%9}, {%0,%1,%2,%3};\n"
        : "+f"(c[0]), "+f"(c[1]), "+f"(c[2]), "+f"(c[3])
        : "r"(a[0]), "r"(a[1]), "r"(a[2]), "r"(a[3]), "r"(b0), "r"(b1));
}
// split two fp32 into packed bf16x2 hi and lo words
__device__ __forceinline__ void packsplit(float x, float y,
                                          uint32_t& hi, uint32_t& lo) {
    __nv_bfloat16 hx = __float2bfloat16(x), hy = __float2bfloat16(y);
    __nv_bfloat162 hh = __halves2bfloat162(hx, hy);
    __nv_bfloat162 ll = __halves2bfloat162(
        __float2bfloat16(x - __bfloat162float(hx)),
        __float2bfloat16(y - __bfloat162float(hy)));
    hi = *(uint32_t*)&hh;
    lo = *(uint32_t*)&ll;
}

// ---------------------------------------------------------------------------
// Mask length computation with on-device dtype detection
// ---------------------------------------------------------------------------
__global__ void lengths_kernel(const void* tmask, const void* smask) {
    int which = blockIdx.x;
    const void* mask = which ? smask : tmask;
    int T = which ? TS_ : TT_;
    int* lens = which ? g_slen : g_tlen;
    int N = B_ * T;

    __shared__ int f3F, fMis;
    __shared__ int cnt[B_];
    int tid = threadIdx.x;
    if (tid == 0) { f3F = 0; fMis = 0; }
    if (tid < B_) cnt[tid] = 0;
    __syncthreads();

    const unsigned char* bytes = (const unsigned char*)mask;
    int l3 = 0, lm = 0;
    for (int i = tid; i < N; i += blockDim.x) {
        unsigned char c = bytes[i];
        if (c == 0x3F) l3 = 1;
        if (c == 1 && (i & 3)) lm = 1;
    }
    if (l3) atomicOr(&f3F, 1);
    if (lm) atomicOr(&fMis, 1);
    __syncthreads();

    if (fMis && !f3F) {
        for (int i = tid; i < N; i += blockDim.x)
            if (bytes[i] == 0) atomicAdd(&cnt[i / T], 1);
    } else {
        const unsigned int* w = (const unsigned int*)mask;
        for (int i = tid; i < N; i += blockDim.x)
            if (w[i] == 0u) atomicAdd(&cnt[i / T], 1);
    }
    __syncthreads();
    if (tid < B_) lens[tid] = cnt[tid];
}

// prefix sums of valid lengths
__global__ void cum_kernel() {
    if (threadIdx.x == 0) {
        int a = 0;
        for (int b = 0; b < B_; b++) {
            g_cum[b] = a;
            a += 2 + g_tlen[b] + g_slen[b];
        }
        g_cum[B_] = a;
    }
}

// ---------------------------------------------------------------------------
// Build COMPACT concatenated sequence x (fp32 + bf16 hi/lo) + row->batch map
// ---------------------------------------------------------------------------
__global__ void build_x_kernel(const float* __restrict__ text,
                               const float* __restrict__ speech,
                               const float* __restrict__ cls,
                               const float* __restrict__ sep) {
    int pos = blockIdx.x, b = blockIdx.y;
    int tl = g_tlen[b], sl = g_slen[b];
    if (pos >= 2 + tl + sl) return;
    int row = g_cum[b] + pos;
    size_t base = (size_t)row * D_;
    if (threadIdx.x == 0) g_rowb[row] = b;

    const float* s;
    if (pos == 0)                 s = cls;
    else if (pos < 1 + tl)        s = &text  [((size_t)(pos - 1) * B_ + b) * D_];
    else if (pos == 1 + tl)       s = sep;
    else                          s = &speech[((size_t)(pos - 2 - tl) * B_ + b) * D_];

    for (int d = threadIdx.x; d < D_; d += blockDim.x) {
        float v = s[d];
        g_x[base + d] = v;
        __nv_bfloat16 h = __float2bfloat16(v);
        g_xh[base + d] = h;
        g_xl[base + d] = __float2bfloat16(v - __bfloat162float(h));
    }
}

// ---------------------------------------------------------------------------
// Fused weight transpose + hi/lo split for ALL weights (one launch).
// tile decode: per layer 12288 tiles: [0,4096) q/k/v/o (1024 each, KxN=1024x1024),
// [4096,8192) fc1 (K=1024,N=4096), [8192,12288) fc2 (K=4096,N=1024).
// ---------------------------------------------------------------------------
__global__ void wsplit_all_kernel(const float* __restrict__ Wq,
                                  const float* __restrict__ Wk,
                                  const float* __restrict__ Wv,
                                  const float* __restrict__ Wo,
                                  const float* __restrict__ F1,
                                  const float* __restrict__ F2) {
    int gidx = blockIdx.x;
    int l = gidx / WT_PER_LAYER;
    int r = gidx - l * WT_PER_LAYER;

    const float* W;
    __nv_bfloat16 *Th, *Tl;
    int K, N, tile;
    if (r < 4096) {
        int type = r >> 10;           // 0=q 1=k 2=v 3=o
        tile = r & 1023;
        K = 1024; N = 1024;
        size_t wofs = (size_t)l * D_ * D_;
        if (type == 0)      { W = Wq + wofs; }
        else if (type == 1) { W = Wk + wofs; }
        else if (type == 2) { W = Wv + wofs; }
        else                { W = Wo + wofs; }
        if (type < 3) {
            size_t dofs = (size_t)l * 3072 * 1024 + (size_t)type * 1024 * 1024;
            Th = g_Wqkvh + dofs; Tl = g_Wqkvl + dofs;
        } else {
            size_t dofs = (size_t)l * D_ * D_;
            Th = g_Woh + dofs; Tl = g_Wol + dofs;
        }
    } else if (r < 8192) {
        tile = r - 4096;
        K = 1024; N = 4096;
        W = F1 + (size_t)l * D_ * F_;
        Th = g_F1h + (size_t)l * D_ * F_;
        Tl = g_F1l + (size_t)l * D_ * F_;
    } else {
        tile = r - 8192;
        K = 4096; N = 1024;
        W = F2 + (size_t)l * F_ * D_;
        Th = g_F2h + (size_t)l * F_ * D_;
        Tl = g_F2l + (size_t)l * F_ * D_;
    }

    int ntiles = N >> 5;
    int n0 = (tile % ntiles) * 32;
    int k0 = (tile / ntiles) * 32;

    __shared__ float t[32][33];
    int tx = threadIdx.x, ty = threadIdx.y;
    #pragma unroll
    for (int j = 0; j < 4; j++) {
        int k = k0 + ty + j * 8;
        t[ty + j * 8][tx] = W[(size_t)k * N + n0 + tx];
    }
    __syncthreads();
    #pragma unroll
    for (int j = 0; j < 4; j++) {
        int n = n0 + ty + j * 8;
        float v = t[tx][ty + j * 8];
        __nv_bfloat16 h = __float2bfloat16(v);
        Th[(size_t)n * K + k0 + tx] = h;
        Tl[(size_t)n * K + k0 + tx] = __float2bfloat16(v - __bfloat162float(h));
    }
}

// ---------------------------------------------------------------------------
// HMMA bf16 GEMM with 3-term hi/lo compensation on COMPACT rows (M = g_cum[B]).
// 128x128x32 CTA tile, 512 threads (16 warps, 4x4), 3-stage cp.async pipeline.
// MODE 0: fp32 C.  MODE 1: bf16 hi/lo C (after optional RELU), stride Nn.
// MODE 3: fused QKV epilogue: n<2048 -> qk buffer (stride 2048);
//         n>=2048 -> V transposed per batch: vt[(b*D + n-2048)*LT + pos].
// ---------------------------------------------------------------------------
template <int RELU, int MODE>
__global__ __launch_bounds__(512, 1) void gemm_mma(
    const __nv_bfloat16* __restrict__ Ah, const __nv_bfloat16* __restrict__ Al,
    const __nv_bfloat16* __restrict__ Bh, const __nv_bfloat16* __restrict__ Bl,
    const float* __restrict__ bias, const float* __restrict__ bias2,
    const float* __restrict__ bias3,
    float* __restrict__ Cf,
    __nv_bfloat16* __restrict__ Ch, __nv_bfloat16* __restrict__ Cl,
    __nv_bfloat16* __restrict__ Ch2, __nv_bfloat16* __restrict__ Cl2,
    int Nn, int Kn) {
    extern __shared__ char dynsmem[];
    uint32_t sbase = (s2u(dynsmem) + 1023u) & ~1023u;
    int tid = threadIdx.x;
    int wid = tid >> 5, lane = tid & 31;
    int m0 = blockIdx.y * 128, n0 = blockIdx.x * 128;
    const int Mc = g_cum[B_];
    if (m0 >= Mc) return;   // fully-pad tile (compact rows)

    int wm = wid & 3, wn = wid >> 2;     // 4x4 warp grid
    int m0w = wm * 32, n0w = wn * 32;
    const int T = Kn / BK_;

    int la = tid >> 7;        // 0..3 -> Ah, Al, Bh, Bl
    int t7 = tid & 127;

    auto issue = [&](int kt) {
        uint32_t stb = sbase + (kt % STAGES_) * STAGE_B + la * ASZ_;
        #pragma unroll
        for (int i = 0; i < 4; i++) {
            int chunk = t7 + 128 * i;         // 0..511
            int row = chunk >> 2;             // 0..127
            int col = chunk & 3;              // 16B chunk within 64B row
            uint32_t dst = stb + (uint32_t)(row * LDS_ + col * 8) * 2;
            if (la < 2) {
                int gr = m0 + row;
                bool v = gr < Mc;
                const __nv_bfloat16* src =
                    (la ? Al : Ah) + (size_t)(v ? gr : 0) * Kn + kt * BK_ + col * 8;
                cp16(dst, src, v ? 16 : 0);
            } else {
                const __nv_bfloat16* src =
                    (la == 2 ? Bh : Bl) + (size_t)(n0 + row) * Kn + kt * BK_ + col * 8;
                cp16(dst, src, 16);
            }
        }
        cp_commit();
    };

    issue(0);
    issue(1);

    float acc[2][4][4];
    #pragma unroll
    for (int i = 0; i < 2; i++)
        #pragma unroll
        for (int j = 0; j < 4; j++)
            #pragma unroll
            for (int p = 0; p < 4; p++) acc[i][j][p] = 0.f;

    int lr = lane & 15, lc8 = (lane >> 4) * 8;

    for (int kt = 0; kt < T; kt++) {
        cp_wait<STAGES_ - 2>();
        __syncthreads();
        uint32_t stb = sbase + (kt % STAGES_) * STAGE_B;
        #pragma unroll
        for (int kk = 0; kk < 2; kk++) {
            int koff = kk * 16 + lc8;
            uint32_t ah[2][4], al[2][4], bh[2][4], bl[2][4];
            #pragma unroll
            for (int im = 0; im < 2; im++) {
                uint32_t ad = stb + (uint32_t)((m0w + im * 16 + lr) * LDS_ + koff) * 2;
                ldsm4(ah[im], ad);
                ldsm4(al[im], ad + ASZ_);
            }
            #pragma unroll
            for (int ib = 0; ib < 2; ib++) {
                uint32_t bd = stb + 2 * ASZ_ +
                              (uint32_t)((n0w + ib * 16 + lr) * LDS_ + koff) * 2;
                ldsm4(bh[ib], bd);
                ldsm4(bl[ib], bd + ASZ_);
            }
            #pragma unroll
            for (int im = 0; im < 2; im++)
                #pragma unroll
                for (int in = 0; in < 4; in++) {
                    int ib = in >> 1, sb = in & 1;
                    mma16816(acc[im][in], ah[im], bh[ib][sb], bh[ib][sb + 2]);
                    mma16816(acc[im][in], ah[im], bl[ib][sb], bl[ib][sb + 2]);
                    mma16816(acc[im][in], al[im], bh[ib][sb], bh[ib][sb + 2]);
                }
        }
        int nt = kt + STAGES_ - 1;
        if (nt < T) issue(nt); else cp_commit();
    }

    // Epilogue
    int g = lane >> 2, tq = lane & 3;
    #pragma unroll
    for (int in = 0; in < 4; in++) {
        int cb = n0 + n0w + in * 8 + tq * 2;
        float b0, b1;
        int section = cb >> 10;   // only meaningful for MODE 3
        if (MODE == 3) {
            const float* bp = (section == 0) ? bias : (section == 1) ? bias2 : bias3;
            b0 = __ldg(&bp[cb & 1023]);
            b1 = __ldg(&bp[(cb & 1023) + 1]);
        } else {
            b0 = __ldg(&bias[cb]);
            b1 = __ldg(&bias[cb + 1]);
        }
        #pragma unroll
        for (int im = 0; im < 2; im++) {
            #pragma unroll
            for (int hrow = 0; hrow < 2; hrow++) {
                int m = m0 + m0w + im * 16 + g + hrow * 8;
                if (m < Mc) {
                    float v0 = acc[im][in][hrow * 2 + 0] + b0;
                    float v1 = acc[im][in][hrow * 2 + 1] + b1;
                    if (RELU) { v0 = fmaxf(v0, 0.f); v1 = fmaxf(v1, 0.f); }
                    if (MODE == 0) {
                        *(float2*)&Cf[(size_t)m * Nn + cb] = make_float2(v0, v1);
                    } else if (MODE == 1) {
                        uint32_t hw, lw;
                        packsplit(v0, v1, hw, lw);
                        *(uint32_t*)&Ch[(size_t)m * Nn + cb] = hw;
                        *(uint32_t*)&Cl[(size_t)m * Nn + cb] = lw;
                    } else {  // MODE 3
                        if (section < 2) {
                            uint32_t hw, lw;
                            packsplit(v0, v1, hw, lw);
                            *(uint32_t*)&Ch[(size_t)m * QKS_ + cb] = hw;
                            *(uint32_t*)&Cl[(size_t)m * QKS_ + cb] = lw;
                        } else {
                            int bb = g_rowb[m];
                            int pos = m - g_cum[bb];
                            int nn = cb & 1023;
                            size_t vt0 = ((size_t)bb * D_ + nn) * LT_ + pos;
                            __nv_bfloat16 h0 = __float2bfloat16(v0);
                            __nv_bfloat16 h1 = __float2bfloat16(v1);
                            Ch2[vt0]       = h0;
                            Ch2[vt0 + LT_] = h1;
                            Cl2[vt0]       = __float2bfloat16(v0 - __bfloat162float(h0));
                            Cl2[vt0 + LT_] = __float2bfloat16(v1 - __bfloat162float(h1));
                        }
                    }
                }
            }
        }
    }
}

// ---------------------------------------------------------------------------
// HMMA flash attention with 3-term hi/lo compensation (compact rows).
// Block: (q-tile 64, head, batch), 128 threads.
// Q/K from g_qkh/l (stride 2048; k at col offset 1024); V from g_vth/l.
// ---------------------------------------------------------------------------
__global__ __launch_bounds__(128, 1) void attn_mma_kernel() {
    extern __shared__ char asmem[];
    uint32_t sb = s2u(asmem);
    int tid = threadIdx.x, lane = tid & 31, w = tid >> 5;
    int qt = blockIdx.x, h = blockIdx.y, b = blockIdx.z;
    int q0 = qt * 64;
    int Lv = 2 + g_tlen[b] + g_slen[b];
    if (q0 >= Lv) return;
    int cumb = g_cum[b];
    const int NKT = (Lv + 63) >> 6;

    int lr = lane & 15, lc8 = (lane >> 4) * 8;
    int r = lane >> 2, tq = lane & 3;
    int lrow = tid >> 1, lhf = tid & 1;   // smem-fill: row, col-half

    // ---- stage Q (hi/lo) ----
    {
        int qrow = q0 + lrow; if (qrow > Lv - 1) qrow = Lv - 1;
        size_t off = (size_t)(cumb + qrow) * QKS_ + h * HD_ + lhf * 32;
        uint32_t dst = sb + (uint32_t)(lrow * ATS + lhf * 32) * 2;
        #pragma unroll
        for (int u = 0; u < 4; u++) {
            cp16(dst + u * 16,           g_qkh + off + u * 8, 16);
            cp16(dst + AT_TILE + u * 16, g_qkl + off + u * 8, 16);
        }
        cp_commit();
    }

    auto loadKV = [&](int kt) {
        uint32_t base = sb + ATT_ST0 + (kt & 1) * ATT_STG;
        int k0 = kt * 64;
        int krow = k0 + lrow; if (krow > Lv - 1) krow = Lv - 1;
        size_t koff = (size_t)(cumb + krow) * QKS_ + 1024 + h * HD_ + lhf * 32;
        uint32_t kdst = base + (uint32_t)(lrow * ATS + lhf * 32) * 2;
        #pragma unroll
        for (int u = 0; u < 4; u++) {
            cp16(kdst + u * 16,           g_qkh + koff + u * 8, 16);
            cp16(kdst + AT_TILE + u * 16, g_qkl + koff + u * 8, 16);
        }
        // V: row stride LT_ (16B-aligned); cols >= Lv are stale/zero but P=0.
        size_t voff = ((size_t)b * D_ + h * HD_ + lrow) * LT_ + k0 + lhf * 32;
        uint32_t vdst = base + 2 * AT_TILE + (uint32_t)(lrow * ATS + lhf * 32) * 2;
        #pragma unroll
        for (int u = 0; u < 4; u++) {
            int col = k0 + lhf * 32 + u * 8;
            int nb = (col < LT_) ? 16 : 0;   // zfill past padded length
            cp16(vdst + u * 16,           g_vth + voff + u * 8, nb);
            cp16(vdst + AT_TILE + u * 16, g_vtl + voff + u * 8, nb);
        }
        cp_commit();
    };

    loadKV(0);
    cp_wait<1>();           // Q staged (KV0 may still be in flight)
    __syncthreads();

    // Q fragments (held in registers for the whole kernel)
    uint32_t qfh[4][4], qfl[4][4];
    #pragma unroll
    for (int c = 0; c < 4; c++) {
        uint32_t ad = sb + (uint32_t)((w * 16 + lr) * ATS + c * 16 + lc8) * 2;
        ldsm4(qfh[c], ad);
        ldsm4(qfl[c], ad + AT_TILE);
    }

    float o[8][4];
    #pragma unroll
    for (int j = 0; j < 8; j++)
        #pragma unroll
        for (int p = 0; p < 4; p++) o[j][p] = 0.f;
    float mrA = -1e30f, mrB = -1e30f, lsA = 0.f, lsB = 0.f;

    for (int kt = 0; kt < NKT; kt++) {
        if (kt + 1 < NKT) { loadKV(kt + 1); cp_wait<1>(); }
        else              { cp_wait<0>(); }
        __syncthreads();
        uint32_t base = sb + ATT_ST0 + (kt & 1) * ATT_STG;
        int k0 = kt * 64;

        // ---- S = Q K^T (3-term) ----
        float s[8][4];
        #pragma unroll
        for (int j = 0; j < 8; j++)
            #pragma unroll
            for (int p = 0; p < 4; p++) s[j][p] = 0.f;

        #pragma unroll
        for (int c = 0; c < 4; c++) {
            #pragma unroll
            for (int ib = 0; ib < 4; ib++) {
                uint32_t bd = base + (uint32_t)((ib * 16 + lr) * ATS + c * 16 + lc8) * 2;
                uint32_t kbh[4], kbl[4];
                ldsm4(kbh, bd);
                ldsm4(kbl, bd + AT_TILE);
                #pragma unroll
                for (int sbn = 0; sbn < 2; sbn++) {
                    int j = ib * 2 + sbn;
                    mma16816(s[j], qfh[c], kbh[sbn], kbh[sbn + 2]);
                    mma16816(s[j], qfh[c], kbl[sbn], kbl[sbn + 2]);
                    mma16816(s[j], qfl[c], kbh[sbn], kbh[sbn + 2]);
                }
            }
        }

        // ---- scale + mask ----
        #pragma unroll
        for (int j = 0; j < 8; j++) {
            int c0 = k0 + j * 8 + 2 * tq, c1 = c0 + 1;
            s[j][0] = (c0 < Lv) ? s[j][0] * 0.125f : -1e9f;
            s[j][1] = (c1 < Lv) ? s[j][1] * 0.125f : -1e9f;
            s[j][2] = (c0 < Lv) ? s[j][2] * 0.125f : -1e9f;
            s[j][3] = (c1 < Lv) ? s[j][3] * 0.125f : -1e9f;
        }

        // ---- online softmax (rows r and r+8) ----
        float mA = -1e30f, mB = -1e30f;
        #pragma unroll
        for (int j = 0; j < 8; j++) {
            mA = fmaxf(mA, fmaxf(s[j][0], s[j][1]));
            mB = fmaxf(mB, fmaxf(s[j][2], s[j][3]));
        }
        mA = fmaxf(mA, __shfl_xor_sync(0xffffffffu, mA, 1));
        mA = fmaxf(mA, __shfl_xor_sync(0xffffffffu, mA, 2));
        mB = fmaxf(mB, __shfl_xor_sync(0xffffffffu, mB, 1));
        mB = fmaxf(mB, __shfl_xor_sync(0xffffffffu, mB, 2));
        float mnA = fmaxf(mrA, mA), mnB = fmaxf(mrB, mB);
        float aA = expf(mrA - mnA), aB = expf(mrB - mnB);
        float rsA = 0.f, rsB = 0.f;
        #pragma unroll
        for (int j = 0; j < 8; j++) {
            s[j][0] = expf(s[j][0] - mnA);
            s[j][1] = expf(s[j][1] - mnA);
            s[j][2] = expf(s[j][2] - mnB);
            s[j][3] = expf(s[j][3] - mnB);
            rsA += s[j][0] + s[j][1];
            rsB += s[j][2] + s[j][3];
        }
        rsA += __shfl_xor_sync(0xffffffffu, rsA, 1);
        rsA += __shfl_xor_sync(0xffffffffu, rsA, 2);
        rsB += __shfl_xor_sync(0xffffffffu, rsB, 1);
        rsB += __shfl_xor_sync(0xffffffffu, rsB, 2);
        lsA = lsA * aA + rsA;
        lsB = lsB * aB + rsB;
        mrA = mnA; mrB = mnB;
        #pragma unroll
        for (int j = 0; j < 8; j++) {
            o[j][0] *= aA; o[j][1] *= aA;
            o[j][2] *= aB; o[j][3] *= aB;
        }

        // ---- O += P V (3-term) ----
        #pragma unroll
        for (int c = 0; c < 4; c++) {
            uint32_t pah[4], pal[4];
            packsplit(s[2 * c][0],     s[2 * c][1],     pah[0], pal[0]);
            packsplit(s[2 * c][2],     s[2 * c][3],     pah[1], pal[1]);
            packsplit(s[2 * c + 1][0], s[2 * c + 1][1], pah[2], pal[2]);
            packsplit(s[2 * c + 1][2], s[2 * c + 1][3], pah[3], pal[3]);
            #pragma unroll
            for (int ib = 0; ib < 4; ib++) {
                uint32_t bd = base + 2 * AT_TILE +
                              (uint32_t)((ib * 16 + lr) * ATS + c * 16 + lc8) * 2;
                uint32_t vbh[4], vbl[4];
                ldsm4(vbh, bd);
                ldsm4(vbl, bd + AT_TILE);
                #pragma unroll
                for (int sbn = 0; sbn < 2; sbn++) {
                    int j = ib * 2 + sbn;
                    mma16816(o[j], pah, vbh[sbn], vbh[sbn + 2]);
                    mma16816(o[j], pal, vbh[sbn], vbh[sbn + 2]);
                    mma16816(o[j], pah, vbl[sbn], vbl[sbn + 2]);
                }
            }
        }
        __syncthreads();
    }

    // ---- write O (compact rows, only valid positions) ----
    float iA = 1.f / lsA, iB = 1.f / lsB;
    int qA = q0 + w * 16 + r, qB = qA + 8;
    #pragma unroll
    for (int j = 0; j < 8; j++) {
        int d = h * HD_ + j * 8 + 2 * tq;
        if (qA < Lv) {
            size_t off = (size_t)(cumb + qA) * D_ + d;
            uint32_t hw, lw;
            packsplit(o[j][0] * iA, o[j][1] * iA, hw, lw);
            *(uint32_t*)&g_ath[off] = hw;
            *(uint32_t*)&g_atl[off] = lw;
        }
        if (qB < Lv) {
            size_t off = (size_t)(cumb + qB) * D_ + d;
            uint32_t hw, lw;
            packsplit(o[j][2] * iB, o[j][3] * iB, hw, lw);
            *(uint32_t*)&g_ath[off] = hw;
            *(uint32_t*)&g_atl[off] = lw;
        }
    }
}

// ---------------------------------------------------------------------------
// x = LayerNorm(x + y) * s + b (in place) + bf16 hi/lo emission (compact rows).
// ---------------------------------------------------------------------------
__global__ __launch_bounds__(256) void add_ln_kernel(const float* __restrict__ sc,
                                                     const float* __restrict__ bi) {
    int row = blockIdx.x;
    if (row >= g_cum[B_]) return;
    size_t base = (size_t)row * D_;
    __shared__ float red[256];
    int tid = threadIdx.x;

    float v[4];
    float s = 0.f;
    #pragma unroll
    for (int u = 0; u < 4; u++) {
        int d = tid + u * 256;
        v[u] = g_x[base + d] + g_y[base + d];
        s += v[u];
    }
    red[tid] = s;
    __syncthreads();
    for (int off = 128; off > 0; off >>= 1) {
        if (tid < off) red[tid] += red[tid + off];
        __syncthreads();
    }
    float mean = red[0] * (1.f / D_);
    __syncthreads();

    float s2 = 0.f;
    #pragma unroll
    for (int u = 0; u < 4; u++) { float dd = v[u] - mean; s2 += dd * dd; }
    red[tid] = s2;
    __syncthreads();
    for (int off = 128; off > 0; off >>= 1) {
        if (tid < off) red[tid] += red[tid + off];
        __syncthreads();
    }
    float var = red[0] * (1.f / D_);
    float inv = rsqrtf(var + 1e-5f);

    #pragma unroll
    for (int u = 0; u < 4; u++) {
        int d = tid + u * 256;
        float t = (v[u] - mean) * inv * sc[d] + bi[d];
        g_x[base + d] = t;
        __nv_bfloat16 hh = __float2bfloat16(t);
        g_xh[base + d] = hh;
        g_xl[base + d] = __float2bfloat16(t - __bfloat162float(hh));
    }
}

// ---------------------------------------------------------------------------
// out[b] = dot(x[cum[b], :], out_w)
// ---------------------------------------------------------------------------
__global__ __launch_bounds__(256) void final_kernel(const float* __restrict__ ow,
                                                    float* __restrict__ out) {
    int b = blockIdx.x;
    __shared__ float red[256];
    const float* xr = &g_x[(size_t)g_cum[b] * D_];
    int tid = threadIdx.x;
    float s = 0.f;
    for (int d = tid; d < D_; d += 256) s += xr[d] * ow[d];
    red[tid] = s;
    __syncthreads();
    for (int off = 128; off > 0; off >>= 1) {
        if (tid < off) red[tid] += red[tid + off];
        __syncthreads();
    }
    if (tid == 0) out[b] = red[0];
}

// ---------------------------------------------------------------------------
// Launch
// ---------------------------------------------------------------------------
extern "C" void kernel_launch(void* const* d_in, const int* in_sizes, int n_in,
                              void* d_out, int out_size) {
    const float* text   = (const float*)d_in[0];
    const float* speech = (const float*)d_in[1];
    const void*  tmask  = d_in[2];
    const void*  smask  = d_in[3];
    const float* cls    = (const float*)d_in[4];
    const float* sep    = (const float*)d_in[5];
    const float* Wq     = (const float*)d_in[6];
    const float* bq     = (const float*)d_in[7];
    const float* Wk     = (const float*)d_in[8];
    const float* bk     = (const float*)d_in[9];
    const float* Wv     = (const float*)d_in[10];
    const float* bv     = (const float*)d_in[11];
    const float* Wo     = (const float*)d_in[12];
    const float* bo     = (const float*)d_in[13];
    const float* ln1s   = (const float*)d_in[14];
    const float* ln1b   = (const float*)d_in[15];
    const float* f1w    = (const float*)d_in[16];
    const float* f1b    = (const float*)d_in[17];
    const float* f2w    = (const float*)d_in[18];
    const float* f2b    = (const float*)d_in[19];
    const float* ln2s   = (const float*)d_in[20];
    const float* ln2b   = (const float*)d_in[21];
    const float* outw   = (const float*)d_in[22];
    float* out = (float*)d_out;

    float* y;
    __nv_bfloat16 *xh, *xl, *qkh, *qkl, *vth, *vtl, *ath, *atl, *hh, *hl;
    __nv_bfloat16 *Wqkvh, *Wqkvl, *Woh, *Wol, *F1h, *F1l, *F2h, *F2l;
    cudaGetSymbolAddress((void**)&y,     g_y);
    cudaGetSymbolAddress((void**)&xh,    g_xh);
    cudaGetSymbolAddress((void**)&xl,    g_xl);
    cudaGetSymbolAddress((void**)&qkh,   g_qkh);
    cudaGetSymbolAddress((void**)&qkl,   g_qkl);
    cudaGetSymbolAddress((void**)&vth,   g_vth);
    cudaGetSymbolAddress((void**)&vtl,   g_vtl);
    cudaGetSymbolAddress((void**)&ath,   g_ath);
    cudaGetSymbolAddress((void**)&atl,   g_atl);
    cudaGetSymbolAddress((void**)&hh,    g_hh);
    cudaGetSymbolAddress((void**)&hl,    g_hl);
    cudaGetSymbolAddress((void**)&Wqkvh, g_Wqkvh);
    cudaGetSymbolAddress((void**)&Wqkvl, g_Wqkvl);
    cudaGetSymbolAddress((void**)&Woh,   g_Woh);
    cudaGetSymbolAddress((void**)&Wol,   g_Wol);
    cudaGetSymbolAddress((void**)&F1h,   g_F1h);
    cudaGetSymbolAddress((void**)&F1l,   g_F1l);
    cudaGetSymbolAddress((void**)&F2h,   g_F2h);
    cudaGetSymbolAddress((void**)&F2l,   g_F2l);

    cudaFuncSetAttribute(attn_mma_kernel,
                         cudaFuncAttributeMaxDynamicSharedMemorySize, ATT_SMEM);
    cudaFuncSetAttribute(gemm_mma<0, 0>,
                         cudaFuncAttributeMaxDynamicSharedMemorySize, GEMM_SMEM);
    cudaFuncSetAttribute(gemm_mma<0, 3>,
                         cudaFuncAttributeMaxDynamicSharedMemorySize, GEMM_SMEM);
    cudaFuncSetAttribute(gemm_mma<1, 1>,
                         cudaFuncAttributeMaxDynamicSharedMemorySize, GEMM_SMEM);

    lengths_kernel<<<2, 256>>>(tmask, smask);
    cum_kernel<<<1, 32>>>();
    build_x_kernel<<<dim3(L_, B_), 256>>>(text, speech, cls, sep);
    wsplit_all_kernel<<<NL_ * WT_PER_LAYER, dim3(32, 8)>>>(Wq, Wk, Wv, Wo, f1w, f2w);

    int mt = (M_ + 127) / 128;  // 81 (static; CTAs past Mc self-skip)
    dim3 gQKV(3072 / 128, mt);
    dim3 gD(D_ / 128, mt);
    dim3 gF(F_ / 128, mt);
    dim3 gAtt((L_ + 63) / 64, H_, B_);

    for (int l = 0; l < NL_; l++) {
        size_t oqkv = (size_t)l * 3072 * 1024;
        size_t od = (size_t)l * D_ * D_;
        size_t o1 = (size_t)l * D_ * F_;
        size_t o2 = (size_t)l * F_ * D_;
        gemm_mma<0, 3><<<gQKV, 512, GEMM_SMEM>>>(
            xh, xl, Wqkvh + oqkv, Wqkvl + oqkv,
            bq + l * D_, bk + l * D_, bv + l * D_,
            nullptr, qkh, qkl, vth, vtl, 3072, D_);
        attn_mma_kernel<<<gAtt, 128, ATT_SMEM>>>();
        gemm_mma<0, 0><<<gD, 512, GEMM_SMEM>>>(
            ath, atl, Woh + od, Wol + od,
            bo + l * D_, nullptr, nullptr,
            y, nullptr, nullptr, nullptr, nullptr, D_, D_);
        add_ln_kernel<<<M_, 256>>>(ln1s + l * D_, ln1b + l * D_);
        gemm_mma<1, 1><<<gF, 512, GEMM_SMEM>>>(
            xh, xl, F1h + o1, F1l + o1,
            f1b + l * F_, nullptr, nullptr,
            nullptr, hh, hl, nullptr, nullptr, F_, D_);
        gemm_mma<0, 0><<<gD, 512, GEMM_SMEM>>>(
            hh, hl, F2h + o2, F2l + o2,
            f2b + l * D_, nullptr, nullptr,
            y, nullptr, nullptr, nullptr, nullptr, D_, F_);
        add_ln_kernel<<<M_, 256>>>(ln2s + l * D_, ln2b + l * D_);
    }
    final_kernel<<<B_, 256>>>(outw, out);
}

// round 13
// speedup vs baseline: 5.2323x; 1.3493x over previous
#include <cuda_runtime.h>
#include <cuda_fp16.h>
#include <math.h>
#include <stdint.h>

// ---------------------------------------------------------------------------
// Problem constants
// ---------------------------------------------------------------------------
namespace {
constexpr int B_  = 16;
constexpr int TT_ = 128;
constexpr int TS_ = 512;
constexpr int L_  = TT_ + TS_ + 2;   // 642
constexpr int LT_ = 648;             // vt row stride: multiple of 8 elems (16B)
constexpr int D_  = 1024;
constexpr int H_  = 16;
constexpr int HD_ = 64;
constexpr int F_  = 4096;
constexpr int NL_ = 4;
constexpr int M_  = B_ * L_;         // 10272
constexpr int QKS_ = 2048;           // fused q|k buffer row stride

// GEMM tiling (fp16 2-term: stages hold Ah, Al, Bh)
constexpr int BK_     = 32;
constexpr int STAGES_ = 4;
constexpr int LDS_    = 40;                    // padded row stride (elements)
constexpr int ASZ_    = 128 * LDS_ * 2;        // 10240 bytes per tile array
constexpr int STAGE_B = 3 * ASZ_;              // 30720 bytes per stage
constexpr int GEMM_SMEM = STAGES_ * STAGE_B + 1024;  // 123904

// Attention tiling
constexpr int ATS      = 72;                   // smem row stride (elements)
constexpr int AT_TILE  = 64 * ATS * 2;         // 9216 bytes per 64x64 fp16 array
constexpr int ATT_ST0  = 2 * AT_TILE;          // Qh, Ql
constexpr int ATT_STG  = 4 * AT_TILE;          // Kh, Kl, Vth, Vtl per stage
constexpr int ATT_SMEM = ATT_ST0 + 2 * ATT_STG; // 92160

// fused wsplit decode
constexpr int WT_PER_LAYER = 4 * 1024 + 4096 + 4096;  // 12288 tiles/layer
}

// ---------------------------------------------------------------------------
// Scratch (allocation-free: __device__ globals; zero-initialized)
// ---------------------------------------------------------------------------
__device__ float g_x[(size_t)M_ * D_];
__device__ float g_y[(size_t)M_ * D_];
__device__ __half g_xh [(size_t)M_ * D_];
__device__ __half g_xl [(size_t)M_ * D_];
__device__ __half g_qkh[(size_t)M_ * QKS_];
__device__ __half g_qkl[(size_t)M_ * QKS_];
__device__ __half g_vth[(size_t)B_ * D_ * LT_ + 64];
__device__ __half g_vtl[(size_t)B_ * D_ * LT_ + 64];
__device__ __half g_ath[(size_t)M_ * D_];
__device__ __half g_atl[(size_t)M_ * D_];
__device__ __half g_hh [(size_t)M_ * F_];
__device__ __half g_hl [(size_t)M_ * F_];
// transposed fp16 weights ([N,K] layout), hi only; QKV concatenated (N=3072)
__device__ __half g_Wqkvh[(size_t)NL_ * 3072 * 1024];
__device__ __half g_Woh[(size_t)NL_ * D_ * D_];
__device__ __half g_F1h[(size_t)NL_ * D_ * F_];
__device__ __half g_F2h[(size_t)NL_ * F_ * D_];
__device__ int g_tlen[B_];
__device__ int g_slen[B_];
__device__ int g_cum[B_ + 1];
__device__ int g_rowb[M_];        // batch index of each compact row

// ---------------------------------------------------------------------------
// PTX helpers (sm_80-era subset only: cp.async, ldmatrix, mma.sync)
// ---------------------------------------------------------------------------
__device__ __forceinline__ uint32_t s2u(const void* p) {
    uint32_t a;
    asm("{ .reg .u64 t; cvta.to.shared.u64 t, %1; cvt.u32.u64 %0, t; }"
        : "=r"(a) : "l"(p));
    return a;
}
__device__ __forceinline__ void cp16(uint32_t s, const void* g, int nbytes) {
    asm volatile("cp.async.cg.shared.global [%0], [%1], 16, %2;"
                 :: "r"(s), "l"(g), "r"(nbytes));
}
__device__ __forceinline__ void cp_commit() {
    asm volatile("cp.async.commit_group;");
}
template <int N> __device__ __forceinline__ void cp_wait() {
    asm volatile("cp.async.wait_group %0;" :: "n"(N));
}
__device__ __forceinline__ void ldsm4(uint32_t* r, uint32_t addr) {
    asm volatile("ldmatrix.sync.aligned.m8n8.x4.shared.b16 {%0,%1,%2,%3}, [%4];"
                 : "=r"(r[0]), "=r"(r[1]), "=r"(r[2]), "=r"(r[3]) : "r"(addr));
}
__device__ __forceinline__ void mma16816(float* c, const uint32_t* a,
                                         uint32_t b0, uint32_t b1) {
    asm volatile(
        "mma.sync.aligned.m16n8k16.row.col.f32.f16.f16.f32 "
        "{%0,%1,%2,%3}, {%4,%5,%6,%7}, {%8,%9}, {%0,%1,%2,%3};\n"
        : "+f"(c[0]), "+f"(c[1]), "+f"(c[2]), "+f"(c[3])
        : "r"(a[0]), "r"(a[1]), "r"(a[2]), "r"(a[3]), "r"(b0), "r"(b1));
}
// split two fp32 into packed fp16x2 hi and lo words
__device__ __forceinline__ void packsplit(float x, float y,
                                          uint32_t& hi, uint32_t& lo) {
    __half hx = __float2half(x), hy = __float2half(y);
    __half2 hh = __halves2half2(hx, hy);
    __half2 ll = __halves2half2(__float2half(x - __half2float(hx)),
                                __float2half(y - __half2float(hy)));
    hi = *(uint32_t*)&hh;
    lo = *(uint32_t*)&ll;
}

// ---------------------------------------------------------------------------
// Mask length computation with on-device dtype detection
// ---------------------------------------------------------------------------
__global__ void lengths_kernel(const void* tmask, const void* smask) {
    int which = blockIdx.x;
    const void* mask = which ? smask : tmask;
    int T = which ? TS_ : TT_;
    int* lens = which ? g_slen : g_tlen;
    int N = B_ * T;

    __shared__ int f3F, fMis;
    __shared__ int cnt[B_];
    int tid = threadIdx.x;
    if (tid == 0) { f3F = 0; fMis = 0; }
    if (tid < B_) cnt[tid] = 0;
    __syncthreads();

    const unsigned char* bytes = (const unsigned char*)mask;
    int l3 = 0, lm = 0;
    for (int i = tid; i < N; i += blockDim.x) {
        unsigned char c = bytes[i];
        if (c == 0x3F) l3 = 1;
        if (c == 1 && (i & 3)) lm = 1;
    }
    if (l3) atomicOr(&f3F, 1);
    if (lm) atomicOr(&fMis, 1);
    __syncthreads();

    if (fMis && !f3F) {
        for (int i = tid; i < N; i += blockDim.x)
            if (bytes[i] == 0) atomicAdd(&cnt[i / T], 1);
    } else {
        const unsigned int* w = (const unsigned int*)mask;
        for (int i = tid; i < N; i += blockDim.x)
            if (w[i] == 0u) atomicAdd(&cnt[i / T], 1);
    }
    __syncthreads();
    if (tid < B_) lens[tid] = cnt[tid];
}

// prefix sums of valid lengths
__global__ void cum_kernel() {
    if (threadIdx.x == 0) {
        int a = 0;
        for (int b = 0; b < B_; b++) {
            g_cum[b] = a;
            a += 2 + g_tlen[b] + g_slen[b];
        }
        g_cum[B_] = a;
    }
}

// ---------------------------------------------------------------------------
// Build COMPACT concatenated sequence x (fp32 + fp16 hi/lo) + row->batch map
// ---------------------------------------------------------------------------
__global__ void build_x_kernel(const float* __restrict__ text,
                               const float* __restrict__ speech,
                               const float* __restrict__ cls,
                               const float* __restrict__ sep) {
    int pos = blockIdx.x, b = blockIdx.y;
    int tl = g_tlen[b], sl = g_slen[b];
    if (pos >= 2 + tl + sl) return;
    int row = g_cum[b] + pos;
    size_t base = (size_t)row * D_;
    if (threadIdx.x == 0) g_rowb[row] = b;

    const float* s;
    if (pos == 0)                 s = cls;
    else if (pos < 1 + tl)        s = &text  [((size_t)(pos - 1) * B_ + b) * D_];
    else if (pos == 1 + tl)       s = sep;
    else                          s = &speech[((size_t)(pos - 2 - tl) * B_ + b) * D_];

    for (int d = threadIdx.x; d < D_; d += blockDim.x) {
        float v = s[d];
        g_x[base + d] = v;
        __half h = __float2half(v);
        g_xh[base + d] = h;
        g_xl[base + d] = __float2half(v - __half2float(h));
    }
}

// ---------------------------------------------------------------------------
// Fused weight transpose + fp16 convert for ALL weights (one launch).
// ---------------------------------------------------------------------------
__global__ void wsplit_all_kernel(const float* __restrict__ Wq,
                                  const float* __restrict__ Wk,
                                  const float* __restrict__ Wv,
                                  const float* __restrict__ Wo,
                                  const float* __restrict__ F1,
                                  const float* __restrict__ F2) {
    int gidx = blockIdx.x;
    int l = gidx / WT_PER_LAYER;
    int r = gidx - l * WT_PER_LAYER;

    const float* W;
    __half* Th;
    int K, N, tile;
    if (r < 4096) {
        int type = r >> 10;           // 0=q 1=k 2=v 3=o
        tile = r & 1023;
        K = 1024; N = 1024;
        size_t wofs = (size_t)l * D_ * D_;
        if (type == 0)      { W = Wq + wofs; }
        else if (type == 1) { W = Wk + wofs; }
        else if (type == 2) { W = Wv + wofs; }
        else                { W = Wo + wofs; }
        if (type < 3)
            Th = g_Wqkvh + (size_t)l * 3072 * 1024 + (size_t)type * 1024 * 1024;
        else
            Th = g_Woh + (size_t)l * D_ * D_;
    } else if (r < 8192) {
        tile = r - 4096;
        K = 1024; N = 4096;
        W = F1 + (size_t)l * D_ * F_;
        Th = g_F1h + (size_t)l * D_ * F_;
    } else {
        tile = r - 8192;
        K = 4096; N = 1024;
        W = F2 + (size_t)l * F_ * D_;
        Th = g_F2h + (size_t)l * F_ * D_;
    }

    int ntiles = N >> 5;
    int n0 = (tile % ntiles) * 32;
    int k0 = (tile / ntiles) * 32;

    __shared__ float t[32][33];
    int tx = threadIdx.x, ty = threadIdx.y;
    #pragma unroll
    for (int j = 0; j < 4; j++) {
        int k = k0 + ty + j * 8;
        t[ty + j * 8][tx] = W[(size_t)k * N + n0 + tx];
    }
    __syncthreads();
    #pragma unroll
    for (int j = 0; j < 4; j++) {
        int n = n0 + ty + j * 8;
        Th[(size_t)n * K + k0 + tx] = __float2half(t[tx][ty + j * 8]);
    }
}

// ---------------------------------------------------------------------------
// HMMA fp16 GEMM with 2-term compensation (A = Ah+Al fp16 exact; B = Bh fp16).
// Error = A*(B - Bh) ~ 2^-13 relative per output.
// 128x128x32 CTA tile, 512 threads (16 warps, 4x4), 4-stage cp.async pipeline.
// MODE 0: fp32 C.  MODE 1: fp16 hi/lo C (after optional RELU), stride Nn.
// MODE 3: fused QKV epilogue: n<2048 -> qk buffer (stride 2048);
//         n>=2048 -> V transposed per batch: vt[(b*D + n-2048)*LT + pos].
// ---------------------------------------------------------------------------
template <int RELU, int MODE>
__global__ __launch_bounds__(512, 1) void gemm_mma(
    const __half* __restrict__ Ah, const __half* __restrict__ Al,
    const __half* __restrict__ Bh,
    const float* __restrict__ bias, const float* __restrict__ bias2,
    const float* __restrict__ bias3,
    float* __restrict__ Cf,
    __half* __restrict__ Ch, __half* __restrict__ Cl,
    __half* __restrict__ Ch2, __half* __restrict__ Cl2,
    int Nn, int Kn) {
    extern __shared__ char dynsmem[];
    uint32_t sbase = (s2u(dynsmem) + 1023u) & ~1023u;
    int tid = threadIdx.x;
    int wid = tid >> 5, lane = tid & 31;
    int m0 = blockIdx.y * 128, n0 = blockIdx.x * 128;
    const int Mc = g_cum[B_];
    if (m0 >= Mc) return;   // fully-pad tile (compact rows)

    int wm = wid & 3, wn = wid >> 2;     // 4x4 warp grid
    int m0w = wm * 32, n0w = wn * 32;
    const int T = Kn / BK_;

    int lrow = tid >> 2, lcol = tid & 3;   // loader: row 0..127, 16B chunk 0..3

    auto issue = [&](int kt) {
        uint32_t stb = sbase + (kt % STAGES_) * STAGE_B;
        uint32_t off = (uint32_t)(lrow * LDS_ + lcol * 8) * 2;
        int gr = m0 + lrow;
        bool vld = gr < Mc;
        size_t aofs = (size_t)(vld ? gr : 0) * Kn + kt * BK_ + lcol * 8;
        cp16(stb + off,            Ah + aofs, vld ? 16 : 0);
        cp16(stb + ASZ_ + off,     Al + aofs, vld ? 16 : 0);
        cp16(stb + 2 * ASZ_ + off,
             Bh + (size_t)(n0 + lrow) * Kn + kt * BK_ + lcol * 8, 16);
        cp_commit();
    };

    issue(0);
    issue(1);
    issue(2);

    float acc[2][4][4];
    #pragma unroll
    for (int i = 0; i < 2; i++)
        #pragma unroll
        for (int j = 0; j < 4; j++)
            #pragma unroll
            for (int p = 0; p < 4; p++) acc[i][j][p] = 0.f;

    int lr = lane & 15, lc8 = (lane >> 4) * 8;

    for (int kt = 0; kt < T; kt++) {
        cp_wait<STAGES_ - 2>();
        __syncthreads();
        uint32_t stb = sbase + (kt % STAGES_) * STAGE_B;
        #pragma unroll
        for (int kk = 0; kk < 2; kk++) {
            int koff = kk * 16 + lc8;
            uint32_t ah[2][4], al[2][4], bh[2][4];
            #pragma unroll
            for (int im = 0; im < 2; im++) {
                uint32_t ad = stb + (uint32_t)((m0w + im * 16 + lr) * LDS_ + koff) * 2;
                ldsm4(ah[im], ad);
                ldsm4(al[im], ad + ASZ_);
            }
            #pragma unroll
            for (int ib = 0; ib < 2; ib++) {
                uint32_t bd = stb + 2 * ASZ_ +
                              (uint32_t)((n0w + ib * 16 + lr) * LDS_ + koff) * 2;
                ldsm4(bh[ib], bd);
            }
            #pragma unroll
            for (int im = 0; im < 2; im++)
                #pragma unroll
                for (int in = 0; in < 4; in++) {
                    int ib = in >> 1, sb = in & 1;
                    mma16816(acc[im][in], ah[im], bh[ib][sb], bh[ib][sb + 2]);
                    mma16816(acc[im][in], al[im], bh[ib][sb], bh[ib][sb + 2]);
                }
        }
        int nt = kt + STAGES_ - 1;
        if (nt < T) issue(nt); else cp_commit();
    }

    // Epilogue
    int g = lane >> 2, tq = lane & 3;
    #pragma unroll
    for (int in = 0; in < 4; in++) {
        int cb = n0 + n0w + in * 8 + tq * 2;
        float b0, b1;
        int section = cb >> 10;   // only meaningful for MODE 3
        if (MODE == 3) {
            const float* bp = (section == 0) ? bias : (section == 1) ? bias2 : bias3;
            b0 = __ldg(&bp[cb & 1023]);
            b1 = __ldg(&bp[(cb & 1023) + 1]);
        } else {
            b0 = __ldg(&bias[cb]);
            b1 = __ldg(&bias[cb + 1]);
        }
        #pragma unroll
        for (int im = 0; im < 2; im++) {
            #pragma unroll
            for (int hrow = 0; hrow < 2; hrow++) {
                int m = m0 + m0w + im * 16 + g + hrow * 8;
                if (m < Mc) {
                    float v0 = acc[im][in][hrow * 2 + 0] + b0;
                    float v1 = acc[im][in][hrow * 2 + 1] + b1;
                    if (RELU) { v0 = fmaxf(v0, 0.f); v1 = fmaxf(v1, 0.f); }
                    if (MODE == 0) {
                        *(float2*)&Cf[(size_t)m * Nn + cb] = make_float2(v0, v1);
                    } else if (MODE == 1) {
                        uint32_t hw, lw;
                        packsplit(v0, v1, hw, lw);
                        *(uint32_t*)&Ch[(size_t)m * Nn + cb] = hw;
                        *(uint32_t*)&Cl[(size_t)m * Nn + cb] = lw;
                    } else {  // MODE 3
                        if (section < 2) {
                            uint32_t hw, lw;
                            packsplit(v0, v1, hw, lw);
                            *(uint32_t*)&Ch[(size_t)m * QKS_ + cb] = hw;
                            *(uint32_t*)&Cl[(size_t)m * QKS_ + cb] = lw;
                        } else {
                            int bb = g_rowb[m];
                            int pos = m - g_cum[bb];
                            int nn = cb & 1023;
                            size_t vt0 = ((size_t)bb * D_ + nn) * LT_ + pos;
                            __half h0 = __float2half(v0);
                            __half h1 = __float2half(v1);
                            Ch2[vt0]       = h0;
                            Ch2[vt0 + LT_] = h1;
                            Cl2[vt0]       = __float2half(v0 - __half2float(h0));
                            Cl2[vt0 + LT_] = __float2half(v1 - __half2float(h1));
                        }
                    }
                }
            }
        }
    }
}

// ---------------------------------------------------------------------------
// HMMA fp16 flash attention with 3-term hi/lo compensation (compact rows).
// Block: (q-tile 64, head, batch), 128 threads.
// Q/K from g_qkh/l (stride 2048; k at col offset 1024); V from g_vth/l.
// ---------------------------------------------------------------------------
__global__ __launch_bounds__(128, 1) void attn_mma_kernel() {
    extern __shared__ char asmem[];
    uint32_t sb = s2u(asmem);
    int tid = threadIdx.x, lane = tid & 31, w = tid >> 5;
    int qt = blockIdx.x, h = blockIdx.y, b = blockIdx.z;
    int q0 = qt * 64;
    int Lv = 2 + g_tlen[b] + g_slen[b];
    if (q0 >= Lv) return;
    int cumb = g_cum[b];
    const int NKT = (Lv + 63) >> 6;

    int lr = lane & 15, lc8 = (lane >> 4) * 8;
    int r = lane >> 2, tq = lane & 3;
    int lrow = tid >> 1, lhf = tid & 1;   // smem-fill: row, col-half

    // ---- stage Q (hi/lo) ----
    {
        int qrow = q0 + lrow; if (qrow > Lv - 1) qrow = Lv - 1;
        size_t off = (size_t)(cumb + qrow) * QKS_ + h * HD_ + lhf * 32;
        uint32_t dst = sb + (uint32_t)(lrow * ATS + lhf * 32) * 2;
        #pragma unroll
        for (int u = 0; u < 4; u++) {
            cp16(dst + u * 16,           g_qkh + off + u * 8, 16);
            cp16(dst + AT_TILE + u * 16, g_qkl + off + u * 8, 16);
        }
        cp_commit();
    }

    auto loadKV = [&](int kt) {
        uint32_t base = sb + ATT_ST0 + (kt & 1) * ATT_STG;
        int k0 = kt * 64;
        int krow = k0 + lrow; if (krow > Lv - 1) krow = Lv - 1;
        size_t koff = (size_t)(cumb + krow) * QKS_ + 1024 + h * HD_ + lhf * 32;
        uint32_t kdst = base + (uint32_t)(lrow * ATS + lhf * 32) * 2;
        #pragma unroll
        for (int u = 0; u < 4; u++) {
            cp16(kdst + u * 16,           g_qkh + koff + u * 8, 16);
            cp16(kdst + AT_TILE + u * 16, g_qkl + koff + u * 8, 16);
        }
        // V: row stride LT_ (16B-aligned); cols >= Lv are stale/zero but P=0.
        size_t voff = ((size_t)b * D_ + h * HD_ + lrow) * LT_ + k0 + lhf * 32;
        uint32_t vdst = base + 2 * AT_TILE + (uint32_t)(lrow * ATS + lhf * 32) * 2;
        #pragma unroll
        for (int u = 0; u < 4; u++) {
            int col = k0 + lhf * 32 + u * 8;
            int nb = (col < LT_) ? 16 : 0;   // zfill past padded length
            cp16(vdst + u * 16,           g_vth + voff + u * 8, nb);
            cp16(vdst + AT_TILE + u * 16, g_vtl + voff + u * 8, nb);
        }
        cp_commit();
    };

    loadKV(0);
    cp_wait<1>();           // Q staged (KV0 may still be in flight)
    __syncthreads();

    // Q fragments (held in registers for the whole kernel)
    uint32_t qfh[4][4], qfl[4][4];
    #pragma unroll
    for (int c = 0; c < 4; c++) {
        uint32_t ad = sb + (uint32_t)((w * 16 + lr) * ATS + c * 16 + lc8) * 2;
        ldsm4(qfh[c], ad);
        ldsm4(qfl[c], ad + AT_TILE);
    }

    float o[8][4];
    #pragma unroll
    for (int j = 0; j < 8; j++)
        #pragma unroll
        for (int p = 0; p < 4; p++) o[j][p] = 0.f;
    float mrA = -1e30f, mrB = -1e30f, lsA = 0.f, lsB = 0.f;

    for (int kt = 0; kt < NKT; kt++) {
        if (kt + 1 < NKT) { loadKV(kt + 1); cp_wait<1>(); }
        else              { cp_wait<0>(); }
        __syncthreads();
        uint32_t base = sb + ATT_ST0 + (kt & 1) * ATT_STG;
        int k0 = kt * 64;

        // ---- S = Q K^T (3-term) ----
        float s[8][4];
        #pragma unroll
        for (int j = 0; j < 8; j++)
            #pragma unroll
            for (int p = 0; p < 4; p++) s[j][p] = 0.f;

        #pragma unroll
        for (int c = 0; c < 4; c++) {
            #pragma unroll
            for (int ib = 0; ib < 4; ib++) {
                uint32_t bd = base + (uint32_t)((ib * 16 + lr) * ATS + c * 16 + lc8) * 2;
                uint32_t kbh[4], kbl[4];
                ldsm4(kbh, bd);
                ldsm4(kbl, bd + AT_TILE);
                #pragma unroll
                for (int sbn = 0; sbn < 2; sbn++) {
                    int j = ib * 2 + sbn;
                    mma16816(s[j], qfh[c], kbh[sbn], kbh[sbn + 2]);
                    mma16816(s[j], qfh[c], kbl[sbn], kbl[sbn + 2]);
                    mma16816(s[j], qfl[c], kbh[sbn], kbh[sbn + 2]);
                }
            }
        }

        // ---- scale + mask ----
        #pragma unroll
        for (int j = 0; j < 8; j++) {
            int c0 = k0 + j * 8 + 2 * tq, c1 = c0 + 1;
            s[j][0] = (c0 < Lv) ? s[j][0] * 0.125f : -1e9f;
            s[j][1] = (c1 < Lv) ? s[j][1] * 0.125f : -1e9f;
            s[j][2] = (c0 < Lv) ? s[j][2] * 0.125f : -1e9f;
            s[j][3] = (c1 < Lv) ? s[j][3] * 0.125f : -1e9f;
        }

        // ---- online softmax (rows r and r+8) ----
        float mA = -1e30f, mB = -1e30f;
        #pragma unroll
        for (int j = 0; j < 8; j++) {
            mA = fmaxf(mA, fmaxf(s[j][0], s[j][1]));
            mB = fmaxf(mB, fmaxf(s[j][2], s[j][3]));
        }
        mA = fmaxf(mA, __shfl_xor_sync(0xffffffffu, mA, 1));
        mA = fmaxf(mA, __shfl_xor_sync(0xffffffffu, mA, 2));
        mB = fmaxf(mB, __shfl_xor_sync(0xffffffffu, mB, 1));
        mB = fmaxf(mB, __shfl_xor_sync(0xffffffffu, mB, 2));
        float mnA = fmaxf(mrA, mA), mnB = fmaxf(mrB, mB);
        float aA = expf(mrA - mnA), aB = expf(mrB - mnB);
        float rsA = 0.f, rsB = 0.f;
        #pragma unroll
        for (int j = 0; j < 8; j++) {
            s[j][0] = expf(s[j][0] - mnA);
            s[j][1] = expf(s[j][1] - mnA);
            s[j][2] = expf(s[j][2] - mnB);
            s[j][3] = expf(s[j][3] - mnB);
            rsA += s[j][0] + s[j][1];
            rsB += s[j][2] + s[j][3];
        }
        rsA += __shfl_xor_sync(0xffffffffu, rsA, 1);
        rsA += __shfl_xor_sync(0xffffffffu, rsA, 2);
        rsB += __shfl_xor_sync(0xffffffffu, rsB, 1);
        rsB += __shfl_xor_sync(0xffffffffu, rsB, 2);
        lsA = lsA * aA + rsA;
        lsB = lsB * aB + rsB;
        mrA = mnA; mrB = mnB;
        #pragma unroll
        for (int j = 0; j < 8; j++) {
            o[j][0] *= aA; o[j][1] *= aA;
            o[j][2] *= aB; o[j][3] *= aB;
        }

        // ---- O += P V (3-term) ----
        #pragma unroll
        for (int c = 0; c < 4; c++) {
            uint32_t pah[4], pal[4];
            packsplit(s[2 * c][0],     s[2 * c][1],     pah[0], pal[0]);
            packsplit(s[2 * c][2],     s[2 * c][3],     pah[1], pal[1]);
            packsplit(s[2 * c + 1][0], s[2 * c + 1][1], pah[2], pal[2]);
            packsplit(s[2 * c + 1][2], s[2 * c + 1][3], pah[3], pal[3]);
            #pragma unroll
            for (int ib = 0; ib < 4; ib++) {
                uint32_t bd = base + 2 * AT_TILE +
                              (uint32_t)((ib * 16 + lr) * ATS + c * 16 + lc8) * 2;
                uint32_t vbh[4], vbl[4];
                ldsm4(vbh, bd);
                ldsm4(vbl, bd + AT_TILE);
                #pragma unroll
                for (int sbn = 0; sbn < 2; sbn++) {
                    int j = ib * 2 + sbn;
                    mma16816(o[j], pah, vbh[sbn], vbh[sbn + 2]);
                    mma16816(o[j], pal, vbh[sbn], vbh[sbn + 2]);
                    mma16816(o[j], pah, vbl[sbn], vbl[sbn + 2]);
                }
            }
        }
        __syncthreads();
    }

    // ---- write O (compact rows, only valid positions) ----
    float iA = 1.f / lsA, iB = 1.f / lsB;
    int qA = q0 + w * 16 + r, qB = qA + 8;
    #pragma unroll
    for (int j = 0; j < 8; j++) {
        int d = h * HD_ + j * 8 + 2 * tq;
        if (qA < Lv) {
            size_t off = (size_t)(cumb + qA) * D_ + d;
            uint32_t hw, lw;
            packsplit(o[j][0] * iA, o[j][1] * iA, hw, lw);
            *(uint32_t*)&g_ath[off] = hw;
            *(uint32_t*)&g_atl[off] = lw;
        }
        if (qB < Lv) {
            size_t off = (size_t)(cumb + qB) * D_ + d;
            uint32_t hw, lw;
            packsplit(o[j][2] * iB, o[j][3] * iB, hw, lw);
            *(uint32_t*)&g_ath[off] = hw;
            *(uint32_t*)&g_atl[off] = lw;
        }
    }
}

// ---------------------------------------------------------------------------
// x = LayerNorm(x + y) * s + b (in place) + fp16 hi/lo emission (compact rows).
// ---------------------------------------------------------------------------
__global__ __launch_bounds__(256) void add_ln_kernel(const float* __restrict__ sc,
                                                     const float* __restrict__ bi) {
    int row = blockIdx.x;
    if (row >= g_cum[B_]) return;
    size_t base = (size_t)row * D_;
    __shared__ float red[256];
    int tid = threadIdx.x;

    float v[4];
    float s = 0.f;
    #pragma unroll
    for (int u = 0; u < 4; u++) {
        int d = tid + u * 256;
        v[u] = g_x[base + d] + g_y[base + d];
        s += v[u];
    }
    red[tid] = s;
    __syncthreads();
    for (int off = 128; off > 0; off >>= 1) {
        if (tid < off) red[tid] += red[tid + off];
        __syncthreads();
    }
    float mean = red[0] * (1.f / D_);
    __syncthreads();

    float s2 = 0.f;
    #pragma unroll
    for (int u = 0; u < 4; u++) { float dd = v[u] - mean; s2 += dd * dd; }
    red[tid] = s2;
    __syncthreads();
    for (int off = 128; off > 0; off >>= 1) {
        if (tid < off) red[tid] += red[tid + off];
        __syncthreads();
    }
    float var = red[0] * (1.f / D_);
    float inv = rsqrtf(var + 1e-5f);

    #pragma unroll
    for (int u = 0; u < 4; u++) {
        int d = tid + u * 256;
        float t = (v[u] - mean) * inv * sc[d] + bi[d];
        g_x[base + d] = t;
        __half hh = __float2half(t);
        g_xh[base + d] = hh;
        g_xl[base + d] = __float2half(t - __half2float(hh));
    }
}

// ---------------------------------------------------------------------------
// out[b] = dot(x[cum[b], :], out_w)
// ---------------------------------------------------------------------------
__global__ __launch_bounds__(256) void final_kernel(const float* __restrict__ ow,
                                                    float* __restrict__ out) {
    int b = blockIdx.x;
    __shared__ float red[256];
    const float* xr = &g_x[(size_t)g_cum[b] * D_];
    int tid = threadIdx.x;
    float s = 0.f;
    for (int d = tid; d < D_; d += 256) s += xr[d] * ow[d];
    red[tid] = s;
    __syncthreads();
    for (int off = 128; off > 0; off >>= 1) {
        if (tid < off) red[tid] += red[tid + off];
        __syncthreads();
    }
    if (tid == 0) out[b] = red[0];
}

// ---------------------------------------------------------------------------
// Launch
// ---------------------------------------------------------------------------
extern "C" void kernel_launch(void* const* d_in, const int* in_sizes, int n_in,
                              void* d_out, int out_size) {
    const float* text   = (const float*)d_in[0];
    const float* speech = (const float*)d_in[1];
    const void*  tmask  = d_in[2];
    const void*  smask  = d_in[3];
    const float* cls    = (const float*)d_in[4];
    const float* sep    = (const float*)d_in[5];
    const float* Wq     = (const float*)d_in[6];
    const float* bq     = (const float*)d_in[7];
    const float* Wk     = (const float*)d_in[8];
    const float* bk     = (const float*)d_in[9];
    const float* Wv     = (const float*)d_in[10];
    const float* bv     = (const float*)d_in[11];
    const float* Wo     = (const float*)d_in[12];
    const float* bo     = (const float*)d_in[13];
    const float* ln1s   = (const float*)d_in[14];
    const float* ln1b   = (const float*)d_in[15];
    const float* f1w    = (const float*)d_in[16];
    const float* f1b    = (const float*)d_in[17];
    const float* f2w    = (const float*)d_in[18];
    const float* f2b    = (const float*)d_in[19];
    const float* ln2s   = (const float*)d_in[20];
    const float* ln2b   = (const float*)d_in[21];
    const float* outw   = (const float*)d_in[22];
    float* out = (float*)d_out;

    float* y;
    __half *xh, *xl, *qkh, *qkl, *vth, *vtl, *ath, *atl, *hh, *hl;
    __half *Wqkvh, *Woh, *F1h, *F2h;
    cudaGetSymbolAddress((void**)&y,     g_y);
    cudaGetSymbolAddress((void**)&xh,    g_xh);
    cudaGetSymbolAddress((void**)&xl,    g_xl);
    cudaGetSymbolAddress((void**)&qkh,   g_qkh);
    cudaGetSymbolAddress((void**)&qkl,   g_qkl);
    cudaGetSymbolAddress((void**)&vth,   g_vth);
    cudaGetSymbolAddress((void**)&vtl,   g_vtl);
    cudaGetSymbolAddress((void**)&ath,   g_ath);
    cudaGetSymbolAddress((void**)&atl,   g_atl);
    cudaGetSymbolAddress((void**)&hh,    g_hh);
    cudaGetSymbolAddress((void**)&hl,    g_hl);
    cudaGetSymbolAddress((void**)&Wqkvh, g_Wqkvh);
    cudaGetSymbolAddress((void**)&Woh,   g_Woh);
    cudaGetSymbolAddress((void**)&F1h,   g_F1h);
    cudaGetSymbolAddress((void**)&F2h,   g_F2h);

    cudaFuncSetAttribute(attn_mma_kernel,
                         cudaFuncAttributeMaxDynamicSharedMemorySize, ATT_SMEM);
    cudaFuncSetAttribute(gemm_mma<0, 0>,
                         cudaFuncAttributeMaxDynamicSharedMemorySize, GEMM_SMEM);
    cudaFuncSetAttribute(gemm_mma<0, 3>,
                         cudaFuncAttributeMaxDynamicSharedMemorySize, GEMM_SMEM);
    cudaFuncSetAttribute(gemm_mma<1, 1>,
                         cudaFuncAttributeMaxDynamicSharedMemorySize, GEMM_SMEM);

    lengths_kernel<<<2, 256>>>(tmask, smask);
    cum_kernel<<<1, 32>>>();
    build_x_kernel<<<dim3(L_, B_), 256>>>(text, speech, cls, sep);
    wsplit_all_kernel<<<NL_ * WT_PER_LAYER, dim3(32, 8)>>>(Wq, Wk, Wv, Wo, f1w, f2w);

    int mt = (M_ + 127) / 128;  // 81 (static; CTAs past Mc self-skip)
    dim3 gQKV(3072 / 128, mt);
    dim3 gD(D_ / 128, mt);
    dim3 gF(F_ / 128, mt);
    dim3 gAtt((L_ + 63) / 64, H_, B_);

    for (int l = 0; l < NL_; l++) {
        size_t oqkv = (size_t)l * 3072 * 1024;
        size_t od = (size_t)l * D_ * D_;
        size_t o1 = (size_t)l * D_ * F_;
        size_t o2 = (size_t)l * F_ * D_;
        gemm_mma<0, 3><<<gQKV, 512, GEMM_SMEM>>>(
            xh, xl, Wqkvh + oqkv,
            bq + l * D_, bk + l * D_, bv + l * D_,
            nullptr, qkh, qkl, vth, vtl, 3072, D_);
        attn_mma_kernel<<<gAtt, 128, ATT_SMEM>>>();
        gemm_mma<0, 0><<<gD, 512, GEMM_SMEM>>>(
            ath, atl, Woh + od,
            bo + l * D_, nullptr, nullptr,
            y, nullptr, nullptr, nullptr, nullptr, D_, D_);
        add_ln_kernel<<<M_, 256>>>(ln1s + l * D_, ln1b + l * D_);
        gemm_mma<1, 1><<<gF, 512, GEMM_SMEM>>>(
            xh, xl, F1h + o1,
            f1b + l * F_, nullptr, nullptr,
            nullptr, hh, hl, nullptr, nullptr, F_, D_);
        gemm_mma<0, 0><<<gD, 512, GEMM_SMEM>>>(
            hh, hl, F2h + o2,
            f2b + l * D_, nullptr, nullptr,
            y, nullptr, nullptr, nullptr, nullptr, D_, F_);
        add_ln_kernel<<<M_, 256>>>(ln2s + l * D_, ln2b + l * D_);
    }
    final_kernel<<<B_, 256>>>(outw, out);
}

// round 14
// speedup vs baseline: 7.1692x; 1.3702x over previous
#include <cuda_runtime.h>
#include <cuda_fp16.h>
#include <math.h>
#include <stdint.h>

// ---------------------------------------------------------------------------
// Problem constants
// ---------------------------------------------------------------------------
namespace {
constexpr int B_  = 16;
constexpr int TT_ = 128;
constexpr int TS_ = 512;
constexpr int L_  = TT_ + TS_ + 2;   // 642
constexpr int LT_ = 648;             // vt row stride: multiple of 8 elems (16B)
constexpr int D_  = 1024;
constexpr int H_  = 16;
constexpr int HD_ = 64;
constexpr int F_  = 4096;
constexpr int NL_ = 4;
constexpr int M_  = B_ * L_;         // 10272
constexpr int QKS_ = 2048;           // fused q|k buffer row stride

// GEMM tiling (stages hold Ah, Al, Bh; 1-term kernels leave Al slot unused)
constexpr int BK_     = 32;
constexpr int STAGES_ = 4;
constexpr int LDS_    = 40;                    // padded row stride (elements)
constexpr int ASZ_    = 128 * LDS_ * 2;        // 10240 bytes per tile array
constexpr int STAGE_B = 3 * ASZ_;              // 30720 bytes per stage
constexpr int GEMM_SMEM = STAGES_ * STAGE_B + 1024;  // 123904

// Attention tiling
constexpr int ATS      = 72;                   // smem row stride (elements)
constexpr int AT_TILE  = 64 * ATS * 2;         // 9216 bytes per 64x64 fp16 array
constexpr int ATT_ST0  = 2 * AT_TILE;          // Qh, Ql
constexpr int ATT_STG  = 4 * AT_TILE;          // Kh, Kl, Vth, Vtl per stage
constexpr int ATT_SMEM = ATT_ST0 + 2 * ATT_STG; // 92160

// fused wsplit decode
constexpr int WT_PER_LAYER = 4 * 1024 + 4096 + 4096;  // 12288 tiles/layer
}

// ---------------------------------------------------------------------------
// Scratch (allocation-free: __device__ globals; zero-initialized)
// ---------------------------------------------------------------------------
__device__ float g_x[(size_t)M_ * D_];
__device__ float g_y[(size_t)M_ * D_];
__device__ __half g_xh [(size_t)M_ * D_];
__device__ __half g_xl [(size_t)M_ * D_];
__device__ __half g_qkh[(size_t)M_ * QKS_];
__device__ __half g_qkl[(size_t)M_ * QKS_];
__device__ __half g_vth[(size_t)B_ * D_ * LT_ + 64];
__device__ __half g_vtl[(size_t)B_ * D_ * LT_ + 64];
__device__ __half g_ath[(size_t)M_ * D_];
__device__ __half g_hh [(size_t)M_ * F_];
// transposed fp16 weights ([N,K] layout), hi only; QKV concatenated (N=3072)
__device__ __half g_Wqkvh[(size_t)NL_ * 3072 * 1024];
__device__ __half g_Woh[(size_t)NL_ * D_ * D_];
__device__ __half g_F1h[(size_t)NL_ * D_ * F_];
__device__ __half g_F2h[(size_t)NL_ * F_ * D_];
__device__ int g_tlen[B_];
__device__ int g_slen[B_];
__device__ int g_cum[B_ + 1];
__device__ int g_rowb[M_];        // batch index of each compact row

// ---------------------------------------------------------------------------
// PTX helpers (sm_80-era subset only: cp.async, ldmatrix, mma.sync)
// ---------------------------------------------------------------------------
__device__ __forceinline__ uint32_t s2u(const void* p) {
    uint32_t a;
    asm("{ .reg .u64 t; cvta.to.shared.u64 t, %1; cvt.u32.u64 %0, t; }"
        : "=r"(a) : "l"(p));
    return a;
}
__device__ __forceinline__ void cp16(uint32_t s, const void* g, int nbytes) {
    asm volatile("cp.async.cg.shared.global [%0], [%1], 16, %2;"
                 :: "r"(s), "l"(g), "r"(nbytes));
}
__device__ __forceinline__ void cp_commit() {
    asm volatile("cp.async.commit_group;");
}
template <int N> __device__ __forceinline__ void cp_wait() {
    asm volatile("cp.async.wait_group %0;" :: "n"(N));
}
__device__ __forceinline__ void ldsm4(uint32_t* r, uint32_t addr) {
    asm volatile("ldmatrix.sync.aligned.m8n8.x4.shared.b16 {%0,%1,%2,%3}, [%4];"
                 : "=r"(r[0]), "=r"(r[1]), "=r"(r[2]), "=r"(r[3]) : "r"(addr));
}
__device__ __forceinline__ void mma16816(float* c, const uint32_t* a,
                                         uint32_t b0, uint32_t b1) {
    asm volatile(
        "mma.sync.aligned.m16n8k16.row.col.f32.f16.f16.f32 "
        "{%0,%1,%2,%3}, {%4,%5,%6,%7}, {%8,%9}, {%0,%1,%2,%3};\n"
        : "+f"(c[0]), "+f"(c[1]), "+f"(c[2]), "+f"(c[3])
        : "r"(a[0]), "r"(a[1]), "r"(a[2]), "r"(a[3]), "r"(b0), "r"(b1));
}
// split two fp32 into packed fp16x2 hi and lo words
__device__ __forceinline__ void packsplit(float x, float y,
                                          uint32_t& hi, uint32_t& lo) {
    __half hx = __float2half(x), hy = __float2half(y);
    __half2 hh = __halves2half2(hx, hy);
    __half2 ll = __halves2half2(__float2half(x - __half2float(hx)),
                                __float2half(y - __half2float(hy)));
    hi = *(uint32_t*)&hh;
    lo = *(uint32_t*)&ll;
}
__device__ __forceinline__ uint32_t packh(float x, float y) {
    __half2 hh = __halves2half2(__float2half(x), __float2half(y));
    return *(uint32_t*)&hh;
}

// ---------------------------------------------------------------------------
// Mask length computation with on-device dtype detection
// ---------------------------------------------------------------------------
__global__ void lengths_kernel(const void* tmask, const void* smask) {
    int which = blockIdx.x;
    const void* mask = which ? smask : tmask;
    int T = which ? TS_ : TT_;
    int* lens = which ? g_slen : g_tlen;
    int N = B_ * T;

    __shared__ int f3F, fMis;
    __shared__ int cnt[B_];
    int tid = threadIdx.x;
    if (tid == 0) { f3F = 0; fMis = 0; }
    if (tid < B_) cnt[tid] = 0;
    __syncthreads();

    const unsigned char* bytes = (const unsigned char*)mask;
    int l3 = 0, lm = 0;
    for (int i = tid; i < N; i += blockDim.x) {
        unsigned char c = bytes[i];
        if (c == 0x3F) l3 = 1;
        if (c == 1 && (i & 3)) lm = 1;
    }
    if (l3) atomicOr(&f3F, 1);
    if (lm) atomicOr(&fMis, 1);
    __syncthreads();

    if (fMis && !f3F) {
        for (int i = tid; i < N; i += blockDim.x)
            if (bytes[i] == 0) atomicAdd(&cnt[i / T], 1);
    } else {
        const unsigned int* w = (const unsigned int*)mask;
        for (int i = tid; i < N; i += blockDim.x)
            if (w[i] == 0u) atomicAdd(&cnt[i / T], 1);
    }
    __syncthreads();
    if (tid < B_) lens[tid] = cnt[tid];
}

// prefix sums of valid lengths
__global__ void cum_kernel() {
    if (threadIdx.x == 0) {
        int a = 0;
        for (int b = 0; b < B_; b++) {
            g_cum[b] = a;
            a += 2 + g_tlen[b] + g_slen[b];
        }
        g_cum[B_] = a;
    }
}

// ---------------------------------------------------------------------------
// Build COMPACT concatenated sequence x (fp32 + fp16 hi/lo) + row->batch map
// ---------------------------------------------------------------------------
__global__ void build_x_kernel(const float* __restrict__ text,
                               const float* __restrict__ speech,
                               const float* __restrict__ cls,
                               const float* __restrict__ sep) {
    int pos = blockIdx.x, b = blockIdx.y;
    int tl = g_tlen[b], sl = g_slen[b];
    if (pos >= 2 + tl + sl) return;
    int row = g_cum[b] + pos;
    size_t base = (size_t)row * D_;
    if (threadIdx.x == 0) g_rowb[row] = b;

    const float* s;
    if (pos == 0)                 s = cls;
    else if (pos < 1 + tl)        s = &text  [((size_t)(pos - 1) * B_ + b) * D_];
    else if (pos == 1 + tl)       s = sep;
    else                          s = &speech[((size_t)(pos - 2 - tl) * B_ + b) * D_];

    for (int d = threadIdx.x; d < D_; d += blockDim.x) {
        float v = s[d];
        g_x[base + d] = v;
        __half h = __float2half(v);
        g_xh[base + d] = h;
        g_xl[base + d] = __float2half(v - __half2float(h));
    }
}

// ---------------------------------------------------------------------------
// Fused weight transpose + fp16 convert for ALL weights (one launch).
// ---------------------------------------------------------------------------
__global__ void wsplit_all_kernel(const float* __restrict__ Wq,
                                  const float* __restrict__ Wk,
                                  const float* __restrict__ Wv,
                                  const float* __restrict__ Wo,
                                  const float* __restrict__ F1,
                                  const float* __restrict__ F2) {
    int gidx = blockIdx.x;
    int l = gidx / WT_PER_LAYER;
    int r = gidx - l * WT_PER_LAYER;

    const float* W;
    __half* Th;
    int K, N, tile;
    if (r < 4096) {
        int type = r >> 10;           // 0=q 1=k 2=v 3=o
        tile = r & 1023;
        K = 1024; N = 1024;
        size_t wofs = (size_t)l * D_ * D_;
        if (type == 0)      { W = Wq + wofs; }
        else if (type == 1) { W = Wk + wofs; }
        else if (type == 2) { W = Wv + wofs; }
        else                { W = Wo + wofs; }
        if (type < 3)
            Th = g_Wqkvh + (size_t)l * 3072 * 1024 + (size_t)type * 1024 * 1024;
        else
            Th = g_Woh + (size_t)l * D_ * D_;
    } else if (r < 8192) {
        tile = r - 4096;
        K = 1024; N = 4096;
        W = F1 + (size_t)l * D_ * F_;
        Th = g_F1h + (size_t)l * D_ * F_;
    } else {
        tile = r - 8192;
        K = 4096; N = 1024;
        W = F2 + (size_t)l * F_ * D_;
        Th = g_F2h + (size_t)l * F_ * D_;
    }

    int ntiles = N >> 5;
    int n0 = (tile % ntiles) * 32;
    int k0 = (tile / ntiles) * 32;

    __shared__ float t[32][33];
    int tx = threadIdx.x, ty = threadIdx.y;
    #pragma unroll
    for (int j = 0; j < 4; j++) {
        int k = k0 + ty + j * 8;
        t[ty + j * 8][tx] = W[(size_t)k * N + n0 + tx];
    }
    __syncthreads();
    #pragma unroll
    for (int j = 0; j < 4; j++) {
        int n = n0 + ty + j * 8;
        Th[(size_t)n * K + k0 + tx] = __float2half(t[tx][ty + j * 8]);
    }
}

// ---------------------------------------------------------------------------
// HMMA fp16 GEMM, TERMS-term compensation (TERMS=2: A=Ah+Al exact, B=Bh;
// TERMS=1: pure Ah*Bh). 128x128x32 CTA tile, 512 threads (16 warps, 4x4),
// 4-stage cp.async pipeline, compact rows (M = g_cum[B]).
// MODE 0: fp32 C.  MODE 4: fp16 hi-only C (after optional RELU), stride Nn.
// MODE 3: fused QKV epilogue: n<2048 -> qk hi/lo buffer (stride 2048);
//         n>=2048 -> V hi/lo transposed per batch: vt[(b*D+n-2048)*LT + pos].
// ---------------------------------------------------------------------------
template <int RELU, int MODE, int TERMS>
__global__ __launch_bounds__(512, 1) void gemm_mma(
    const __half* __restrict__ Ah, const __half* __restrict__ Al,
    const __half* __restrict__ Bh,
    const float* __restrict__ bias, const float* __restrict__ bias2,
    const float* __restrict__ bias3,
    float* __restrict__ Cf,
    __half* __restrict__ Ch, __half* __restrict__ Cl,
    __half* __restrict__ Ch2, __half* __restrict__ Cl2,
    int Nn, int Kn) {
    extern __shared__ char dynsmem[];
    uint32_t sbase = (s2u(dynsmem) + 1023u) & ~1023u;
    int tid = threadIdx.x;
    int wid = tid >> 5, lane = tid & 31;
    int m0 = blockIdx.y * 128, n0 = blockIdx.x * 128;
    const int Mc = g_cum[B_];
    if (m0 >= Mc) return;   // fully-pad tile (compact rows)

    int wm = wid & 3, wn = wid >> 2;     // 4x4 warp grid
    int m0w = wm * 32, n0w = wn * 32;
    const int T = Kn / BK_;

    int lrow = tid >> 2, lcol = tid & 3;   // loader: row 0..127, 16B chunk 0..3

    auto issue = [&](int kt) {
        uint32_t stb = sbase + (kt % STAGES_) * STAGE_B;
        uint32_t off = (uint32_t)(lrow * LDS_ + lcol * 8) * 2;
        int gr = m0 + lrow;
        bool vld = gr < Mc;
        size_t aofs = (size_t)(vld ? gr : 0) * Kn + kt * BK_ + lcol * 8;
        cp16(stb + off, Ah + aofs, vld ? 16 : 0);
        if (TERMS == 2)
            cp16(stb + ASZ_ + off, Al + aofs, vld ? 16 : 0);
        cp16(stb + 2 * ASZ_ + off,
             Bh + (size_t)(n0 + lrow) * Kn + kt * BK_ + lcol * 8, 16);
        cp_commit();
    };

    issue(0);
    issue(1);
    issue(2);

    float acc[2][4][4];
    #pragma unroll
    for (int i = 0; i < 2; i++)
        #pragma unroll
        for (int j = 0; j < 4; j++)
            #pragma unroll
            for (int p = 0; p < 4; p++) acc[i][j][p] = 0.f;

    int lr = lane & 15, lc8 = (lane >> 4) * 8;

    for (int kt = 0; kt < T; kt++) {
        cp_wait<STAGES_ - 2>();
        __syncthreads();
        uint32_t stb = sbase + (kt % STAGES_) * STAGE_B;
        #pragma unroll
        for (int kk = 0; kk < 2; kk++) {
            int koff = kk * 16 + lc8;
            uint32_t ah[2][4], al[2][4], bh[2][4];
            #pragma unroll
            for (int im = 0; im < 2; im++) {
                uint32_t ad = stb + (uint32_t)((m0w + im * 16 + lr) * LDS_ + koff) * 2;
                ldsm4(ah[im], ad);
                if (TERMS == 2) ldsm4(al[im], ad + ASZ_);
            }
            #pragma unroll
            for (int ib = 0; ib < 2; ib++) {
                uint32_t bd = stb + 2 * ASZ_ +
                              (uint32_t)((n0w + ib * 16 + lr) * LDS_ + koff) * 2;
                ldsm4(bh[ib], bd);
            }
            #pragma unroll
            for (int im = 0; im < 2; im++)
                #pragma unroll
                for (int in = 0; in < 4; in++) {
                    int ib = in >> 1, sb = in & 1;
                    mma16816(acc[im][in], ah[im], bh[ib][sb], bh[ib][sb + 2]);
                    if (TERMS == 2)
                        mma16816(acc[im][in], al[im], bh[ib][sb], bh[ib][sb + 2]);
                }
        }
        int nt = kt + STAGES_ - 1;
        if (nt < T) issue(nt); else cp_commit();
    }

    // Epilogue
    int g = lane >> 2, tq = lane & 3;
    #pragma unroll
    for (int in = 0; in < 4; in++) {
        int cb = n0 + n0w + in * 8 + tq * 2;
        float b0, b1;
        int section = cb >> 10;   // only meaningful for MODE 3
        if (MODE == 3) {
            const float* bp = (section == 0) ? bias : (section == 1) ? bias2 : bias3;
            b0 = __ldg(&bp[cb & 1023]);
            b1 = __ldg(&bp[(cb & 1023) + 1]);
        } else {
            b0 = __ldg(&bias[cb]);
            b1 = __ldg(&bias[cb + 1]);
        }
        #pragma unroll
        for (int im = 0; im < 2; im++) {
            #pragma unroll
            for (int hrow = 0; hrow < 2; hrow++) {
                int m = m0 + m0w + im * 16 + g + hrow * 8;
                if (m < Mc) {
                    float v0 = acc[im][in][hrow * 2 + 0] + b0;
                    float v1 = acc[im][in][hrow * 2 + 1] + b1;
                    if (RELU) { v0 = fmaxf(v0, 0.f); v1 = fmaxf(v1, 0.f); }
                    if (MODE == 0) {
                        *(float2*)&Cf[(size_t)m * Nn + cb] = make_float2(v0, v1);
                    } else if (MODE == 4) {
                        *(uint32_t*)&Ch[(size_t)m * Nn + cb] = packh(v0, v1);
                    } else {  // MODE 3
                        if (section < 2) {
                            uint32_t hw, lw;
                            packsplit(v0, v1, hw, lw);
                            *(uint32_t*)&Ch[(size_t)m * QKS_ + cb] = hw;
                            *(uint32_t*)&Cl[(size_t)m * QKS_ + cb] = lw;
                        } else {
                            int bb = g_rowb[m];
                            int pos = m - g_cum[bb];
                            int nn = cb & 1023;
                            size_t vt0 = ((size_t)bb * D_ + nn) * LT_ + pos;
                            __half h0 = __float2half(v0);
                            __half h1 = __float2half(v1);
                            Ch2[vt0]       = h0;
                            Ch2[vt0 + LT_] = h1;
                            Cl2[vt0]       = __float2half(v0 - __half2float(h0));
                            Cl2[vt0 + LT_] = __float2half(v1 - __half2float(h1));
                        }
                    }
                }
            }
        }
    }
}

// ---------------------------------------------------------------------------
// HMMA fp16 flash attention with 3-term hi/lo compensation (compact rows).
// Block: (q-tile 64, head, batch), 128 threads.
// Q/K from g_qkh/l (stride 2048; k at col offset 1024); V from g_vth/l.
// Writes hi-only output to g_ath (consumed by 1-term O GEMM).
// ---------------------------------------------------------------------------
__global__ __launch_bounds__(128, 1) void attn_mma_kernel() {
    extern __shared__ char asmem[];
    uint32_t sb = s2u(asmem);
    int tid = threadIdx.x, lane = tid & 31, w = tid >> 5;
    int qt = blockIdx.x, h = blockIdx.y, b = blockIdx.z;
    int q0 = qt * 64;
    int Lv = 2 + g_tlen[b] + g_slen[b];
    if (q0 >= Lv) return;
    int cumb = g_cum[b];
    const int NKT = (Lv + 63) >> 6;

    int lr = lane & 15, lc8 = (lane >> 4) * 8;
    int r = lane >> 2, tq = lane & 3;
    int lrow = tid >> 1, lhf = tid & 1;   // smem-fill: row, col-half

    // ---- stage Q (hi/lo) ----
    {
        int qrow = q0 + lrow; if (qrow > Lv - 1) qrow = Lv - 1;
        size_t off = (size_t)(cumb + qrow) * QKS_ + h * HD_ + lhf * 32;
        uint32_t dst = sb + (uint32_t)(lrow * ATS + lhf * 32) * 2;
        #pragma unroll
        for (int u = 0; u < 4; u++) {
            cp16(dst + u * 16,           g_qkh + off + u * 8, 16);
            cp16(dst + AT_TILE + u * 16, g_qkl + off + u * 8, 16);
        }
        cp_commit();
    }

    auto loadKV = [&](int kt) {
        uint32_t base = sb + ATT_ST0 + (kt & 1) * ATT_STG;
        int k0 = kt * 64;
        int krow = k0 + lrow; if (krow > Lv - 1) krow = Lv - 1;
        size_t koff = (size_t)(cumb + krow) * QKS_ + 1024 + h * HD_ + lhf * 32;
        uint32_t kdst = base + (uint32_t)(lrow * ATS + lhf * 32) * 2;
        #pragma unroll
        for (int u = 0; u < 4; u++) {
            cp16(kdst + u * 16,           g_qkh + koff + u * 8, 16);
            cp16(kdst + AT_TILE + u * 16, g_qkl + koff + u * 8, 16);
        }
        // V: row stride LT_ (16B-aligned); cols >= Lv are stale/zero but P=0.
        size_t voff = ((size_t)b * D_ + h * HD_ + lrow) * LT_ + k0 + lhf * 32;
        uint32_t vdst = base + 2 * AT_TILE + (uint32_t)(lrow * ATS + lhf * 32) * 2;
        #pragma unroll
        for (int u = 0; u < 4; u++) {
            int col = k0 + lhf * 32 + u * 8;
            int nb = (col < LT_) ? 16 : 0;   // zfill past padded length
            cp16(vdst + u * 16,           g_vth + voff + u * 8, nb);
            cp16(vdst + AT_TILE + u * 16, g_vtl + voff + u * 8, nb);
        }
        cp_commit();
    };

    loadKV(0);
    cp_wait<1>();           // Q staged (KV0 may still be in flight)
    __syncthreads();

    // Q fragments (held in registers for the whole kernel)
    uint32_t qfh[4][4], qfl[4][4];
    #pragma unroll
    for (int c = 0; c < 4; c++) {
        uint32_t ad = sb + (uint32_t)((w * 16 + lr) * ATS + c * 16 + lc8) * 2;
        ldsm4(qfh[c], ad);
        ldsm4(qfl[c], ad + AT_TILE);
    }

    float o[8][4];
    #pragma unroll
    for (int j = 0; j < 8; j++)
        #pragma unroll
        for (int p = 0; p < 4; p++) o[j][p] = 0.f;
    float mrA = -1e30f, mrB = -1e30f, lsA = 0.f, lsB = 0.f;

    for (int kt = 0; kt < NKT; kt++) {
        if (kt + 1 < NKT) { loadKV(kt + 1); cp_wait<1>(); }
        else              { cp_wait<0>(); }
        __syncthreads();
        uint32_t base = sb + ATT_ST0 + (kt & 1) * ATT_STG;
        int k0 = kt * 64;

        // ---- S = Q K^T (3-term) ----
        float s[8][4];
        #pragma unroll
        for (int j = 0; j < 8; j++)
            #pragma unroll
            for (int p = 0; p < 4; p++) s[j][p] = 0.f;

        #pragma unroll
        for (int c = 0; c < 4; c++) {
            #pragma unroll
            for (int ib = 0; ib < 4; ib++) {
                uint32_t bd = base + (uint32_t)((ib * 16 + lr) * ATS + c * 16 + lc8) * 2;
                uint32_t kbh[4], kbl[4];
                ldsm4(kbh, bd);
                ldsm4(kbl, bd + AT_TILE);
                #pragma unroll
                for (int sbn = 0; sbn < 2; sbn++) {
                    int j = ib * 2 + sbn;
                    mma16816(s[j], qfh[c], kbh[sbn], kbh[sbn + 2]);
                    mma16816(s[j], qfh[c], kbl[sbn], kbl[sbn + 2]);
                    mma16816(s[j], qfl[c], kbh[sbn], kbh[sbn + 2]);
                }
            }
        }

        // ---- scale + mask ----
        #pragma unroll
        for (int j = 0; j < 8; j++) {
            int c0 = k0 + j * 8 + 2 * tq, c1 = c0 + 1;
            s[j][0] = (c0 < Lv) ? s[j][0] * 0.125f : -1e9f;
            s[j][1] = (c1 < Lv) ? s[j][1] * 0.125f : -1e9f;
            s[j][2] = (c0 < Lv) ? s[j][2] * 0.125f : -1e9f;
            s[j][3] = (c1 < Lv) ? s[j][3] * 0.125f : -1e9f;
        }

        // ---- online softmax (rows r and r+8) ----
        float mA = -1e30f, mB = -1e30f;
        #pragma unroll
        for (int j = 0; j < 8; j++) {
            mA = fmaxf(mA, fmaxf(s[j][0], s[j][1]));
            mB = fmaxf(mB, fmaxf(s[j][2], s[j][3]));
        }
        mA = fmaxf(mA, __shfl_xor_sync(0xffffffffu, mA, 1));
        mA = fmaxf(mA, __shfl_xor_sync(0xffffffffu, mA, 2));
        mB = fmaxf(mB, __shfl_xor_sync(0xffffffffu, mB, 1));
        mB = fmaxf(mB, __shfl_xor_sync(0xffffffffu, mB, 2));
        float mnA = fmaxf(mrA, mA), mnB = fmaxf(mrB, mB);
        float aA = expf(mrA - mnA), aB = expf(mrB - mnB);
        float rsA = 0.f, rsB = 0.f;
        #pragma unroll
        for (int j = 0; j < 8; j++) {
            s[j][0] = expf(s[j][0] - mnA);
            s[j][1] = expf(s[j][1] - mnA);
            s[j][2] = expf(s[j][2] - mnB);
            s[j][3] = expf(s[j][3] - mnB);
            rsA += s[j][0] + s[j][1];
            rsB += s[j][2] + s[j][3];
        }
        rsA += __shfl_xor_sync(0xffffffffu, rsA, 1);
        rsA += __shfl_xor_sync(0xffffffffu, rsA, 2);
        rsB += __shfl_xor_sync(0xffffffffu, rsB, 1);
        rsB += __shfl_xor_sync(0xffffffffu, rsB, 2);
        lsA = lsA * aA + rsA;
        lsB = lsB * aB + rsB;
        mrA = mnA; mrB = mnB;
        #pragma unroll
        for (int j = 0; j < 8; j++) {
            o[j][0] *= aA; o[j][1] *= aA;
            o[j][2] *= aB; o[j][3] *= aB;
        }

        // ---- O += P V (3-term) ----
        #pragma unroll
        for (int c = 0; c < 4; c++) {
            uint32_t pah[4], pal[4];
            packsplit(s[2 * c][0],     s[2 * c][1],     pah[0], pal[0]);
            packsplit(s[2 * c][2],     s[2 * c][3],     pah[1], pal[1]);
            packsplit(s[2 * c + 1][0], s[2 * c + 1][1], pah[2], pal[2]);
            packsplit(s[2 * c + 1][2], s[2 * c + 1][3], pah[3], pal[3]);
            #pragma unroll
            for (int ib = 0; ib < 4; ib++) {
                uint32_t bd = base + 2 * AT_TILE +
                              (uint32_t)((ib * 16 + lr) * ATS + c * 16 + lc8) * 2;
                uint32_t vbh[4], vbl[4];
                ldsm4(vbh, bd);
                ldsm4(vbl, bd + AT_TILE);
                #pragma unroll
                for (int sbn = 0; sbn < 2; sbn++) {
                    int j = ib * 2 + sbn;
                    mma16816(o[j], pah, vbh[sbn], vbh[sbn + 2]);
                    mma16816(o[j], pal, vbh[sbn], vbh[sbn + 2]);
                    mma16816(o[j], pah, vbl[sbn], vbl[sbn + 2]);
                }
            }
        }
        __syncthreads();
    }

    // ---- write O (hi only; compact rows, only valid positions) ----
    float iA = 1.f / lsA, iB = 1.f / lsB;
    int qA = q0 + w * 16 + r, qB = qA + 8;
    #pragma unroll
    for (int j = 0; j < 8; j++) {
        int d = h * HD_ + j * 8 + 2 * tq;
        if (qA < Lv) {
            size_t off = (size_t)(cumb + qA) * D_ + d;
            *(uint32_t*)&g_ath[off] = packh(o[j][0] * iA, o[j][1] * iA);
        }
        if (qB < Lv) {
            size_t off = (size_t)(cumb + qB) * D_ + d;
            *(uint32_t*)&g_ath[off] = packh(o[j][2] * iB, o[j][3] * iB);
        }
    }
}

// ---------------------------------------------------------------------------
// x = LayerNorm(x + y) * s + b (in place) + fp16 hi/lo emission (compact rows).
// ---------------------------------------------------------------------------
__global__ __launch_bounds__(256) void add_ln_kernel(const float* __restrict__ sc,
                                                     const float* __restrict__ bi) {
    int row = blockIdx.x;
    if (row >= g_cum[B_]) return;
    size_t base = (size_t)row * D_;
    __shared__ float red[256];
    int tid = threadIdx.x;

    float v[4];
    float s = 0.f;
    #pragma unroll
    for (int u = 0; u < 4; u++) {
        int d = tid + u * 256;
        v[u] = g_x[base + d] + g_y[base + d];
        s += v[u];
    }
    red[tid] = s;
    __syncthreads();
    for (int off = 128; off > 0; off >>= 1) {
        if (tid < off) red[tid] += red[tid + off];
        __syncthreads();
    }
    float mean = red[0] * (1.f / D_);
    __syncthreads();

    float s2 = 0.f;
    #pragma unroll
    for (int u = 0; u < 4; u++) { float dd = v[u] - mean; s2 += dd * dd; }
    red[tid] = s2;
    __syncthreads();
    for (int off = 128; off > 0; off >>= 1) {
        if (tid < off) red[tid] += red[tid + off];
        __syncthreads();
    }
    float var = red[0] * (1.f / D_);
    float inv = rsqrtf(var + 1e-5f);

    #pragma unroll
    for (int u = 0; u < 4; u++) {
        int d = tid + u * 256;
        float t = (v[u] - mean) * inv * sc[d] + bi[d];
        g_x[base + d] = t;
        __half hh = __float2half(t);
        g_xh[base + d] = hh;
        g_xl[base + d] = __float2half(t - __half2float(hh));
    }
}

// ---------------------------------------------------------------------------
// out[b] = dot(x[cum[b], :], out_w)
// ---------------------------------------------------------------------------
__global__ __launch_bounds__(256) void final_kernel(const float* __restrict__ ow,
                                                    float* __restrict__ out) {
    int b = blockIdx.x;
    __shared__ float red[256];
    const float* xr = &g_x[(size_t)g_cum[b] * D_];
    int tid = threadIdx.x;
    float s = 0.f;
    for (int d = tid; d < D_; d += 256) s += xr[d] * ow[d];
    red[tid] = s;
    __syncthreads();
    for (int off = 128; off > 0; off >>= 1) {
        if (tid < off) red[tid] += red[tid + off];
        __syncthreads();
    }
    if (tid == 0) out[b] = red[0];
}

// ---------------------------------------------------------------------------
// Launch
// ---------------------------------------------------------------------------
extern "C" void kernel_launch(void* const* d_in, const int* in_sizes, int n_in,
                              void* d_out, int out_size) {
    const float* text   = (const float*)d_in[0];
    const float* speech = (const float*)d_in[1];
    const void*  tmask  = d_in[2];
    const void*  smask  = d_in[3];
    const float* cls    = (const float*)d_in[4];
    const float* sep    = (const float*)d_in[5];
    const float* Wq     = (const float*)d_in[6];
    const float* bq     = (const float*)d_in[7];
    const float* Wk     = (const float*)d_in[8];
    const float* bk     = (const float*)d_in[9];
    const float* Wv     = (const float*)d_in[10];
    const float* bv     = (const float*)d_in[11];
    const float* Wo     = (const float*)d_in[12];
    const float* bo     = (const float*)d_in[13];
    const float* ln1s   = (const float*)d_in[14];
    const float* ln1b   = (const float*)d_in[15];
    const float* f1w    = (const float*)d_in[16];
    const float* f1b    = (const float*)d_in[17];
    const float* f2w    = (const float*)d_in[18];
    const float* f2b    = (const float*)d_in[19];
    const float* ln2s   = (const float*)d_in[20];
    const float* ln2b   = (const float*)d_in[21];
    const float* outw   = (const float*)d_in[22];
    float* out = (float*)d_out;

    float* y;
    __half *xh, *xl, *qkh, *qkl, *vth, *vtl, *ath, *hh;
    __half *Wqkvh, *Woh, *F1h, *F2h;
    cudaGetSymbolAddress((void**)&y,     g_y);
    cudaGetSymbolAddress((void**)&xh,    g_xh);
    cudaGetSymbolAddress((void**)&xl,    g_xl);
    cudaGetSymbolAddress((void**)&qkh,   g_qkh);
    cudaGetSymbolAddress((void**)&qkl,   g_qkl);
    cudaGetSymbolAddress((void**)&vth,   g_vth);
    cudaGetSymbolAddress((void**)&vtl,   g_vtl);
    cudaGetSymbolAddress((void**)&ath,   g_ath);
    cudaGetSymbolAddress((void**)&hh,    g_hh);
    cudaGetSymbolAddress((void**)&Wqkvh, g_Wqkvh);
    cudaGetSymbolAddress((void**)&Woh,   g_Woh);
    cudaGetSymbolAddress((void**)&F1h,   g_F1h);
    cudaGetSymbolAddress((void**)&F2h,   g_F2h);

    cudaFuncSetAttribute(attn_mma_kernel,
                         cudaFuncAttributeMaxDynamicSharedMemorySize, ATT_SMEM);
    cudaFuncSetAttribute(gemm_mma<0, 3, 2>,
                         cudaFuncAttributeMaxDynamicSharedMemorySize, GEMM_SMEM);
    cudaFuncSetAttribute(gemm_mma<0, 0, 1>,
                         cudaFuncAttributeMaxDynamicSharedMemorySize, GEMM_SMEM);
    cudaFuncSetAttribute(gemm_mma<1, 4, 1>,
                         cudaFuncAttributeMaxDynamicSharedMemorySize, GEMM_SMEM);

    lengths_kernel<<<2, 256>>>(tmask, smask);
    cum_kernel<<<1, 32>>>();
    build_x_kernel<<<dim3(L_, B_), 256>>>(text, speech, cls, sep);
    wsplit_all_kernel<<<NL_ * WT_PER_LAYER, dim3(32, 8)>>>(Wq, Wk, Wv, Wo, f1w, f2w);

    int mt = (M_ + 127) / 128;  // 81 (static; CTAs past Mc self-skip)
    dim3 gQKV(3072 / 128, mt);
    dim3 gD(D_ / 128, mt);
    dim3 gF(F_ / 128, mt);
    dim3 gAtt((L_ + 63) / 64, H_, B_);

    for (int l = 0; l < NL_; l++) {
        size_t oqkv = (size_t)l * 3072 * 1024;
        size_t od = (size_t)l * D_ * D_;
        size_t o1 = (size_t)l * D_ * F_;
        size_t o2 = (size_t)l * F_ * D_;
        gemm_mma<0, 3, 2><<<gQKV, 512, GEMM_SMEM>>>(
            xh, xl, Wqkvh + oqkv,
            bq + l * D_, bk + l * D_, bv + l * D_,
            nullptr, qkh, qkl, vth, vtl, 3072, D_);
        attn_mma_kernel<<<gAtt, 128, ATT_SMEM>>>();
        gemm_mma<0, 0, 1><<<gD, 512, GEMM_SMEM>>>(
            ath, nullptr, Woh + od,
            bo + l * D_, nullptr, nullptr,
            y, nullptr, nullptr, nullptr, nullptr, D_, D_);
        add_ln_kernel<<<M_, 256>>>(ln1s + l * D_, ln1b + l * D_);
        gemm_mma<1, 4, 1><<<gF, 512, GEMM_SMEM>>>(
            xh, nullptr, F1h + o1,
            f1b + l * F_, nullptr, nullptr,
            nullptr, hh, nullptr, nullptr, nullptr, F_, D_);
        gemm_mma<0, 0, 1><<<gD, 512, GEMM_SMEM>>>(
            hh, nullptr, F2h + o2,
            f2b + l * D_, nullptr, nullptr,
            y, nullptr, nullptr, nullptr, nullptr, D_, F_);
        add_ln_kernel<<<M_, 256>>>(ln2s + l * D_, ln2b + l * D_);
    }
    final_kernel<<<B_, 256>>>(outw, out);
}

// round 15
// speedup vs baseline: 8.3590x; 1.1660x over previous
#include <cuda_runtime.h>
#include <cuda_fp16.h>
#include <math.h>
#include <stdint.h>

// ---------------------------------------------------------------------------
// Problem constants
// ---------------------------------------------------------------------------
namespace {
constexpr int B_  = 16;
constexpr int TT_ = 128;
constexpr int TS_ = 512;
constexpr int L_  = TT_ + TS_ + 2;   // 642
constexpr int LT_ = 648;             // vt row stride: multiple of 8 elems (16B)
constexpr int D_  = 1024;
constexpr int H_  = 16;
constexpr int HD_ = 64;
constexpr int F_  = 4096;
constexpr int NL_ = 4;
constexpr int M_  = B_ * L_;         // 10272
constexpr int QKS_ = 2048;           // fused q|k buffer row stride

// GEMM tiling (all 1-term: stages hold Ah, Bh)
constexpr int BK_     = 32;
constexpr int STAGES_ = 5;
constexpr int LDS_    = 40;                    // padded row stride (elements)
constexpr int ASZ_    = 128 * LDS_ * 2;        // 10240 bytes per tile array
constexpr int STAGE_B = 2 * ASZ_;              // 20480 bytes per stage
constexpr int GEMM_SMEM = STAGES_ * STAGE_B + 1024;  // 103424

// Attention tiling
constexpr int ATS      = 72;                   // smem row stride (elements)
constexpr int AT_TILE  = 64 * ATS * 2;         // 9216 bytes per 64x64 fp16 array
constexpr int ATT_ST0  = 2 * AT_TILE;          // Qh, Ql
constexpr int ATT_STG  = 4 * AT_TILE;          // Kh, Kl, Vth, Vtl per stage
constexpr int ATT_SMEM = ATT_ST0 + 2 * ATT_STG; // 92160

// fused wsplit decode
constexpr int WT_PER_LAYER = 4 * 1024 + 4096 + 4096;  // 12288 tiles/layer
}

// ---------------------------------------------------------------------------
// Scratch (allocation-free: __device__ globals; zero-initialized)
// ---------------------------------------------------------------------------
__device__ float g_x[(size_t)M_ * D_];
__device__ float g_y[(size_t)M_ * D_];
__device__ __half g_xh [(size_t)M_ * D_];
__device__ __half g_qkh[(size_t)M_ * QKS_];
__device__ __half g_qkl[(size_t)M_ * QKS_];
__device__ __half g_vth[(size_t)B_ * D_ * LT_ + 64];
__device__ __half g_vtl[(size_t)B_ * D_ * LT_ + 64];
__device__ __half g_ath[(size_t)M_ * D_];
__device__ __half g_hh [(size_t)M_ * F_];
// transposed fp16 weights ([N,K] layout), hi only; QKV concatenated (N=3072)
__device__ __half g_Wqkvh[(size_t)NL_ * 3072 * 1024];
__device__ __half g_Woh[(size_t)NL_ * D_ * D_];
__device__ __half g_F1h[(size_t)NL_ * D_ * F_];
__device__ __half g_F2h[(size_t)NL_ * F_ * D_];
__device__ int g_tlen[B_];
__device__ int g_slen[B_];
__device__ int g_cum[B_ + 1];
__device__ int g_rowb[M_];        // batch index of each compact row

// ---------------------------------------------------------------------------
// PTX helpers (sm_80-era subset only: cp.async, ldmatrix, mma.sync)
// ---------------------------------------------------------------------------
__device__ __forceinline__ uint32_t s2u(const void* p) {
    uint32_t a;
    asm("{ .reg .u64 t; cvta.to.shared.u64 t, %1; cvt.u32.u64 %0, t; }"
        : "=r"(a) : "l"(p));
    return a;
}
__device__ __forceinline__ void cp16(uint32_t s, const void* g, int nbytes) {
    asm volatile("cp.async.cg.shared.global [%0], [%1], 16, %2;"
                 :: "r"(s), "l"(g), "r"(nbytes));
}
__device__ __forceinline__ void cp_commit() {
    asm volatile("cp.async.commit_group;");
}
template <int N> __device__ __forceinline__ void cp_wait() {
    asm volatile("cp.async.wait_group %0;" :: "n"(N));
}
__device__ __forceinline__ void ldsm4(uint32_t* r, uint32_t addr) {
    asm volatile("ldmatrix.sync.aligned.m8n8.x4.shared.b16 {%0,%1,%2,%3}, [%4];"
                 : "=r"(r[0]), "=r"(r[1]), "=r"(r[2]), "=r"(r[3]) : "r"(addr));
}
__device__ __forceinline__ void mma16816(float* c, const uint32_t* a,
                                         uint32_t b0, uint32_t b1) {
    asm volatile(
        "mma.sync.aligned.m16n8k16.row.col.f32.f16.f16.f32 "
        "{%0,%1,%2,%3}, {%4,%5,%6,%7}, {%8,%9}, {%0,%1,%2,%3};\n"
        : "+f"(c[0]), "+f"(c[1]), "+f"(c[2]), "+f"(c[3])
        : "r"(a[0]), "r"(a[1]), "r"(a[2]), "r"(a[3]), "r"(b0), "r"(b1));
}
// split two fp32 into packed fp16x2 hi and lo words
__device__ __forceinline__ void packsplit(float x, float y,
                                          uint32_t& hi, uint32_t& lo) {
    __half hx = __float2half(x), hy = __float2half(y);
    __half2 hh = __halves2half2(hx, hy);
    __half2 ll = __halves2half2(__float2half(x - __half2float(hx)),
                                __float2half(y - __half2float(hy)));
    hi = *(uint32_t*)&hh;
    lo = *(uint32_t*)&ll;
}
__device__ __forceinline__ uint32_t packh(float x, float y) {
    __half2 hh = __halves2half2(__float2half(x), __float2half(y));
    return *(uint32_t*)&hh;
}

// ---------------------------------------------------------------------------
// Mask length computation with on-device dtype detection
// ---------------------------------------------------------------------------
__global__ void lengths_kernel(const void* tmask, const void* smask) {
    int which = blockIdx.x;
    const void* mask = which ? smask : tmask;
    int T = which ? TS_ : TT_;
    int* lens = which ? g_slen : g_tlen;
    int N = B_ * T;

    __shared__ int f3F, fMis;
    __shared__ int cnt[B_];
    int tid = threadIdx.x;
    if (tid == 0) { f3F = 0; fMis = 0; }
    if (tid < B_) cnt[tid] = 0;
    __syncthreads();

    const unsigned char* bytes = (const unsigned char*)mask;
    int l3 = 0, lm = 0;
    for (int i = tid; i < N; i += blockDim.x) {
        unsigned char c = bytes[i];
        if (c == 0x3F) l3 = 1;
        if (c == 1 && (i & 3)) lm = 1;
    }
    if (l3) atomicOr(&f3F, 1);
    if (lm) atomicOr(&fMis, 1);
    __syncthreads();

    if (fMis && !f3F) {
        for (int i = tid; i < N; i += blockDim.x)
            if (bytes[i] == 0) atomicAdd(&cnt[i / T], 1);
    } else {
        const unsigned int* w = (const unsigned int*)mask;
        for (int i = tid; i < N; i += blockDim.x)
            if (w[i] == 0u) atomicAdd(&cnt[i / T], 1);
    }
    __syncthreads();
    if (tid < B_) lens[tid] = cnt[tid];
}

// prefix sums of valid lengths
__global__ void cum_kernel() {
    if (threadIdx.x == 0) {
        int a = 0;
        for (int b = 0; b < B_; b++) {
            g_cum[b] = a;
            a += 2 + g_tlen[b] + g_slen[b];
        }
        g_cum[B_] = a;
    }
}

// ---------------------------------------------------------------------------
// Build COMPACT concatenated sequence x (fp32 + fp16 hi) + row->batch map
// ---------------------------------------------------------------------------
__global__ void build_x_kernel(const float* __restrict__ text,
                               const float* __restrict__ speech,
                               const float* __restrict__ cls,
                               const float* __restrict__ sep) {
    int pos = blockIdx.x, b = blockIdx.y;
    int tl = g_tlen[b], sl = g_slen[b];
    if (pos >= 2 + tl + sl) return;
    int row = g_cum[b] + pos;
    size_t base = (size_t)row * D_;
    if (threadIdx.x == 0) g_rowb[row] = b;

    const float* s;
    if (pos == 0)                 s = cls;
    else if (pos < 1 + tl)        s = &text  [((size_t)(pos - 1) * B_ + b) * D_];
    else if (pos == 1 + tl)       s = sep;
    else                          s = &speech[((size_t)(pos - 2 - tl) * B_ + b) * D_];

    for (int d = threadIdx.x; d < D_; d += blockDim.x) {
        float v = s[d];
        g_x[base + d] = v;
        g_xh[base + d] = __float2half(v);
    }
}

// ---------------------------------------------------------------------------
// Fused weight transpose + fp16 convert for ALL weights (one launch).
// ---------------------------------------------------------------------------
__global__ void wsplit_all_kernel(const float* __restrict__ Wq,
                                  const float* __restrict__ Wk,
                                  const float* __restrict__ Wv,
                                  const float* __restrict__ Wo,
                                  const float* __restrict__ F1,
                                  const float* __restrict__ F2) {
    int gidx = blockIdx.x;
    int l = gidx / WT_PER_LAYER;
    int r = gidx - l * WT_PER_LAYER;

    const float* W;
    __half* Th;
    int K, N, tile;
    if (r < 4096) {
        int type = r >> 10;           // 0=q 1=k 2=v 3=o
        tile = r & 1023;
        K = 1024; N = 1024;
        size_t wofs = (size_t)l * D_ * D_;
        if (type == 0)      { W = Wq + wofs; }
        else if (type == 1) { W = Wk + wofs; }
        else if (type == 2) { W = Wv + wofs; }
        else                { W = Wo + wofs; }
        if (type < 3)
            Th = g_Wqkvh + (size_t)l * 3072 * 1024 + (size_t)type * 1024 * 1024;
        else
            Th = g_Woh + (size_t)l * D_ * D_;
    } else if (r < 8192) {
        tile = r - 4096;
        K = 1024; N = 4096;
        W = F1 + (size_t)l * D_ * F_;
        Th = g_F1h + (size_t)l * D_ * F_;
    } else {
        tile = r - 8192;
        K = 4096; N = 1024;
        W = F2 + (size_t)l * F_ * D_;
        Th = g_F2h + (size_t)l * F_ * D_;
    }

    int ntiles = N >> 5;
    int n0 = (tile % ntiles) * 32;
    int k0 = (tile / ntiles) * 32;

    __shared__ float t[32][33];
    int tx = threadIdx.x, ty = threadIdx.y;
    #pragma unroll
    for (int j = 0; j < 4; j++) {
        int k = k0 + ty + j * 8;
        t[ty + j * 8][tx] = W[(size_t)k * N + n0 + tx];
    }
    __syncthreads();
    #pragma unroll
    for (int j = 0; j < 4; j++) {
        int n = n0 + ty + j * 8;
        Th[(size_t)n * K + k0 + tx] = __float2half(t[tx][ty + j * 8]);
    }
}

// ---------------------------------------------------------------------------
// HMMA fp16 GEMM, 1-term (C = Ah*Bh + bias), compact rows (M = g_cum[B]).
// 128x128x32 CTA tile, 512 threads (16 warps, 4x4), 5-stage cp.async pipeline.
// MODE 0: fp32 C.  MODE 4: fp16 hi-only C (after optional RELU), stride Nn.
// MODE 3: fused QKV epilogue: n<2048 -> qk hi/lo buffer (stride 2048);
//         n>=2048 -> V hi/lo transposed per batch: vt[(b*D+n-2048)*LT + pos].
// ---------------------------------------------------------------------------
template <int RELU, int MODE>
__global__ __launch_bounds__(512, 1) void gemm_mma(
    const __half* __restrict__ Ah,
    const __half* __restrict__ Bh,
    const float* __restrict__ bias, const float* __restrict__ bias2,
    const float* __restrict__ bias3,
    float* __restrict__ Cf,
    __half* __restrict__ Ch, __half* __restrict__ Cl,
    __half* __restrict__ Ch2, __half* __restrict__ Cl2,
    int Nn, int Kn) {
    extern __shared__ char dynsmem[];
    uint32_t sbase = (s2u(dynsmem) + 1023u) & ~1023u;
    int tid = threadIdx.x;
    int wid = tid >> 5, lane = tid & 31;
    int m0 = blockIdx.y * 128, n0 = blockIdx.x * 128;
    const int Mc = g_cum[B_];
    if (m0 >= Mc) return;   // fully-pad tile (compact rows)

    int wm = wid & 3, wn = wid >> 2;     // 4x4 warp grid
    int m0w = wm * 32, n0w = wn * 32;
    const int T = Kn / BK_;

    int lrow = tid >> 2, lcol = tid & 3;   // loader: row 0..127, 16B chunk 0..3

    auto issue = [&](int kt) {
        uint32_t stb = sbase + (kt % STAGES_) * STAGE_B;
        uint32_t off = (uint32_t)(lrow * LDS_ + lcol * 8) * 2;
        int gr = m0 + lrow;
        bool vld = gr < Mc;
        cp16(stb + off,
             Ah + (size_t)(vld ? gr : 0) * Kn + kt * BK_ + lcol * 8, vld ? 16 : 0);
        cp16(stb + ASZ_ + off,
             Bh + (size_t)(n0 + lrow) * Kn + kt * BK_ + lcol * 8, 16);
        cp_commit();
    };

    #pragma unroll
    for (int p = 0; p < STAGES_ - 1; p++)
        if (p < T) issue(p);

    float acc[2][4][4];
    #pragma unroll
    for (int i = 0; i < 2; i++)
        #pragma unroll
        for (int j = 0; j < 4; j++)
            #pragma unroll
            for (int p = 0; p < 4; p++) acc[i][j][p] = 0.f;

    int lr = lane & 15, lc8 = (lane >> 4) * 8;

    for (int kt = 0; kt < T; kt++) {
        cp_wait<STAGES_ - 2>();
        __syncthreads();
        uint32_t stb = sbase + (kt % STAGES_) * STAGE_B;
        #pragma unroll
        for (int kk = 0; kk < 2; kk++) {
            int koff = kk * 16 + lc8;
            uint32_t ah[2][4], bh[2][4];
            #pragma unroll
            for (int im = 0; im < 2; im++) {
                uint32_t ad = stb + (uint32_t)((m0w + im * 16 + lr) * LDS_ + koff) * 2;
                ldsm4(ah[im], ad);
            }
            #pragma unroll
            for (int ib = 0; ib < 2; ib++) {
                uint32_t bd = stb + ASZ_ +
                              (uint32_t)((n0w + ib * 16 + lr) * LDS_ + koff) * 2;
                ldsm4(bh[ib], bd);
            }
            #pragma unroll
            for (int im = 0; im < 2; im++)
                #pragma unroll
                for (int in = 0; in < 4; in++) {
                    int ib = in >> 1, sb = in & 1;
                    mma16816(acc[im][in], ah[im], bh[ib][sb], bh[ib][sb + 2]);
                }
        }
        int nt = kt + STAGES_ - 1;
        if (nt < T) issue(nt); else cp_commit();
    }

    // Epilogue
    int g = lane >> 2, tq = lane & 3;
    #pragma unroll
    for (int in = 0; in < 4; in++) {
        int cb = n0 + n0w + in * 8 + tq * 2;
        float b0, b1;
        int section = cb >> 10;   // only meaningful for MODE 3
        if (MODE == 3) {
            const float* bp = (section == 0) ? bias : (section == 1) ? bias2 : bias3;
            b0 = __ldg(&bp[cb & 1023]);
            b1 = __ldg(&bp[(cb & 1023) + 1]);
        } else {
            b0 = __ldg(&bias[cb]);
            b1 = __ldg(&bias[cb + 1]);
        }
        #pragma unroll
        for (int im = 0; im < 2; im++) {
            #pragma unroll
            for (int hrow = 0; hrow < 2; hrow++) {
                int m = m0 + m0w + im * 16 + g + hrow * 8;
                if (m < Mc) {
                    float v0 = acc[im][in][hrow * 2 + 0] + b0;
                    float v1 = acc[im][in][hrow * 2 + 1] + b1;
                    if (RELU) { v0 = fmaxf(v0, 0.f); v1 = fmaxf(v1, 0.f); }
                    if (MODE == 0) {
                        *(float2*)&Cf[(size_t)m * Nn + cb] = make_float2(v0, v1);
                    } else if (MODE == 4) {
                        *(uint32_t*)&Ch[(size_t)m * Nn + cb] = packh(v0, v1);
                    } else {  // MODE 3
                        if (section < 2) {
                            uint32_t hw, lw;
                            packsplit(v0, v1, hw, lw);
                            *(uint32_t*)&Ch[(size_t)m * QKS_ + cb] = hw;
                            *(uint32_t*)&Cl[(size_t)m * QKS_ + cb] = lw;
                        } else {
                            int bb = g_rowb[m];
                            int pos = m - g_cum[bb];
                            int nn = cb & 1023;
                            size_t vt0 = ((size_t)bb * D_ + nn) * LT_ + pos;
                            __half h0 = __float2half(v0);
                            __half h1 = __float2half(v1);
                            Ch2[vt0]       = h0;
                            Ch2[vt0 + LT_] = h1;
                            Cl2[vt0]       = __float2half(v0 - __half2float(h0));
                            Cl2[vt0 + LT_] = __float2half(v1 - __half2float(h1));
                        }
                    }
                }
            }
        }
    }
}

// ---------------------------------------------------------------------------
// HMMA fp16 flash attention with 3-term hi/lo compensation (compact rows).
// Block: (q-tile 64, head, batch), 128 threads.
// Q/K from g_qkh/l (stride 2048; k at col offset 1024); V from g_vth/l.
// Writes hi-only output to g_ath (consumed by 1-term O GEMM).
// ---------------------------------------------------------------------------
__global__ __launch_bounds__(128, 1) void attn_mma_kernel() {
    extern __shared__ char asmem[];
    uint32_t sb = s2u(asmem);
    int tid = threadIdx.x, lane = tid & 31, w = tid >> 5;
    int qt = blockIdx.x, h = blockIdx.y, b = blockIdx.z;
    int q0 = qt * 64;
    int Lv = 2 + g_tlen[b] + g_slen[b];
    if (q0 >= Lv) return;
    int cumb = g_cum[b];
    const int NKT = (Lv + 63) >> 6;

    int lr = lane & 15, lc8 = (lane >> 4) * 8;
    int r = lane >> 2, tq = lane & 3;
    int lrow = tid >> 1, lhf = tid & 1;   // smem-fill: row, col-half

    // ---- stage Q (hi/lo) ----
    {
        int qrow = q0 + lrow; if (qrow > Lv - 1) qrow = Lv - 1;
        size_t off = (size_t)(cumb + qrow) * QKS_ + h * HD_ + lhf * 32;
        uint32_t dst = sb + (uint32_t)(lrow * ATS + lhf * 32) * 2;
        #pragma unroll
        for (int u = 0; u < 4; u++) {
            cp16(dst + u * 16,           g_qkh + off + u * 8, 16);
            cp16(dst + AT_TILE + u * 16, g_qkl + off + u * 8, 16);
        }
        cp_commit();
    }

    auto loadKV = [&](int kt) {
        uint32_t base = sb + ATT_ST0 + (kt & 1) * ATT_STG;
        int k0 = kt * 64;
        int krow = k0 + lrow; if (krow > Lv - 1) krow = Lv - 1;
        size_t koff = (size_t)(cumb + krow) * QKS_ + 1024 + h * HD_ + lhf * 32;
        uint32_t kdst = base + (uint32_t)(lrow * ATS + lhf * 32) * 2;
        #pragma unroll
        for (int u = 0; u < 4; u++) {
            cp16(kdst + u * 16,           g_qkh + koff + u * 8, 16);
            cp16(kdst + AT_TILE + u * 16, g_qkl + koff + u * 8, 16);
        }
        // V: row stride LT_ (16B-aligned); cols >= Lv are stale/zero but P=0.
        size_t voff = ((size_t)b * D_ + h * HD_ + lrow) * LT_ + k0 + lhf * 32;
        uint32_t vdst = base + 2 * AT_TILE + (uint32_t)(lrow * ATS + lhf * 32) * 2;
        #pragma unroll
        for (int u = 0; u < 4; u++) {
            int col = k0 + lhf * 32 + u * 8;
            int nb = (col < LT_) ? 16 : 0;   // zfill past padded length
            cp16(vdst + u * 16,           g_vth + voff + u * 8, nb);
            cp16(vdst + AT_TILE + u * 16, g_vtl + voff + u * 8, nb);
        }
        cp_commit();
    };

    loadKV(0);
    cp_wait<1>();           // Q staged (KV0 may still be in flight)
    __syncthreads();

    // Q fragments (held in registers for the whole kernel)
    uint32_t qfh[4][4], qfl[4][4];
    #pragma unroll
    for (int c = 0; c < 4; c++) {
        uint32_t ad = sb + (uint32_t)((w * 16 + lr) * ATS + c * 16 + lc8) * 2;
        ldsm4(qfh[c], ad);
        ldsm4(qfl[c], ad + AT_TILE);
    }

    float o[8][4];
    #pragma unroll
    for (int j = 0; j < 8; j++)
        #pragma unroll
        for (int p = 0; p < 4; p++) o[j][p] = 0.f;
    float mrA = -1e30f, mrB = -1e30f, lsA = 0.f, lsB = 0.f;

    for (int kt = 0; kt < NKT; kt++) {
        if (kt + 1 < NKT) { loadKV(kt + 1); cp_wait<1>(); }
        else              { cp_wait<0>(); }
        __syncthreads();
        uint32_t base = sb + ATT_ST0 + (kt & 1) * ATT_STG;
        int k0 = kt * 64;

        // ---- S = Q K^T (3-term) ----
        float s[8][4];
        #pragma unroll
        for (int j = 0; j < 8; j++)
            #pragma unroll
            for (int p = 0; p < 4; p++) s[j][p] = 0.f;

        #pragma unroll
        for (int c = 0; c < 4; c++) {
            #pragma unroll
            for (int ib = 0; ib < 4; ib++) {
                uint32_t bd = base + (uint32_t)((ib * 16 + lr) * ATS + c * 16 + lc8) * 2;
                uint32_t kbh[4], kbl[4];
                ldsm4(kbh, bd);
                ldsm4(kbl, bd + AT_TILE);
                #pragma unroll
                for (int sbn = 0; sbn < 2; sbn++) {
                    int j = ib * 2 + sbn;
                    mma16816(s[j], qfh[c], kbh[sbn], kbh[sbn + 2]);
                    mma16816(s[j], qfh[c], kbl[sbn], kbl[sbn + 2]);
                    mma16816(s[j], qfl[c], kbh[sbn], kbh[sbn + 2]);
                }
            }
        }

        // ---- scale + mask ----
        #pragma unroll
        for (int j = 0; j < 8; j++) {
            int c0 = k0 + j * 8 + 2 * tq, c1 = c0 + 1;
            s[j][0] = (c0 < Lv) ? s[j][0] * 0.125f : -1e9f;
            s[j][1] = (c1 < Lv) ? s[j][1] * 0.125f : -1e9f;
            s[j][2] = (c0 < Lv) ? s[j][2] * 0.125f : -1e9f;
            s[j][3] = (c1 < Lv) ? s[j][3] * 0.125f : -1e9f;
        }

        // ---- online softmax (rows r and r+8) ----
        float mA = -1e30f, mB = -1e30f;
        #pragma unroll
        for (int j = 0; j < 8; j++) {
            mA = fmaxf(mA, fmaxf(s[j][0], s[j][1]));
            mB = fmaxf(mB, fmaxf(s[j][2], s[j][3]));
        }
        mA = fmaxf(mA, __shfl_xor_sync(0xffffffffu, mA, 1));
        mA = fmaxf(mA, __shfl_xor_sync(0xffffffffu, mA, 2));
        mB = fmaxf(mB, __shfl_xor_sync(0xffffffffu, mB, 1));
        mB = fmaxf(mB, __shfl_xor_sync(0xffffffffu, mB, 2));
        float mnA = fmaxf(mrA, mA), mnB = fmaxf(mrB, mB);
        float aA = expf(mrA - mnA), aB = expf(mrB - mnB);
        float rsA = 0.f, rsB = 0.f;
        #pragma unroll
        for (int j = 0; j < 8; j++) {
            s[j][0] = expf(s[j][0] - mnA);
            s[j][1] = expf(s[j][1] - mnA);
            s[j][2] = expf(s[j][2] - mnB);
            s[j][3] = expf(s[j][3] - mnB);
            rsA += s[j][0] + s[j][1];
            rsB += s[j][2] + s[j][3];
        }
        rsA += __shfl_xor_sync(0xffffffffu, rsA, 1);
        rsA += __shfl_xor_sync(0xffffffffu, rsA, 2);
        rsB += __shfl_xor_sync(0xffffffffu, rsB, 1);
        rsB += __shfl_xor_sync(0xffffffffu, rsB, 2);
        lsA = lsA * aA + rsA;
        lsB = lsB * aB + rsB;
        mrA = mnA; mrB = mnB;
        #pragma unroll
        for (int j = 0; j < 8; j++) {
            o[j][0] *= aA; o[j][1] *= aA;
            o[j][2] *= aB; o[j][3] *= aB;
        }

        // ---- O += P V (3-term) ----
        #pragma unroll
        for (int c = 0; c < 4; c++) {
            uint32_t pah[4], pal[4];
            packsplit(s[2 * c][0],     s[2 * c][1],     pah[0], pal[0]);
            packsplit(s[2 * c][2],     s[2 * c][3],     pah[1], pal[1]);
            packsplit(s[2 * c + 1][0], s[2 * c + 1][1], pah[2], pal[2]);
            packsplit(s[2 * c + 1][2], s[2 * c + 1][3], pah[3], pal[3]);
            #pragma unroll
            for (int ib = 0; ib < 4; ib++) {
                uint32_t bd = base + 2 * AT_TILE +
                              (uint32_t)((ib * 16 + lr) * ATS + c * 16 + lc8) * 2;
                uint32_t vbh[4], vbl[4];
                ldsm4(vbh, bd);
                ldsm4(vbl, bd + AT_TILE);
                #pragma unroll
                for (int sbn = 0; sbn < 2; sbn++) {
                    int j = ib * 2 + sbn;
                    mma16816(o[j], pah, vbh[sbn], vbh[sbn + 2]);
                    mma16816(o[j], pal, vbh[sbn], vbh[sbn + 2]);
                    mma16816(o[j], pah, vbl[sbn], vbl[sbn + 2]);
                }
            }
        }
        __syncthreads();
    }

    // ---- write O (hi only; compact rows, only valid positions) ----
    float iA = 1.f / lsA, iB = 1.f / lsB;
    int qA = q0 + w * 16 + r, qB = qA + 8;
    #pragma unroll
    for (int j = 0; j < 8; j++) {
        int d = h * HD_ + j * 8 + 2 * tq;
        if (qA < Lv) {
            size_t off = (size_t)(cumb + qA) * D_ + d;
            *(uint32_t*)&g_ath[off] = packh(o[j][0] * iA, o[j][1] * iA);
        }
        if (qB < Lv) {
            size_t off = (size_t)(cumb + qB) * D_ + d;
            *(uint32_t*)&g_ath[off] = packh(o[j][2] * iB, o[j][3] * iB);
        }
    }
}

// ---------------------------------------------------------------------------
// x = LayerNorm(x + y) * s + b (in place) + fp16 hi emission (compact rows).
// ---------------------------------------------------------------------------
__global__ __launch_bounds__(256) void add_ln_kernel(const float* __restrict__ sc,
                                                     const float* __restrict__ bi) {
    int row = blockIdx.x;
    if (row >= g_cum[B_]) return;
    size_t base = (size_t)row * D_;
    __shared__ float red[256];
    int tid = threadIdx.x;

    float v[4];
    float s = 0.f;
    #pragma unroll
    for (int u = 0; u < 4; u++) {
        int d = tid + u * 256;
        v[u] = g_x[base + d] + g_y[base + d];
        s += v[u];
    }
    red[tid] = s;
    __syncthreads();
    for (int off = 128; off > 0; off >>= 1) {
        if (tid < off) red[tid] += red[tid + off];
        __syncthreads();
    }
    float mean = red[0] * (1.f / D_);
    __syncthreads();

    float s2 = 0.f;
    #pragma unroll
    for (int u = 0; u < 4; u++) { float dd = v[u] - mean; s2 += dd * dd; }
    red[tid] = s2;
    __syncthreads();
    for (int off = 128; off > 0; off >>= 1) {
        if (tid < off) red[tid] += red[tid + off];
        __syncthreads();
    }
    float var = red[0] * (1.f / D_);
    float inv = rsqrtf(var + 1e-5f);

    #pragma unroll
    for (int u = 0; u < 4; u++) {
        int d = tid + u * 256;
        float t = (v[u] - mean) * inv * sc[d] + bi[d];
        g_x[base + d] = t;
        g_xh[base + d] = __float2half(t);
    }
}

// ---------------------------------------------------------------------------
// out[b] = dot(x[cum[b], :], out_w)
// ---------------------------------------------------------------------------
__global__ __launch_bounds__(256) void final_kernel(const float* __restrict__ ow,
                                                    float* __restrict__ out) {
    int b = blockIdx.x;
    __shared__ float red[256];
    const float* xr = &g_x[(size_t)g_cum[b] * D_];
    int tid = threadIdx.x;
    float s = 0.f;
    for (int d = tid; d < D_; d += 256) s += xr[d] * ow[d];
    red[tid] = s;
    __syncthreads();
    for (int off = 128; off > 0; off >>= 1) {
        if (tid < off) red[tid] += red[tid + off];
        __syncthreads();
    }
    if (tid == 0) out[b] = red[0];
}

// ---------------------------------------------------------------------------
// Launch
// ---------------------------------------------------------------------------
extern "C" void kernel_launch(void* const* d_in, const int* in_sizes, int n_in,
                              void* d_out, int out_size) {
    const float* text   = (const float*)d_in[0];
    const float* speech = (const float*)d_in[1];
    const void*  tmask  = d_in[2];
    const void*  smask  = d_in[3];
    const float* cls    = (const float*)d_in[4];
    const float* sep    = (const float*)d_in[5];
    const float* Wq     = (const float*)d_in[6];
    const float* bq     = (const float*)d_in[7];
    const float* Wk     = (const float*)d_in[8];
    const float* bk     = (const float*)d_in[9];
    const float* Wv     = (const float*)d_in[10];
    const float* bv     = (const float*)d_in[11];
    const float* Wo     = (const float*)d_in[12];
    const float* bo     = (const float*)d_in[13];
    const float* ln1s   = (const float*)d_in[14];
    const float* ln1b   = (const float*)d_in[15];
    const float* f1w    = (const float*)d_in[16];
    const float* f1b    = (const float*)d_in[17];
    const float* f2w    = (const float*)d_in[18];
    const float* f2b    = (const float*)d_in[19];
    const float* ln2s   = (const float*)d_in[20];
    const float* ln2b   = (const float*)d_in[21];
    const float* outw   = (const float*)d_in[22];
    float* out = (float*)d_out;

    float* y;
    __half *xh, *qkh, *qkl, *vth, *vtl, *ath, *hh;
    __half *Wqkvh, *Woh, *F1h, *F2h;
    cudaGetSymbolAddress((void**)&y,     g_y);
    cudaGetSymbolAddress((void**)&xh,    g_xh);
    cudaGetSymbolAddress((void**)&qkh,   g_qkh);
    cudaGetSymbolAddress((void**)&qkl,   g_qkl);
    cudaGetSymbolAddress((void**)&vth,   g_vth);
    cudaGetSymbolAddress((void**)&vtl,   g_vtl);
    cudaGetSymbolAddress((void**)&ath,   g_ath);
    cudaGetSymbolAddress((void**)&hh,    g_hh);
    cudaGetSymbolAddress((void**)&Wqkvh, g_Wqkvh);
    cudaGetSymbolAddress((void**)&Woh,   g_Woh);
    cudaGetSymbolAddress((void**)&F1h,   g_F1h);
    cudaGetSymbolAddress((void**)&F2h,   g_F2h);

    cudaFuncSetAttribute(attn_mma_kernel,
                         cudaFuncAttributeMaxDynamicSharedMemorySize, ATT_SMEM);
    cudaFuncSetAttribute(gemm_mma<0, 3>,
                         cudaFuncAttributeMaxDynamicSharedMemorySize, GEMM_SMEM);
    cudaFuncSetAttribute(gemm_mma<0, 0>,
                         cudaFuncAttributeMaxDynamicSharedMemorySize, GEMM_SMEM);
    cudaFuncSetAttribute(gemm_mma<1, 4>,
                         cudaFuncAttributeMaxDynamicSharedMemorySize, GEMM_SMEM);

    lengths_kernel<<<2, 256>>>(tmask, smask);
    cum_kernel<<<1, 32>>>();
    build_x_kernel<<<dim3(L_, B_), 256>>>(text, speech, cls, sep);
    wsplit_all_kernel<<<NL_ * WT_PER_LAYER, dim3(32, 8)>>>(Wq, Wk, Wv, Wo, f1w, f2w);

    int mt = (M_ + 127) / 128;  // 81 (static; CTAs past Mc self-skip)
    dim3 gQKV(3072 / 128, mt);
    dim3 gD(D_ / 128, mt);
    dim3 gF(F_ / 128, mt);
    dim3 gAtt((L_ + 63) / 64, H_, B_);

    for (int l = 0; l < NL_; l++) {
        size_t oqkv = (size_t)l * 3072 * 1024;
        size_t od = (size_t)l * D_ * D_;
        size_t o1 = (size_t)l * D_ * F_;
        size_t o2 = (size_t)l * F_ * D_;
        gemm_mma<0, 3><<<gQKV, 512, GEMM_SMEM>>>(
            xh, Wqkvh + oqkv,
            bq + l * D_, bk + l * D_, bv + l * D_,
            nullptr, qkh, qkl, vth, vtl, 3072, D_);
        attn_mma_kernel<<<gAtt, 128, ATT_SMEM>>>();
        gemm_mma<0, 0><<<gD, 512, GEMM_SMEM>>>(
            ath, Woh + od,
            bo + l * D_, nullptr, nullptr,
            y, nullptr, nullptr, nullptr, nullptr, D_, D_);
        add_ln_kernel<<<M_, 256>>>(ln1s + l * D_, ln1b + l * D_);
        gemm_mma<1, 4><<<gF, 512, GEMM_SMEM>>>(
            xh, F1h + o1,
            f1b + l * F_, nullptr, nullptr,
            nullptr, hh, nullptr, nullptr, nullptr, F_, D_);
        gemm_mma<0, 0><<<gD, 512, GEMM_SMEM>>>(
            hh, F2h + o2,
            f2b + l * D_, nullptr, nullptr,
            y, nullptr, nullptr, nullptr, nullptr, D_, F_);
        add_ln_kernel<<<M_, 256>>>(ln2s + l * D_, ln2b + l * D_);
    }
    final_kernel<<<B_, 256>>>(outw, out);
}

// round 16
// speedup vs baseline: 8.9426x; 1.0698x over previous
#include <cuda_runtime.h>
#include <cuda_fp16.h>
#include <math.h>
#include <stdint.h>

// ---------------------------------------------------------------------------
// Problem constants
// ---------------------------------------------------------------------------
namespace {
constexpr int B_  = 16;
constexpr int TT_ = 128;
constexpr int TS_ = 512;
constexpr int L_  = TT_ + TS_ + 2;   // 642
constexpr int LT_ = 648;             // vt row stride: multiple of 8 elems (16B)
constexpr int D_  = 1024;
constexpr int H_  = 16;
constexpr int HD_ = 64;
constexpr int F_  = 4096;
constexpr int NL_ = 4;
constexpr int M_  = B_ * L_;         // 10272
constexpr int QKS_ = 2048;           // fused q|k buffer row stride

// GEMM tiling (all 1-term: stages hold Ah, Bh)
constexpr int BK_     = 32;
constexpr int STAGES_ = 5;
constexpr int LDS_    = 40;                    // padded row stride (elements)
constexpr int ASZ_    = 128 * LDS_ * 2;        // 10240 bytes per tile array
constexpr int STAGE_B = 2 * ASZ_;              // 20480 bytes per stage
constexpr int GEMM_SMEM = STAGES_ * STAGE_B + 1024;  // 103424

// Attention tiling (2-term: Q hi/lo resident; stages hold Kh, Vth only)
constexpr int ATS      = 72;                   // smem row stride (elements)
constexpr int AT_TILE  = 64 * ATS * 2;         // 9216 bytes per 64x64 fp16 array
constexpr int ATT_ST0  = 2 * AT_TILE;          // Qh, Ql
constexpr int ATT_STG  = 2 * AT_TILE;          // Kh, Vth per stage
constexpr int ATT_SMEM = ATT_ST0 + 2 * ATT_STG; // 55296 -> 4 CTAs/SM

// fused wsplit decode
constexpr int WT_PER_LAYER = 4 * 1024 + 4096 + 4096;  // 12288 tiles/layer
}

// ---------------------------------------------------------------------------
// Scratch (allocation-free: __device__ globals; zero-initialized)
// ---------------------------------------------------------------------------
__device__ float g_x[(size_t)M_ * D_];
__device__ float g_y[(size_t)M_ * D_];
__device__ __half g_xh [(size_t)M_ * D_];
__device__ __half g_qkh[(size_t)M_ * QKS_];
__device__ __half g_qkl[(size_t)M_ * QKS_];
__device__ __half g_vth[(size_t)B_ * D_ * LT_ + 64];
__device__ __half g_ath[(size_t)M_ * D_];
__device__ __half g_hh [(size_t)M_ * F_];
// transposed fp16 weights ([N,K] layout), hi only; QKV concatenated (N=3072)
__device__ __half g_Wqkvh[(size_t)NL_ * 3072 * 1024];
__device__ __half g_Woh[(size_t)NL_ * D_ * D_];
__device__ __half g_F1h[(size_t)NL_ * D_ * F_];
__device__ __half g_F2h[(size_t)NL_ * F_ * D_];
__device__ int g_tlen[B_];
__device__ int g_slen[B_];
__device__ int g_cum[B_ + 1];
__device__ int g_rowb[M_];        // batch index of each compact row

// ---------------------------------------------------------------------------
// PTX helpers (sm_80-era subset only: cp.async, ldmatrix, mma.sync)
// ---------------------------------------------------------------------------
__device__ __forceinline__ uint32_t s2u(const void* p) {
    uint32_t a;
    asm("{ .reg .u64 t; cvta.to.shared.u64 t, %1; cvt.u32.u64 %0, t; }"
        : "=r"(a) : "l"(p));
    return a;
}
__device__ __forceinline__ void cp16(uint32_t s, const void* g, int nbytes) {
    asm volatile("cp.async.cg.shared.global [%0], [%1], 16, %2;"
                 :: "r"(s), "l"(g), "r"(nbytes));
}
__device__ __forceinline__ void cp_commit() {
    asm volatile("cp.async.commit_group;");
}
template <int N> __device__ __forceinline__ void cp_wait() {
    asm volatile("cp.async.wait_group %0;" :: "n"(N));
}
__device__ __forceinline__ void ldsm4(uint32_t* r, uint32_t addr) {
    asm volatile("ldmatrix.sync.aligned.m8n8.x4.shared.b16 {%0,%1,%2,%3}, [%4];"
                 : "=r"(r[0]), "=r"(r[1]), "=r"(r[2]), "=r"(r[3]) : "r"(addr));
}
__device__ __forceinline__ void mma16816(float* c, const uint32_t* a,
                                         uint32_t b0, uint32_t b1) {
    asm volatile(
        "mma.sync.aligned.m16n8k16.row.col.f32.f16.f16.f32 "
        "{%0,%1,%2,%3}, {%4,%5,%6,%7}, {%8,%9}, {%0,%1,%2,%3};\n"
        : "+f"(c[0]), "+f"(c[1]), "+f"(c[2]), "+f"(c[3])
        : "r"(a[0]), "r"(a[1]), "r"(a[2]), "r"(a[3]), "r"(b0), "r"(b1));
}
// split two fp32 into packed fp16x2 hi and lo words
__device__ __forceinline__ void packsplit(float x, float y,
                                          uint32_t& hi, uint32_t& lo) {
    __half hx = __float2half(x), hy = __float2half(y);
    __half2 hh = __halves2half2(hx, hy);
    __half2 ll = __halves2half2(__float2half(x - __half2float(hx)),
                                __float2half(y - __half2float(hy)));
    hi = *(uint32_t*)&hh;
    lo = *(uint32_t*)&ll;
}
__device__ __forceinline__ uint32_t packh(float x, float y) {
    __half2 hh = __halves2half2(__float2half(x), __float2half(y));
    return *(uint32_t*)&hh;
}

// ---------------------------------------------------------------------------
// Mask length computation with on-device dtype detection
// ---------------------------------------------------------------------------
__global__ void lengths_kernel(const void* tmask, const void* smask) {
    int which = blockIdx.x;
    const void* mask = which ? smask : tmask;
    int T = which ? TS_ : TT_;
    int* lens = which ? g_slen : g_tlen;
    int N = B_ * T;

    __shared__ int f3F, fMis;
    __shared__ int cnt[B_];
    int tid = threadIdx.x;
    if (tid == 0) { f3F = 0; fMis = 0; }
    if (tid < B_) cnt[tid] = 0;
    __syncthreads();

    const unsigned char* bytes = (const unsigned char*)mask;
    int l3 = 0, lm = 0;
    for (int i = tid; i < N; i += blockDim.x) {
        unsigned char c = bytes[i];
        if (c == 0x3F) l3 = 1;
        if (c == 1 && (i & 3)) lm = 1;
    }
    if (l3) atomicOr(&f3F, 1);
    if (lm) atomicOr(&fMis, 1);
    __syncthreads();

    if (fMis && !f3F) {
        for (int i = tid; i < N; i += blockDim.x)
            if (bytes[i] == 0) atomicAdd(&cnt[i / T], 1);
    } else {
        const unsigned int* w = (const unsigned int*)mask;
        for (int i = tid; i < N; i += blockDim.x)
            if (w[i] == 0u) atomicAdd(&cnt[i / T], 1);
    }
    __syncthreads();
    if (tid < B_) lens[tid] = cnt[tid];
}

// prefix sums of valid lengths
__global__ void cum_kernel() {
    if (threadIdx.x == 0) {
        int a = 0;
        for (int b = 0; b < B_; b++) {
            g_cum[b] = a;
            a += 2 + g_tlen[b] + g_slen[b];
        }
        g_cum[B_] = a;
    }
}

// ---------------------------------------------------------------------------
// Build COMPACT concatenated sequence x (fp32 + fp16 hi) + row->batch map
// ---------------------------------------------------------------------------
__global__ void build_x_kernel(const float* __restrict__ text,
                               const float* __restrict__ speech,
                               const float* __restrict__ cls,
                               const float* __restrict__ sep) {
    int pos = blockIdx.x, b = blockIdx.y;
    int tl = g_tlen[b], sl = g_slen[b];
    if (pos >= 2 + tl + sl) return;
    int row = g_cum[b] + pos;
    size_t base = (size_t)row * D_;
    if (threadIdx.x == 0) g_rowb[row] = b;

    const float* s;
    if (pos == 0)                 s = cls;
    else if (pos < 1 + tl)        s = &text  [((size_t)(pos - 1) * B_ + b) * D_];
    else if (pos == 1 + tl)       s = sep;
    else                          s = &speech[((size_t)(pos - 2 - tl) * B_ + b) * D_];

    for (int d = threadIdx.x; d < D_; d += blockDim.x) {
        float v = s[d];
        g_x[base + d] = v;
        g_xh[base + d] = __float2half(v);
    }
}

// ---------------------------------------------------------------------------
// Fused weight transpose + fp16 convert for ALL weights (one launch).
// ---------------------------------------------------------------------------
__global__ void wsplit_all_kernel(const float* __restrict__ Wq,
                                  const float* __restrict__ Wk,
                                  const float* __restrict__ Wv,
                                  const float* __restrict__ Wo,
                                  const float* __restrict__ F1,
                                  const float* __restrict__ F2) {
    int gidx = blockIdx.x;
    int l = gidx / WT_PER_LAYER;
    int r = gidx - l * WT_PER_LAYER;

    const float* W;
    __half* Th;
    int K, N, tile;
    if (r < 4096) {
        int type = r >> 10;           // 0=q 1=k 2=v 3=o
        tile = r & 1023;
        K = 1024; N = 1024;
        size_t wofs = (size_t)l * D_ * D_;
        if (type == 0)      { W = Wq + wofs; }
        else if (type == 1) { W = Wk + wofs; }
        else if (type == 2) { W = Wv + wofs; }
        else                { W = Wo + wofs; }
        if (type < 3)
            Th = g_Wqkvh + (size_t)l * 3072 * 1024 + (size_t)type * 1024 * 1024;
        else
            Th = g_Woh + (size_t)l * D_ * D_;
    } else if (r < 8192) {
        tile = r - 4096;
        K = 1024; N = 4096;
        W = F1 + (size_t)l * D_ * F_;
        Th = g_F1h + (size_t)l * D_ * F_;
    } else {
        tile = r - 8192;
        K = 4096; N = 1024;
        W = F2 + (size_t)l * F_ * D_;
        Th = g_F2h + (size_t)l * F_ * D_;
    }

    int ntiles = N >> 5;
    int n0 = (tile % ntiles) * 32;
    int k0 = (tile / ntiles) * 32;

    __shared__ float t[32][33];
    int tx = threadIdx.x, ty = threadIdx.y;
    #pragma unroll
    for (int j = 0; j < 4; j++) {
        int k = k0 + ty + j * 8;
        t[ty + j * 8][tx] = W[(size_t)k * N + n0 + tx];
    }
    __syncthreads();
    #pragma unroll
    for (int j = 0; j < 4; j++) {
        int n = n0 + ty + j * 8;
        Th[(size_t)n * K + k0 + tx] = __float2half(t[tx][ty + j * 8]);
    }
}

// ---------------------------------------------------------------------------
// HMMA fp16 GEMM, 1-term (C = Ah*Bh + bias), compact rows (M = g_cum[B]).
// 128x128x32 CTA tile, 512 threads (16 warps, 4x4), 5-stage cp.async pipeline.
// MODE 0: fp32 C.  MODE 4: fp16 hi-only C (after optional RELU), stride Nn.
// MODE 3: fused QKV epilogue: n<2048 -> qk hi/lo buffer (stride 2048);
//         n>=2048 -> V hi transposed per batch: vt[(b*D+n-2048)*LT + pos].
// ---------------------------------------------------------------------------
template <int RELU, int MODE>
__global__ __launch_bounds__(512, 1) void gemm_mma(
    const __half* __restrict__ Ah,
    const __half* __restrict__ Bh,
    const float* __restrict__ bias, const float* __restrict__ bias2,
    const float* __restrict__ bias3,
    float* __restrict__ Cf,
    __half* __restrict__ Ch, __half* __restrict__ Cl,
    __half* __restrict__ Ch2,
    int Nn, int Kn) {
    extern __shared__ char dynsmem[];
    uint32_t sbase = (s2u(dynsmem) + 1023u) & ~1023u;
    int tid = threadIdx.x;
    int wid = tid >> 5, lane = tid & 31;
    int m0 = blockIdx.y * 128, n0 = blockIdx.x * 128;
    const int Mc = g_cum[B_];
    if (m0 >= Mc) return;   // fully-pad tile (compact rows)

    int wm = wid & 3, wn = wid >> 2;     // 4x4 warp grid
    int m0w = wm * 32, n0w = wn * 32;
    const int T = Kn / BK_;

    int lrow = tid >> 2, lcol = tid & 3;   // loader: row 0..127, 16B chunk 0..3

    auto issue = [&](int kt) {
        uint32_t stb = sbase + (kt % STAGES_) * STAGE_B;
        uint32_t off = (uint32_t)(lrow * LDS_ + lcol * 8) * 2;
        int gr = m0 + lrow;
        bool vld = gr < Mc;
        cp16(stb + off,
             Ah + (size_t)(vld ? gr : 0) * Kn + kt * BK_ + lcol * 8, vld ? 16 : 0);
        cp16(stb + ASZ_ + off,
             Bh + (size_t)(n0 + lrow) * Kn + kt * BK_ + lcol * 8, 16);
        cp_commit();
    };

    #pragma unroll
    for (int p = 0; p < STAGES_ - 1; p++)
        if (p < T) issue(p);

    float acc[2][4][4];
    #pragma unroll
    for (int i = 0; i < 2; i++)
        #pragma unroll
        for (int j = 0; j < 4; j++)
            #pragma unroll
            for (int p = 0; p < 4; p++) acc[i][j][p] = 0.f;

    int lr = lane & 15, lc8 = (lane >> 4) * 8;

    for (int kt = 0; kt < T; kt++) {
        cp_wait<STAGES_ - 2>();
        __syncthreads();
        uint32_t stb = sbase + (kt % STAGES_) * STAGE_B;
        #pragma unroll
        for (int kk = 0; kk < 2; kk++) {
            int koff = kk * 16 + lc8;
            uint32_t ah[2][4], bh[2][4];
            #pragma unroll
            for (int im = 0; im < 2; im++) {
                uint32_t ad = stb + (uint32_t)((m0w + im * 16 + lr) * LDS_ + koff) * 2;
                ldsm4(ah[im], ad);
            }
            #pragma unroll
            for (int ib = 0; ib < 2; ib++) {
                uint32_t bd = stb + ASZ_ +
                              (uint32_t)((n0w + ib * 16 + lr) * LDS_ + koff) * 2;
                ldsm4(bh[ib], bd);
            }
            #pragma unroll
            for (int im = 0; im < 2; im++)
                #pragma unroll
                for (int in = 0; in < 4; in++) {
                    int ib = in >> 1, sb = in & 1;
                    mma16816(acc[im][in], ah[im], bh[ib][sb], bh[ib][sb + 2]);
                }
        }
        int nt = kt + STAGES_ - 1;
        if (nt < T) issue(nt); else cp_commit();
    }

    // Epilogue
    int g = lane >> 2, tq = lane & 3;
    #pragma unroll
    for (int in = 0; in < 4; in++) {
        int cb = n0 + n0w + in * 8 + tq * 2;
        float b0, b1;
        int section = cb >> 10;   // only meaningful for MODE 3
        if (MODE == 3) {
            const float* bp = (section == 0) ? bias : (section == 1) ? bias2 : bias3;
            b0 = __ldg(&bp[cb & 1023]);
            b1 = __ldg(&bp[(cb & 1023) + 1]);
        } else {
            b0 = __ldg(&bias[cb]);
            b1 = __ldg(&bias[cb + 1]);
        }
        #pragma unroll
        for (int im = 0; im < 2; im++) {
            #pragma unroll
            for (int hrow = 0; hrow < 2; hrow++) {
                int m = m0 + m0w + im * 16 + g + hrow * 8;
                if (m < Mc) {
                    float v0 = acc[im][in][hrow * 2 + 0] + b0;
                    float v1 = acc[im][in][hrow * 2 + 1] + b1;
                    if (RELU) { v0 = fmaxf(v0, 0.f); v1 = fmaxf(v1, 0.f); }
                    if (MODE == 0) {
                        *(float2*)&Cf[(size_t)m * Nn + cb] = make_float2(v0, v1);
                    } else if (MODE == 4) {
                        *(uint32_t*)&Ch[(size_t)m * Nn + cb] = packh(v0, v1);
                    } else {  // MODE 3
                        if (section < 2) {
                            uint32_t hw, lw;
                            packsplit(v0, v1, hw, lw);
                            *(uint32_t*)&Ch[(size_t)m * QKS_ + cb] = hw;
                            *(uint32_t*)&Cl[(size_t)m * QKS_ + cb] = lw;
                        } else {
                            int bb = g_rowb[m];
                            int pos = m - g_cum[bb];
                            int nn = cb & 1023;
                            size_t vt0 = ((size_t)bb * D_ + nn) * LT_ + pos;
                            Ch2[vt0]       = __float2half(v0);
                            Ch2[vt0 + LT_] = __float2half(v1);
                        }
                    }
                }
            }
        }
    }
}

// ---------------------------------------------------------------------------
// HMMA fp16 flash attention, 2-term compensation (compact rows).
// S = (Qh+Ql)*Kh (exact Q); O = (Ph+Pl)*Vh (exact P).
// Block: (q-tile 64, head, batch), 128 threads; 55KB smem -> 4 CTAs/SM.
// Q/K from g_qkh/l (stride 2048; k at col offset 1024); V from g_vth.
// Writes hi-only output to g_ath (consumed by 1-term O GEMM).
// ---------------------------------------------------------------------------
__global__ __launch_bounds__(128) void attn_mma_kernel() {
    extern __shared__ char asmem[];
    uint32_t sb = s2u(asmem);
    int tid = threadIdx.x, lane = tid & 31, w = tid >> 5;
    int qt = blockIdx.x, h = blockIdx.y, b = blockIdx.z;
    int q0 = qt * 64;
    int Lv = 2 + g_tlen[b] + g_slen[b];
    if (q0 >= Lv) return;
    int cumb = g_cum[b];
    const int NKT = (Lv + 63) >> 6;

    int lr = lane & 15, lc8 = (lane >> 4) * 8;
    int r = lane >> 2, tq = lane & 3;
    int lrow = tid >> 1, lhf = tid & 1;   // smem-fill: row, col-half

    // ---- stage Q (hi/lo) ----
    {
        int qrow = q0 + lrow; if (qrow > Lv - 1) qrow = Lv - 1;
        size_t off = (size_t)(cumb + qrow) * QKS_ + h * HD_ + lhf * 32;
        uint32_t dst = sb + (uint32_t)(lrow * ATS + lhf * 32) * 2;
        #pragma unroll
        for (int u = 0; u < 4; u++) {
            cp16(dst + u * 16,           g_qkh + off + u * 8, 16);
            cp16(dst + AT_TILE + u * 16, g_qkl + off + u * 8, 16);
        }
        cp_commit();
    }

    auto loadKV = [&](int kt) {
        uint32_t base = sb + ATT_ST0 + (kt & 1) * ATT_STG;
        int k0 = kt * 64;
        int krow = k0 + lrow; if (krow > Lv - 1) krow = Lv - 1;
        size_t koff = (size_t)(cumb + krow) * QKS_ + 1024 + h * HD_ + lhf * 32;
        uint32_t kdst = base + (uint32_t)(lrow * ATS + lhf * 32) * 2;
        #pragma unroll
        for (int u = 0; u < 4; u++)
            cp16(kdst + u * 16, g_qkh + koff + u * 8, 16);
        // V (hi only): row stride LT_; cols >= Lv are stale/zero but P=0.
        size_t voff = ((size_t)b * D_ + h * HD_ + lrow) * LT_ + k0 + lhf * 32;
        uint32_t vdst = base + AT_TILE + (uint32_t)(lrow * ATS + lhf * 32) * 2;
        #pragma unroll
        for (int u = 0; u < 4; u++) {
            int col = k0 + lhf * 32 + u * 8;
            int nb = (col < LT_) ? 16 : 0;   // zfill past padded length
            cp16(vdst + u * 16, g_vth + voff + u * 8, nb);
        }
        cp_commit();
    };

    loadKV(0);
    cp_wait<1>();           // Q staged (KV0 may still be in flight)
    __syncthreads();

    // Q fragments (held in registers for the whole kernel)
    uint32_t qfh[4][4], qfl[4][4];
    #pragma unroll
    for (int c = 0; c < 4; c++) {
        uint32_t ad = sb + (uint32_t)((w * 16 + lr) * ATS + c * 16 + lc8) * 2;
        ldsm4(qfh[c], ad);
        ldsm4(qfl[c], ad + AT_TILE);
    }

    float o[8][4];
    #pragma unroll
    for (int j = 0; j < 8; j++)
        #pragma unroll
        for (int p = 0; p < 4; p++) o[j][p] = 0.f;
    float mrA = -1e30f, mrB = -1e30f, lsA = 0.f, lsB = 0.f;

    for (int kt = 0; kt < NKT; kt++) {
        if (kt + 1 < NKT) { loadKV(kt + 1); cp_wait<1>(); }
        else              { cp_wait<0>(); }
        __syncthreads();
        uint32_t base = sb + ATT_ST0 + (kt & 1) * ATT_STG;
        int k0 = kt * 64;

        // ---- S = (Qh+Ql) Kh^T (2-term) ----
        float s[8][4];
        #pragma unroll
        for (int j = 0; j < 8; j++)
            #pragma unroll
            for (int p = 0; p < 4; p++) s[j][p] = 0.f;

        #pragma unroll
        for (int c = 0; c < 4; c++) {
            #pragma unroll
            for (int ib = 0; ib < 4; ib++) {
                uint32_t bd = base + (uint32_t)((ib * 16 + lr) * ATS + c * 16 + lc8) * 2;
                uint32_t kbh[4];
                ldsm4(kbh, bd);
                #pragma unroll
                for (int sbn = 0; sbn < 2; sbn++) {
                    int j = ib * 2 + sbn;
                    mma16816(s[j], qfh[c], kbh[sbn], kbh[sbn + 2]);
                    mma16816(s[j], qfl[c], kbh[sbn], kbh[sbn + 2]);
                }
            }
        }

        // ---- scale + mask ----
        #pragma unroll
        for (int j = 0; j < 8; j++) {
            int c0 = k0 + j * 8 + 2 * tq, c1 = c0 + 1;
            s[j][0] = (c0 < Lv) ? s[j][0] * 0.125f : -1e9f;
            s[j][1] = (c1 < Lv) ? s[j][1] * 0.125f : -1e9f;
            s[j][2] = (c0 < Lv) ? s[j][2] * 0.125f : -1e9f;
            s[j][3] = (c1 < Lv) ? s[j][3] * 0.125f : -1e9f;
        }

        // ---- online softmax (rows r and r+8) ----
        float mA = -1e30f, mB = -1e30f;
        #pragma unroll
        for (int j = 0; j < 8; j++) {
            mA = fmaxf(mA, fmaxf(s[j][0], s[j][1]));
            mB = fmaxf(mB, fmaxf(s[j][2], s[j][3]));
        }
        mA = fmaxf(mA, __shfl_xor_sync(0xffffffffu, mA, 1));
        mA = fmaxf(mA, __shfl_xor_sync(0xffffffffu, mA, 2));
        mB = fmaxf(mB, __shfl_xor_sync(0xffffffffu, mB, 1));
        mB = fmaxf(mB, __shfl_xor_sync(0xffffffffu, mB, 2));
        float mnA = fmaxf(mrA, mA), mnB = fmaxf(mrB, mB);
        float aA = expf(mrA - mnA), aB = expf(mrB - mnB);
        float rsA = 0.f, rsB = 0.f;
        #pragma unroll
        for (int j = 0; j < 8; j++) {
            s[j][0] = expf(s[j][0] - mnA);
            s[j][1] = expf(s[j][1] - mnA);
            s[j][2] = expf(s[j][2] - mnB);
            s[j][3] = expf(s[j][3] - mnB);
            rsA += s[j][0] + s[j][1];
            rsB += s[j][2] + s[j][3];
        }
        rsA += __shfl_xor_sync(0xffffffffu, rsA, 1);
        rsA += __shfl_xor_sync(0xffffffffu, rsA, 2);
        rsB += __shfl_xor_sync(0xffffffffu, rsB, 1);
        rsB += __shfl_xor_sync(0xffffffffu, rsB, 2);
        lsA = lsA * aA + rsA;
        lsB = lsB * aB + rsB;
        mrA = mnA; mrB = mnB;
        #pragma unroll
        for (int j = 0; j < 8; j++) {
            o[j][0] *= aA; o[j][1] *= aA;
            o[j][2] *= aB; o[j][3] *= aB;
        }

        // ---- O += (Ph+Pl) Vh (2-term) ----
        #pragma unroll
        for (int c = 0; c < 4; c++) {
            uint32_t pah[4], pal[4];
            packsplit(s[2 * c][0],     s[2 * c][1],     pah[0], pal[0]);
            packsplit(s[2 * c][2],     s[2 * c][3],     pah[1], pal[1]);
            packsplit(s[2 * c + 1][0], s[2 * c + 1][1], pah[2], pal[2]);
            packsplit(s[2 * c + 1][2], s[2 * c + 1][3], pah[3], pal[3]);
            #pragma unroll
            for (int ib = 0; ib < 4; ib++) {
                uint32_t bd = base + AT_TILE +
                              (uint32_t)((ib * 16 + lr) * ATS + c * 16 + lc8) * 2;
                uint32_t vbh[4];
                ldsm4(vbh, bd);
                #pragma unroll
                for (int sbn = 0; sbn < 2; sbn++) {
                    int j = ib * 2 + sbn;
                    mma16816(o[j], pah, vbh[sbn], vbh[sbn + 2]);
                    mma16816(o[j], pal, vbh[sbn], vbh[sbn + 2]);
                }
            }
        }
        __syncthreads();
    }

    // ---- write O (hi only; compact rows, only valid positions) ----
    float iA = 1.f / lsA, iB = 1.f / lsB;
    int qA = q0 + w * 16 + r, qB = qA + 8;
    #pragma unroll
    for (int j = 0; j < 8; j++) {
        int d = h * HD_ + j * 8 + 2 * tq;
        if (qA < Lv) {
            size_t off = (size_t)(cumb + qA) * D_ + d;
            *(uint32_t*)&g_ath[off] = packh(o[j][0] * iA, o[j][1] * iA);
        }
        if (qB < Lv) {
            size_t off = (size_t)(cumb + qB) * D_ + d;
            *(uint32_t*)&g_ath[off] = packh(o[j][2] * iB, o[j][3] * iB);
        }
    }
}

// ---------------------------------------------------------------------------
// x = LayerNorm(x + y) * s + b (in place) + fp16 hi emission (compact rows).
// ---------------------------------------------------------------------------
__global__ __launch_bounds__(256) void add_ln_kernel(const float* __restrict__ sc,
                                                     const float* __restrict__ bi) {
    int row = blockIdx.x;
    if (row >= g_cum[B_]) return;
    size_t base = (size_t)row * D_;
    __shared__ float red[256];
    int tid = threadIdx.x;

    float v[4];
    float s = 0.f;
    #pragma unroll
    for (int u = 0; u < 4; u++) {
        int d = tid + u * 256;
        v[u] = g_x[base + d] + g_y[base + d];
        s += v[u];
    }
    red[tid] = s;
    __syncthreads();
    for (int off = 128; off > 0; off >>= 1) {
        if (tid < off) red[tid] += red[tid + off];
        __syncthreads();
    }
    float mean = red[0] * (1.f / D_);
    __syncthreads();

    float s2 = 0.f;
    #pragma unroll
    for (int u = 0; u < 4; u++) { float dd = v[u] - mean; s2 += dd * dd; }
    red[tid] = s2;
    __syncthreads();
    for (int off = 128; off > 0; off >>= 1) {
        if (tid < off) red[tid] += red[tid + off];
        __syncthreads();
    }
    float var = red[0] * (1.f / D_);
    float inv = rsqrtf(var + 1e-5f);

    #pragma unroll
    for (int u = 0; u < 4; u++) {
        int d = tid + u * 256;
        float t = (v[u] - mean) * inv * sc[d] + bi[d];
        g_x[base + d] = t;
        g_xh[base + d] = __float2half(t);
    }
}

// ---------------------------------------------------------------------------
// out[b] = dot(x[cum[b], :], out_w)
// ---------------------------------------------------------------------------
__global__ __launch_bounds__(256) void final_kernel(const float* __restrict__ ow,
                                                    float* __restrict__ out) {
    int b = blockIdx.x;
    __shared__ float red[256];
    const float* xr = &g_x[(size_t)g_cum[b] * D_];
    int tid = threadIdx.x;
    float s = 0.f;
    for (int d = tid; d < D_; d += 256) s += xr[d] * ow[d];
    red[tid] = s;
    __syncthreads();
    for (int off = 128; off > 0; off >>= 1) {
        if (tid < off) red[tid] += red[tid + off];
        __syncthreads();
    }
    if (tid == 0) out[b] = red[0];
}

// ---------------------------------------------------------------------------
// Launch
// ---------------------------------------------------------------------------
extern "C" void kernel_launch(void* const* d_in, const int* in_sizes, int n_in,
                              void* d_out, int out_size) {
    const float* text   = (const float*)d_in[0];
    const float* speech = (const float*)d_in[1];
    const void*  tmask  = d_in[2];
    const void*  smask  = d_in[3];
    const float* cls    = (const float*)d_in[4];
    const float* sep    = (const float*)d_in[5];
    const float* Wq     = (const float*)d_in[6];
    const float* bq     = (const float*)d_in[7];
    const float* Wk     = (const float*)d_in[8];
    const float* bk     = (const float*)d_in[9];
    const float* Wv     = (const float*)d_in[10];
    const float* bv     = (const float*)d_in[11];
    const float* Wo     = (const float*)d_in[12];
    const float* bo     = (const float*)d_in[13];
    const float* ln1s   = (const float*)d_in[14];
    const float* ln1b   = (const float*)d_in[15];
    const float* f1w    = (const float*)d_in[16];
    const float* f1b    = (const float*)d_in[17];
    const float* f2w    = (const float*)d_in[18];
    const float* f2b    = (const float*)d_in[19];
    const float* ln2s   = (const float*)d_in[20];
    const float* ln2b   = (const float*)d_in[21];
    const float* outw   = (const float*)d_in[22];
    float* out = (float*)d_out;

    float* y;
    __half *xh, *qkh, *qkl, *vth, *ath, *hh;
    __half *Wqkvh, *Woh, *F1h, *F2h;
    cudaGetSymbolAddress((void**)&y,     g_y);
    cudaGetSymbolAddress((void**)&xh,    g_xh);
    cudaGetSymbolAddress((void**)&qkh,   g_qkh);
    cudaGetSymbolAddress((void**)&qkl,   g_qkl);
    cudaGetSymbolAddress((void**)&vth,   g_vth);
    cudaGetSymbolAddress((void**)&ath,   g_ath);
    cudaGetSymbolAddress((void**)&hh,    g_hh);
    cudaGetSymbolAddress((void**)&Wqkvh, g_Wqkvh);
    cudaGetSymbolAddress((void**)&Woh,   g_Woh);
    cudaGetSymbolAddress((void**)&F1h,   g_F1h);
    cudaGetSymbolAddress((void**)&F2h,   g_F2h);

    cudaFuncSetAttribute(attn_mma_kernel,
                         cudaFuncAttributeMaxDynamicSharedMemorySize, ATT_SMEM);
    cudaFuncSetAttribute(gemm_mma<0, 3>,
                         cudaFuncAttributeMaxDynamicSharedMemorySize, GEMM_SMEM);
    cudaFuncSetAttribute(gemm_mma<0, 0>,
                         cudaFuncAttributeMaxDynamicSharedMemorySize, GEMM_SMEM);
    cudaFuncSetAttribute(gemm_mma<1, 4>,
                         cudaFuncAttributeMaxDynamicSharedMemorySize, GEMM_SMEM);

    lengths_kernel<<<2, 256>>>(tmask, smask);
    cum_kernel<<<1, 32>>>();
    build_x_kernel<<<dim3(L_, B_), 256>>>(text, speech, cls, sep);
    wsplit_all_kernel<<<NL_ * WT_PER_LAYER, dim3(32, 8)>>>(Wq, Wk, Wv, Wo, f1w, f2w);

    int mt = (M_ + 127) / 128;  // 81 (static; CTAs past Mc self-skip)
    dim3 gQKV(3072 / 128, mt);
    dim3 gD(D_ / 128, mt);
    dim3 gF(F_ / 128, mt);
    dim3 gAtt((L_ + 63) / 64, H_, B_);

    for (int l = 0; l < NL_; l++) {
        size_t oqkv = (size_t)l * 3072 * 1024;
        size_t od = (size_t)l * D_ * D_;
        size_t o1 = (size_t)l * D_ * F_;
        size_t o2 = (size_t)l * F_ * D_;
        gemm_mma<0, 3><<<gQKV, 512, GEMM_SMEM>>>(
            xh, Wqkvh + oqkv,
            bq + l * D_, bk + l * D_, bv + l * D_,
            nullptr, qkh, qkl, vth, 3072, D_);
        attn_mma_kernel<<<gAtt, 128, ATT_SMEM>>>();
        gemm_mma<0, 0><<<gD, 512, GEMM_SMEM>>>(
            ath, Woh + od,
            bo + l * D_, nullptr, nullptr,
            y, nullptr, nullptr, nullptr, D_, D_);
        add_ln_kernel<<<M_, 256>>>(ln1s + l * D_, ln1b + l * D_);
        gemm_mma<1, 4><<<gF, 512, GEMM_SMEM>>>(
            xh, F1h + o1,
            f1b + l * F_, nullptr, nullptr,
            nullptr, hh, nullptr, nullptr, F_, D_);
        gemm_mma<0, 0><<<gD, 512, GEMM_SMEM>>>(
            hh, F2h + o2,
            f2b + l * D_, nullptr, nullptr,
            y, nullptr, nullptr, nullptr, D_, F_);
        add_ln_kernel<<<M_, 256>>>(ln2s + l * D_, ln2b + l * D_);
    }
    final_kernel<<<B_, 256>>>(outw, out);
}

// round 17
// speedup vs baseline: 9.1130x; 1.0190x over previous
#include <cuda_runtime.h>
#include <cuda_fp16.h>
#include <math.h>
#include <stdint.h>

// ---------------------------------------------------------------------------
// Problem constants
// ---------------------------------------------------------------------------
namespace {
constexpr int B_  = 16;
constexpr int TT_ = 128;
constexpr int TS_ = 512;
constexpr int L_  = TT_ + TS_ + 2;   // 642
constexpr int LT_ = 648;             // vt row stride: multiple of 8 elems (16B)
constexpr int D_  = 1024;
constexpr int H_  = 16;
constexpr int HD_ = 64;
constexpr int F_  = 4096;
constexpr int NL_ = 4;
constexpr int M_  = B_ * L_;         // 10272
constexpr int QKS_ = 2048;           // fused q|k buffer row stride

// GEMM tiling (1-term, BK=64: stages hold Ah, Bh; fewer barriers per GEMM)
constexpr int BK_     = 64;
constexpr int STAGES_ = 3;
constexpr int LDS_    = 72;                    // padded row stride (elements)
constexpr int ASZ_    = 128 * LDS_ * 2;        // 18432 bytes per tile array
constexpr int STAGE_B = 2 * ASZ_;              // 36864 bytes per stage
constexpr int GEMM_SMEM = STAGES_ * STAGE_B + 1024;  // 111616

// Attention tiling (2-term: Q hi/lo resident; stages hold Kh, Vth only)
constexpr int ATS      = 72;                   // smem row stride (elements)
constexpr int AT_TILE  = 64 * ATS * 2;         // 9216 bytes per 64x64 fp16 array
constexpr int ATT_ST0  = 2 * AT_TILE;          // Qh, Ql
constexpr int ATT_STG  = 2 * AT_TILE;          // Kh, Vth per stage
constexpr int ATT_SMEM = ATT_ST0 + 2 * ATT_STG; // 55296 -> 4 CTAs/SM

// fused wsplit decode
constexpr int WT_PER_LAYER = 4 * 1024 + 4096 + 4096;  // 12288 tiles/layer
}

// ---------------------------------------------------------------------------
// Scratch (allocation-free: __device__ globals; zero-initialized)
// ---------------------------------------------------------------------------
__device__ float g_x[(size_t)M_ * D_];
__device__ __half g_yh [(size_t)M_ * D_];
__device__ __half g_xh [(size_t)M_ * D_];
__device__ __half g_qkh[(size_t)M_ * QKS_];
__device__ __half g_qkl[(size_t)M_ * QKS_];
__device__ __half g_vth[(size_t)B_ * D_ * LT_ + 64];
__device__ __half g_ath[(size_t)M_ * D_];
__device__ __half g_hh [(size_t)M_ * F_];
// transposed fp16 weights ([N,K] layout), hi only; QKV concatenated (N=3072)
__device__ __half g_Wqkvh[(size_t)NL_ * 3072 * 1024];
__device__ __half g_Woh[(size_t)NL_ * D_ * D_];
__device__ __half g_F1h[(size_t)NL_ * D_ * F_];
__device__ __half g_F2h[(size_t)NL_ * F_ * D_];
__device__ int g_tlen[B_];
__device__ int g_slen[B_];
__device__ int g_cum[B_ + 1];
__device__ int g_rowb[M_];        // batch index of each compact row

// ---------------------------------------------------------------------------
// PTX helpers (sm_80-era subset only: cp.async, ldmatrix, mma.sync)
// ---------------------------------------------------------------------------
__device__ __forceinline__ uint32_t s2u(const void* p) {
    uint32_t a;
    asm("{ .reg .u64 t; cvta.to.shared.u64 t, %1; cvt.u32.u64 %0, t; }"
        : "=r"(a) : "l"(p));
    return a;
}
__device__ __forceinline__ void cp16(uint32_t s, const void* g, int nbytes) {
    asm volatile("cp.async.cg.shared.global [%0], [%1], 16, %2;"
                 :: "r"(s), "l"(g), "r"(nbytes));
}
__device__ __forceinline__ void cp_commit() {
    asm volatile("cp.async.commit_group;");
}
template <int N> __device__ __forceinline__ void cp_wait() {
    asm volatile("cp.async.wait_group %0;" :: "n"(N));
}
__device__ __forceinline__ void ldsm4(uint32_t* r, uint32_t addr) {
    asm volatile("ldmatrix.sync.aligned.m8n8.x4.shared.b16 {%0,%1,%2,%3}, [%4];"
                 : "=r"(r[0]), "=r"(r[1]), "=r"(r[2]), "=r"(r[3]) : "r"(addr));
}
__device__ __forceinline__ void mma16816(float* c, const uint32_t* a,
                                         uint32_t b0, uint32_t b1) {
    asm volatile(
        "mma.sync.aligned.m16n8k16.row.col.f32.f16.f16.f32 "
        "{%0,%1,%2,%3}, {%4,%5,%6,%7}, {%8,%9}, {%0,%1,%2,%3};\n"
        : "+f"(c[0]), "+f"(c[1]), "+f"(c[2]), "+f"(c[3])
        : "r"(a[0]), "r"(a[1]), "r"(a[2]), "r"(a[3]), "r"(b0), "r"(b1));
}
// split two fp32 into packed fp16x2 hi and lo words
__device__ __forceinline__ void packsplit(float x, float y,
                                          uint32_t& hi, uint32_t& lo) {
    __half hx = __float2half(x), hy = __float2half(y);
    __half2 hh = __halves2half2(hx, hy);
    __half2 ll = __halves2half2(__float2half(x - __half2float(hx)),
                                __float2half(y - __half2float(hy)));
    hi = *(uint32_t*)&hh;
    lo = *(uint32_t*)&ll;
}
__device__ __forceinline__ uint32_t packh(float x, float y) {
    __half2 hh = __halves2half2(__float2half(x), __float2half(y));
    return *(uint32_t*)&hh;
}

// ---------------------------------------------------------------------------
// Mask length computation with on-device dtype detection
// ---------------------------------------------------------------------------
__global__ void lengths_kernel(const void* tmask, const void* smask) {
    int which = blockIdx.x;
    const void* mask = which ? smask : tmask;
    int T = which ? TS_ : TT_;
    int* lens = which ? g_slen : g_tlen;
    int N = B_ * T;

    __shared__ int f3F, fMis;
    __shared__ int cnt[B_];
    int tid = threadIdx.x;
    if (tid == 0) { f3F = 0; fMis = 0; }
    if (tid < B_) cnt[tid] = 0;
    __syncthreads();

    const unsigned char* bytes = (const unsigned char*)mask;
    int l3 = 0, lm = 0;
    for (int i = tid; i < N; i += blockDim.x) {
        unsigned char c = bytes[i];
        if (c == 0x3F) l3 = 1;
        if (c == 1 && (i & 3)) lm = 1;
    }
    if (l3) atomicOr(&f3F, 1);
    if (lm) atomicOr(&fMis, 1);
    __syncthreads();

    if (fMis && !f3F) {
        for (int i = tid; i < N; i += blockDim.x)
            if (bytes[i] == 0) atomicAdd(&cnt[i / T], 1);
    } else {
        const unsigned int* w = (const unsigned int*)mask;
        for (int i = tid; i < N; i += blockDim.x)
            if (w[i] == 0u) atomicAdd(&cnt[i / T], 1);
    }
    __syncthreads();
    if (tid < B_) lens[tid] = cnt[tid];
}

// prefix sums of valid lengths
__global__ void cum_kernel() {
    if (threadIdx.x == 0) {
        int a = 0;
        for (int b = 0; b < B_; b++) {
            g_cum[b] = a;
            a += 2 + g_tlen[b] + g_slen[b];
        }
        g_cum[B_] = a;
    }
}

// ---------------------------------------------------------------------------
// Build COMPACT concatenated sequence x (fp32 + fp16 hi) + row->batch map
// ---------------------------------------------------------------------------
__global__ void build_x_kernel(const float* __restrict__ text,
                               const float* __restrict__ speech,
                               const float* __restrict__ cls,
                               const float* __restrict__ sep) {
    int pos = blockIdx.x, b = blockIdx.y;
    int tl = g_tlen[b], sl = g_slen[b];
    if (pos >= 2 + tl + sl) return;
    int row = g_cum[b] + pos;
    size_t base = (size_t)row * D_;
    if (threadIdx.x == 0) g_rowb[row] = b;

    const float* s;
    if (pos == 0)                 s = cls;
    else if (pos < 1 + tl)        s = &text  [((size_t)(pos - 1) * B_ + b) * D_];
    else if (pos == 1 + tl)       s = sep;
    else                          s = &speech[((size_t)(pos - 2 - tl) * B_ + b) * D_];

    for (int d = threadIdx.x; d < D_; d += blockDim.x) {
        float v = s[d];
        g_x[base + d] = v;
        g_xh[base + d] = __float2half(v);
    }
}

// ---------------------------------------------------------------------------
// Fused weight transpose + fp16 convert for ALL weights (one launch).
// ---------------------------------------------------------------------------
__global__ void wsplit_all_kernel(const float* __restrict__ Wq,
                                  const float* __restrict__ Wk,
                                  const float* __restrict__ Wv,
                                  const float* __restrict__ Wo,
                                  const float* __restrict__ F1,
                                  const float* __restrict__ F2) {
    int gidx = blockIdx.x;
    int l = gidx / WT_PER_LAYER;
    int r = gidx - l * WT_PER_LAYER;

    const float* W;
    __half* Th;
    int K, N, tile;
    if (r < 4096) {
        int type = r >> 10;           // 0=q 1=k 2=v 3=o
        tile = r & 1023;
        K = 1024; N = 1024;
        size_t wofs = (size_t)l * D_ * D_;
        if (type == 0)      { W = Wq + wofs; }
        else if (type == 1) { W = Wk + wofs; }
        else if (type == 2) { W = Wv + wofs; }
        else                { W = Wo + wofs; }
        if (type < 3)
            Th = g_Wqkvh + (size_t)l * 3072 * 1024 + (size_t)type * 1024 * 1024;
        else
            Th = g_Woh + (size_t)l * D_ * D_;
    } else if (r < 8192) {
        tile = r - 4096;
        K = 1024; N = 4096;
        W = F1 + (size_t)l * D_ * F_;
        Th = g_F1h + (size_t)l * D_ * F_;
    } else {
        tile = r - 8192;
        K = 4096; N = 1024;
        W = F2 + (size_t)l * F_ * D_;
        Th = g_F2h + (size_t)l * F_ * D_;
    }

    int ntiles = N >> 5;
    int n0 = (tile % ntiles) * 32;
    int k0 = (tile / ntiles) * 32;

    __shared__ float t[32][33];
    int tx = threadIdx.x, ty = threadIdx.y;
    #pragma unroll
    for (int j = 0; j < 4; j++) {
        int k = k0 + ty + j * 8;
        t[ty + j * 8][tx] = W[(size_t)k * N + n0 + tx];
    }
    __syncthreads();
    #pragma unroll
    for (int j = 0; j < 4; j++) {
        int n = n0 + ty + j * 8;
        Th[(size_t)n * K + k0 + tx] = __float2half(t[tx][ty + j * 8]);
    }
}

// ---------------------------------------------------------------------------
// HMMA fp16 GEMM, 1-term (C = Ah*Bh + bias), compact rows (M = g_cum[B]).
// 128x128x64 CTA tile, 512 threads (16 warps, 4x4), 3-stage cp.async pipeline.
// MODE 4: fp16 hi-only C (after optional RELU), stride Nn.
// MODE 3: fused QKV epilogue: n<2048 -> qk hi/lo buffer (stride 2048);
//         n>=2048 -> V hi transposed per batch: vt[(b*D+n-2048)*LT + pos].
// ---------------------------------------------------------------------------
template <int RELU, int MODE>
__global__ __launch_bounds__(512, 1) void gemm_mma(
    const __half* __restrict__ Ah,
    const __half* __restrict__ Bh,
    const float* __restrict__ bias, const float* __restrict__ bias2,
    const float* __restrict__ bias3,
    __half* __restrict__ Ch, __half* __restrict__ Cl,
    __half* __restrict__ Ch2,
    int Nn, int Kn) {
    extern __shared__ char dynsmem[];
    uint32_t sbase = (s2u(dynsmem) + 1023u) & ~1023u;
    int tid = threadIdx.x;
    int wid = tid >> 5, lane = tid & 31;
    int m0 = blockIdx.y * 128, n0 = blockIdx.x * 128;
    const int Mc = g_cum[B_];
    if (m0 >= Mc) return;   // fully-pad tile (compact rows)

    int wm = wid & 3, wn = wid >> 2;     // 4x4 warp grid
    int m0w = wm * 32, n0w = wn * 32;
    const int T = Kn / BK_;

    int lrow = tid >> 2, lcol = tid & 3;   // loader: row 0..127, base chunk 0..3

    auto issue = [&](int kt) {
        uint32_t stb = sbase + (kt % STAGES_) * STAGE_B;
        int gr = m0 + lrow;
        bool vld = gr < Mc;
        size_t arow = (size_t)(vld ? gr : 0) * Kn + kt * BK_;
        size_t brow = (size_t)(n0 + lrow) * Kn + kt * BK_;
        #pragma unroll
        for (int u = 0; u < 2; u++) {
            int c = lcol + u * 4;          // 16B chunk 0..7 within 128B row
            uint32_t off = (uint32_t)(lrow * LDS_ + c * 8) * 2;
            cp16(stb + off,        Ah + arow + c * 8, vld ? 16 : 0);
            cp16(stb + ASZ_ + off, Bh + brow + c * 8, 16);
        }
        cp_commit();
    };

    #pragma unroll
    for (int p = 0; p < STAGES_ - 1; p++)
        if (p < T) issue(p);

    float acc[2][4][4];
    #pragma unroll
    for (int i = 0; i < 2; i++)
        #pragma unroll
        for (int j = 0; j < 4; j++)
            #pragma unroll
            for (int p = 0; p < 4; p++) acc[i][j][p] = 0.f;

    int lr = lane & 15, lc8 = (lane >> 4) * 8;

    for (int kt = 0; kt < T; kt++) {
        cp_wait<STAGES_ - 2>();
        __syncthreads();
        uint32_t stb = sbase + (kt % STAGES_) * STAGE_B;
        #pragma unroll
        for (int kk = 0; kk < 4; kk++) {
            int koff = kk * 16 + lc8;
            uint32_t ah[2][4], bh[2][4];
            #pragma unroll
            for (int im = 0; im < 2; im++) {
                uint32_t ad = stb + (uint32_t)((m0w + im * 16 + lr) * LDS_ + koff) * 2;
                ldsm4(ah[im], ad);
            }
            #pragma unroll
            for (int ib = 0; ib < 2; ib++) {
                uint32_t bd = stb + ASZ_ +
                              (uint32_t)((n0w + ib * 16 + lr) * LDS_ + koff) * 2;
                ldsm4(bh[ib], bd);
            }
            #pragma unroll
            for (int im = 0; im < 2; im++)
                #pragma unroll
                for (int in = 0; in < 4; in++) {
                    int ib = in >> 1, sb = in & 1;
                    mma16816(acc[im][in], ah[im], bh[ib][sb], bh[ib][sb + 2]);
                }
        }
        int nt = kt + STAGES_ - 1;
        if (nt < T) issue(nt); else cp_commit();
    }

    // Epilogue
    int g = lane >> 2, tq = lane & 3;
    #pragma unroll
    for (int in = 0; in < 4; in++) {
        int cb = n0 + n0w + in * 8 + tq * 2;
        float b0, b1;
        int section = cb >> 10;   // only meaningful for MODE 3
        if (MODE == 3) {
            const float* bp = (section == 0) ? bias : (section == 1) ? bias2 : bias3;
            b0 = __ldg(&bp[cb & 1023]);
            b1 = __ldg(&bp[(cb & 1023) + 1]);
        } else {
            b0 = __ldg(&bias[cb]);
            b1 = __ldg(&bias[cb + 1]);
        }
        #pragma unroll
        for (int im = 0; im < 2; im++) {
            #pragma unroll
            for (int hrow = 0; hrow < 2; hrow++) {
                int m = m0 + m0w + im * 16 + g + hrow * 8;
                if (m < Mc) {
                    float v0 = acc[im][in][hrow * 2 + 0] + b0;
                    float v1 = acc[im][in][hrow * 2 + 1] + b1;
                    if (RELU) { v0 = fmaxf(v0, 0.f); v1 = fmaxf(v1, 0.f); }
                    if (MODE == 4) {
                        *(uint32_t*)&Ch[(size_t)m * Nn + cb] = packh(v0, v1);
                    } else {  // MODE 3
                        if (section < 2) {
                            uint32_t hw, lw;
                            packsplit(v0, v1, hw, lw);
                            *(uint32_t*)&Ch[(size_t)m * QKS_ + cb] = hw;
                            *(uint32_t*)&Cl[(size_t)m * QKS_ + cb] = lw;
                        } else {
                            int bb = g_rowb[m];
                            int pos = m - g_cum[bb];
                            int nn = cb & 1023;
                            size_t vt0 = ((size_t)bb * D_ + nn) * LT_ + pos;
                            Ch2[vt0]       = __float2half(v0);
                            Ch2[vt0 + LT_] = __float2half(v1);
                        }
                    }
                }
            }
        }
    }
}

// ---------------------------------------------------------------------------
// HMMA fp16 flash attention, 2-term compensation (compact rows).
// S = (Qh+Ql)*Kh (exact Q); O = (Ph+Pl)*Vh (exact P).
// Block: (q-tile 64, head, batch), 128 threads; 55KB smem -> 4 CTAs/SM.
// ---------------------------------------------------------------------------
__global__ __launch_bounds__(128) void attn_mma_kernel() {
    extern __shared__ char asmem[];
    uint32_t sb = s2u(asmem);
    int tid = threadIdx.x, lane = tid & 31, w = tid >> 5;
    int qt = blockIdx.x, h = blockIdx.y, b = blockIdx.z;
    int q0 = qt * 64;
    int Lv = 2 + g_tlen[b] + g_slen[b];
    if (q0 >= Lv) return;
    int cumb = g_cum[b];
    const int NKT = (Lv + 63) >> 6;

    int lr = lane & 15, lc8 = (lane >> 4) * 8;
    int r = lane >> 2, tq = lane & 3;
    int lrow = tid >> 1, lhf = tid & 1;   // smem-fill: row, col-half

    // ---- stage Q (hi/lo) ----
    {
        int qrow = q0 + lrow; if (qrow > Lv - 1) qrow = Lv - 1;
        size_t off = (size_t)(cumb + qrow) * QKS_ + h * HD_ + lhf * 32;
        uint32_t dst = sb + (uint32_t)(lrow * ATS + lhf * 32) * 2;
        #pragma unroll
        for (int u = 0; u < 4; u++) {
            cp16(dst + u * 16,           g_qkh + off + u * 8, 16);
            cp16(dst + AT_TILE + u * 16, g_qkl + off + u * 8, 16);
        }
        cp_commit();
    }

    auto loadKV = [&](int kt) {
        uint32_t base = sb + ATT_ST0 + (kt & 1) * ATT_STG;
        int k0 = kt * 64;
        int krow = k0 + lrow; if (krow > Lv - 1) krow = Lv - 1;
        size_t koff = (size_t)(cumb + krow) * QKS_ + 1024 + h * HD_ + lhf * 32;
        uint32_t kdst = base + (uint32_t)(lrow * ATS + lhf * 32) * 2;
        #pragma unroll
        for (int u = 0; u < 4; u++)
            cp16(kdst + u * 16, g_qkh + koff + u * 8, 16);
        // V (hi only): row stride LT_; cols >= Lv are stale/zero but P=0.
        size_t voff = ((size_t)b * D_ + h * HD_ + lrow) * LT_ + k0 + lhf * 32;
        uint32_t vdst = base + AT_TILE + (uint32_t)(lrow * ATS + lhf * 32) * 2;
        #pragma unroll
        for (int u = 0; u < 4; u++) {
            int col = k0 + lhf * 32 + u * 8;
            int nb = (col < LT_) ? 16 : 0;   // zfill past padded length
            cp16(vdst + u * 16, g_vth + voff + u * 8, nb);
        }
        cp_commit();
    };

    loadKV(0);
    cp_wait<1>();           // Q staged (KV0 may still be in flight)
    __syncthreads();

    // Q fragments (held in registers for the whole kernel)
    uint32_t qfh[4][4], qfl[4][4];
    #pragma unroll
    for (int c = 0; c < 4; c++) {
        uint32_t ad = sb + (uint32_t)((w * 16 + lr) * ATS + c * 16 + lc8) * 2;
        ldsm4(qfh[c], ad);
        ldsm4(qfl[c], ad + AT_TILE);
    }

    float o[8][4];
    #pragma unroll
    for (int j = 0; j < 8; j++)
        #pragma unroll
        for (int p = 0; p < 4; p++) o[j][p] = 0.f;
    float mrA = -1e30f, mrB = -1e30f, lsA = 0.f, lsB = 0.f;

    for (int kt = 0; kt < NKT; kt++) {
        if (kt + 1 < NKT) { loadKV(kt + 1); cp_wait<1>(); }
        else              { cp_wait<0>(); }
        __syncthreads();
        uint32_t base = sb + ATT_ST0 + (kt & 1) * ATT_STG;
        int k0 = kt * 64;

        // ---- S = (Qh+Ql) Kh^T (2-term) ----
        float s[8][4];
        #pragma unroll
        for (int j = 0; j < 8; j++)
            #pragma unroll
            for (int p = 0; p < 4; p++) s[j][p] = 0.f;

        #pragma unroll
        for (int c = 0; c < 4; c++) {
            #pragma unroll
            for (int ib = 0; ib < 4; ib++) {
                uint32_t bd = base + (uint32_t)((ib * 16 + lr) * ATS + c * 16 + lc8) * 2;
                uint32_t kbh[4];
                ldsm4(kbh, bd);
                #pragma unroll
                for (int sbn = 0; sbn < 2; sbn++) {
                    int j = ib * 2 + sbn;
                    mma16816(s[j], qfh[c], kbh[sbn], kbh[sbn + 2]);
                    mma16816(s[j], qfl[c], kbh[sbn], kbh[sbn + 2]);
                }
            }
        }

        // ---- scale + mask ----
        #pragma unroll
        for (int j = 0; j < 8; j++) {
            int c0 = k0 + j * 8 + 2 * tq, c1 = c0 + 1;
            s[j][0] = (c0 < Lv) ? s[j][0] * 0.125f : -1e9f;
            s[j][1] = (c1 < Lv) ? s[j][1] * 0.125f : -1e9f;
            s[j][2] = (c0 < Lv) ? s[j][2] * 0.125f : -1e9f;
            s[j][3] = (c1 < Lv) ? s[j][3] * 0.125f : -1e9f;
        }

        // ---- online softmax (rows r and r+8) ----
        float mA = -1e30f, mB = -1e30f;
        #pragma unroll
        for (int j = 0; j < 8; j++) {
            mA = fmaxf(mA, fmaxf(s[j][0], s[j][1]));
            mB = fmaxf(mB, fmaxf(s[j][2], s[j][3]));
        }
        mA = fmaxf(mA, __shfl_xor_sync(0xffffffffu, mA, 1));
        mA = fmaxf(mA, __shfl_xor_sync(0xffffffffu, mA, 2));
        mB = fmaxf(mB, __shfl_xor_sync(0xffffffffu, mB, 1));
        mB = fmaxf(mB, __shfl_xor_sync(0xffffffffu, mB, 2));
        float mnA = fmaxf(mrA, mA), mnB = fmaxf(mrB, mB);
        float aA = expf(mrA - mnA), aB = expf(mrB - mnB);
        float rsA = 0.f, rsB = 0.f;
        #pragma unroll
        for (int j = 0; j < 8; j++) {
            s[j][0] = expf(s[j][0] - mnA);
            s[j][1] = expf(s[j][1] - mnA);
            s[j][2] = expf(s[j][2] - mnB);
            s[j][3] = expf(s[j][3] - mnB);
            rsA += s[j][0] + s[j][1];
            rsB += s[j][2] + s[j][3];
        }
        rsA += __shfl_xor_sync(0xffffffffu, rsA, 1);
        rsA += __shfl_xor_sync(0xffffffffu, rsA, 2);
        rsB += __shfl_xor_sync(0xffffffffu, rsB, 1);
        rsB += __shfl_xor_sync(0xffffffffu, rsB, 2);
        lsA = lsA * aA + rsA;
        lsB = lsB * aB + rsB;
        mrA = mnA; mrB = mnB;
        #pragma unroll
        for (int j = 0; j < 8; j++) {
            o[j][0] *= aA; o[j][1] *= aA;
            o[j][2] *= aB; o[j][3] *= aB;
        }

        // ---- O += (Ph+Pl) Vh (2-term) ----
        #pragma unroll
        for (int c = 0; c < 4; c++) {
            uint32_t pah[4], pal[4];
            packsplit(s[2 * c][0],     s[2 * c][1],     pah[0], pal[0]);
            packsplit(s[2 * c][2],     s[2 * c][3],     pah[1], pal[1]);
            packsplit(s[2 * c + 1][0], s[2 * c + 1][1], pah[2], pal[2]);
            packsplit(s[2 * c + 1][2], s[2 * c + 1][3], pah[3], pal[3]);
            #pragma unroll
            for (int ib = 0; ib < 4; ib++) {
                uint32_t bd = base + AT_TILE +
                              (uint32_t)((ib * 16 + lr) * ATS + c * 16 + lc8) * 2;
                uint32_t vbh[4];
                ldsm4(vbh, bd);
                #pragma unroll
                for (int sbn = 0; sbn < 2; sbn++) {
                    int j = ib * 2 + sbn;
                    mma16816(o[j], pah, vbh[sbn], vbh[sbn + 2]);
                    mma16816(o[j], pal, vbh[sbn], vbh[sbn + 2]);
                }
            }
        }
        __syncthreads();
    }

    // ---- write O (hi only; compact rows, only valid positions) ----
    float iA = 1.f / lsA, iB = 1.f / lsB;
    int qA = q0 + w * 16 + r, qB = qA + 8;
    #pragma unroll
    for (int j = 0; j < 8; j++) {
        int d = h * HD_ + j * 8 + 2 * tq;
        if (qA < Lv) {
            size_t off = (size_t)(cumb + qA) * D_ + d;
            *(uint32_t*)&g_ath[off] = packh(o[j][0] * iA, o[j][1] * iA);
        }
        if (qB < Lv) {
            size_t off = (size_t)(cumb + qB) * D_ + d;
            *(uint32_t*)&g_ath[off] = packh(o[j][2] * iB, o[j][3] * iB);
        }
    }
}

// ---------------------------------------------------------------------------
// x = LayerNorm(x + y) * s + b (in place; y fp16) + fp16 hi emission.
// ---------------------------------------------------------------------------
__global__ __launch_bounds__(256) void add_ln_kernel(const float* __restrict__ sc,
                                                     const float* __restrict__ bi) {
    int row = blockIdx.x;
    if (row >= g_cum[B_]) return;
    size_t base = (size_t)row * D_;
    __shared__ float red[256];
    int tid = threadIdx.x;

    float v[4];
    float s = 0.f;
    #pragma unroll
    for (int u = 0; u < 4; u++) {
        int d = tid + u * 256;
        v[u] = g_x[base + d] + __half2float(g_yh[base + d]);
        s += v[u];
    }
    red[tid] = s;
    __syncthreads();
    for (int off = 128; off > 0; off >>= 1) {
        if (tid < off) red[tid] += red[tid + off];
        __syncthreads();
    }
    float mean = red[0] * (1.f / D_);
    __syncthreads();

    float s2 = 0.f;
    #pragma unroll
    for (int u = 0; u < 4; u++) { float dd = v[u] - mean; s2 += dd * dd; }
    red[tid] = s2;
    __syncthreads();
    for (int off = 128; off > 0; off >>= 1) {
        if (tid < off) red[tid] += red[tid + off];
        __syncthreads();
    }
    float var = red[0] * (1.f / D_);
    float inv = rsqrtf(var + 1e-5f);

    #pragma unroll
    for (int u = 0; u < 4; u++) {
        int d = tid + u * 256;
        float t = (v[u] - mean) * inv * sc[d] + bi[d];
        g_x[base + d] = t;
        g_xh[base + d] = __float2half(t);
    }
}

// ---------------------------------------------------------------------------
// out[b] = dot(x[cum[b], :], out_w)
// ---------------------------------------------------------------------------
__global__ __launch_bounds__(256) void final_kernel(const float* __restrict__ ow,
                                                    float* __restrict__ out) {
    int b = blockIdx.x;
    __shared__ float red[256];
    const float* xr = &g_x[(size_t)g_cum[b] * D_];
    int tid = threadIdx.x;
    float s = 0.f;
    for (int d = tid; d < D_; d += 256) s += xr[d] * ow[d];
    red[tid] = s;
    __syncthreads();
    for (int off = 128; off > 0; off >>= 1) {
        if (tid < off) red[tid] += red[tid + off];
        __syncthreads();
    }
    if (tid == 0) out[b] = red[0];
}

// ---------------------------------------------------------------------------
// Launch
// ---------------------------------------------------------------------------
extern "C" void kernel_launch(void* const* d_in, const int* in_sizes, int n_in,
                              void* d_out, int out_size) {
    const float* text   = (const float*)d_in[0];
    const float* speech = (const float*)d_in[1];
    const void*  tmask  = d_in[2];
    const void*  smask  = d_in[3];
    const float* cls    = (const float*)d_in[4];
    const float* sep    = (const float*)d_in[5];
    const float* Wq     = (const float*)d_in[6];
    const float* bq     = (const float*)d_in[7];
    const float* Wk     = (const float*)d_in[8];
    const float* bk     = (const float*)d_in[9];
    const float* Wv     = (const float*)d_in[10];
    const float* bv     = (const float*)d_in[11];
    const float* Wo     = (const float*)d_in[12];
    const float* bo     = (const float*)d_in[13];
    const float* ln1s   = (const float*)d_in[14];
    const float* ln1b   = (const float*)d_in[15];
    const float* f1w    = (const float*)d_in[16];
    const float* f1b    = (const float*)d_in[17];
    const float* f2w    = (const float*)d_in[18];
    const float* f2b    = (const float*)d_in[19];
    const float* ln2s   = (const float*)d_in[20];
    const float* ln2b   = (const float*)d_in[21];
    const float* outw   = (const float*)d_in[22];
    float* out = (float*)d_out;

    __half *yh, *xh, *qkh, *qkl, *vth, *ath, *hh;
    __half *Wqkvh, *Woh, *F1h, *F2h;
    cudaGetSymbolAddress((void**)&yh,    g_yh);
    cudaGetSymbolAddress((void**)&xh,    g_xh);
    cudaGetSymbolAddress((void**)&qkh,   g_qkh);
    cudaGetSymbolAddress((void**)&qkl,   g_qkl);
    cudaGetSymbolAddress((void**)&vth,   g_vth);
    cudaGetSymbolAddress((void**)&ath,   g_ath);
    cudaGetSymbolAddress((void**)&hh,    g_hh);
    cudaGetSymbolAddress((void**)&Wqkvh, g_Wqkvh);
    cudaGetSymbolAddress((void**)&Woh,   g_Woh);
    cudaGetSymbolAddress((void**)&F1h,   g_F1h);
    cudaGetSymbolAddress((void**)&F2h,   g_F2h);

    cudaFuncSetAttribute(attn_mma_kernel,
                         cudaFuncAttributeMaxDynamicSharedMemorySize, ATT_SMEM);
    cudaFuncSetAttribute(gemm_mma<0, 3>,
                         cudaFuncAttributeMaxDynamicSharedMemorySize, GEMM_SMEM);
    cudaFuncSetAttribute(gemm_mma<0, 4>,
                         cudaFuncAttributeMaxDynamicSharedMemorySize, GEMM_SMEM);
    cudaFuncSetAttribute(gemm_mma<1, 4>,
                         cudaFuncAttributeMaxDynamicSharedMemorySize, GEMM_SMEM);

    lengths_kernel<<<2, 256>>>(tmask, smask);
    cum_kernel<<<1, 32>>>();
    build_x_kernel<<<dim3(L_, B_), 256>>>(text, speech, cls, sep);
    wsplit_all_kernel<<<NL_ * WT_PER_LAYER, dim3(32, 8)>>>(Wq, Wk, Wv, Wo, f1w, f2w);

    int mt = (M_ + 127) / 128;  // 81 (static; CTAs past Mc self-skip)
    dim3 gQKV(3072 / 128, mt);
    dim3 gD(D_ / 128, mt);
    dim3 gF(F_ / 128, mt);
    dim3 gAtt((L_ + 63) / 64, H_, B_);

    for (int l = 0; l < NL_; l++) {
        size_t oqkv = (size_t)l * 3072 * 1024;
        size_t od = (size_t)l * D_ * D_;
        size_t o1 = (size_t)l * D_ * F_;
        size_t o2 = (size_t)l * F_ * D_;
        gemm_mma<0, 3><<<gQKV, 512, GEMM_SMEM>>>(
            xh, Wqkvh + oqkv,
            bq + l * D_, bk + l * D_, bv + l * D_,
            qkh, qkl, vth, 3072, D_);
        attn_mma_kernel<<<gAtt, 128, ATT_SMEM>>>();
        gemm_mma<0, 4><<<gD, 512, GEMM_SMEM>>>(
            ath, Woh + od,
            bo + l * D_, nullptr, nullptr,
            yh, nullptr, nullptr, D_, D_);
        add_ln_kernel<<<M_, 256>>>(ln1s + l * D_, ln1b + l * D_);
        gemm_mma<1, 4><<<gF, 512, GEMM_SMEM>>>(
            xh, F1h + o1,
            f1b + l * F_, nullptr, nullptr,
            hh, nullptr, nullptr, F_, D_);
        gemm_mma<0, 4><<<gD, 512, GEMM_SMEM>>>(
            hh, F2h + o2,
            f2b + l * D_, nullptr, nullptr,
            yh, nullptr, nullptr, D_, F_);
        add_ln_kernel<<<M_, 256>>>(ln2s + l * D_, ln2b + l * D_);
    }
    final_kernel<<<B_, 256>>>(outw, out);
}